// round 5
// baseline (speedup 1.0000x reference)
#include <cuda_runtime.h>
#include <mma.h>
#include <math.h>

using namespace nvcuda;

#define B_    4
#define S_    4096
#define D_    1024
#define H_    16
#define DH_   64
#define NF_   2049
#define NFFT  4096
#define LOGN  12

// ---------------- scratch (device globals; no allocations allowed) ----------------
__device__ float  g_Vt[(size_t)B_ * D_ * S_];   // V transposed: [b][c=h*64+d][s]
__device__ float  g_At[(size_t)B_ * D_ * S_];   // attn transposed, same layout
__device__ float2 g_tw[NFFT / 2];               // e^{-2*pi*i*k/N}
__device__ float  g_xpart[B_ * 32 * D_];        // partial sums of x over s-chunks
__device__ float  g_xsum[B_ * D_];              // sum of x over s
__device__ float  g_meanq[B_ * D_];             // mean_q [b][h*64+dh]
__device__ float  g_hdn[B_ * D_];               // gelu(mlp1)
__device__ float  g_gri[B_ * 2 * NF_];          // gates real|imag

// ---------------- twiddle table ----------------
__global__ void __launch_bounds__(256) k_twiddle() {
    int i = blockIdx.x * blockDim.x + threadIdx.x;
    if (i < NFFT / 2) {
        double ang = -6.283185307179586476925286766559 * (double)i / (double)NFFT;
        g_tw[i] = make_float2((float)cos(ang), (float)sin(ang));
    }
}

// ---------------- gate path (tiny) ----------------
__global__ void __launch_bounds__(128) k_xpart(const float* __restrict__ x) {
    int d = blockIdx.x * 128 + threadIdx.x;
    int chunk = blockIdx.y;          // 0..31
    int b = blockIdx.z;
    const float* p = x + ((size_t)b * S_ + (size_t)chunk * 128) * D_ + d;
    float acc = 0.f;
    #pragma unroll 4
    for (int s = 0; s < 128; s++) acc += p[(size_t)s * D_];
    g_xpart[(b * 32 + chunk) * D_ + d] = acc;
}

__global__ void __launch_bounds__(128) k_xsum() {
    int d = blockIdx.x * 128 + threadIdx.x;
    int b = blockIdx.y;
    float acc = 0.f;
    #pragma unroll
    for (int q = 0; q < 32; q++) acc += g_xpart[(b * 32 + q) * D_ + d];
    g_xsum[b * D_ + d] = acc;
}

// warp-per-output dot products: meanq[b][c] = dot(xsum[b], Wq[c]) / S
__global__ void __launch_bounds__(256) k_meanq(const float* __restrict__ Wq) {
    int warp = threadIdx.x >> 5, lane = threadIdx.x & 31;
    int c = blockIdx.x * 8 + warp;
    int b = blockIdx.y;
    const float* w  = Wq + (size_t)c * D_;
    const float* xm = g_xsum + b * D_;
    float acc = 0.f;
    #pragma unroll 8
    for (int i = lane; i < D_; i += 32) acc += xm[i] * w[i];
    #pragma unroll
    for (int o = 16; o; o >>= 1) acc += __shfl_xor_sync(0xffffffffu, acc, o);
    if (lane == 0) g_meanq[b * D_ + c] = acc * (1.0f / S_);
}

// layernorm per (b,h) over DH, mean over h, then mlp1+gelu. one block per b.
__global__ void __launch_bounds__(256) k_lnmlp1(const float* __restrict__ gamma,
                                                const float* __restrict__ beta,
                                                const float* __restrict__ w1,
                                                const float* __restrict__ b1) {
    __shared__ float sv[16][64];
    __shared__ float sq[64];
    __shared__ float smean[16], srstd[16];
    int b = blockIdx.x;
    int t = threadIdx.x;           // 0..255

    #pragma unroll
    for (int r = 0; r < 4; r++) {
        int c = t + r * 256;
        sv[c >> 6][c & 63] = g_meanq[b * D_ + c];
    }
    __syncthreads();
    if (t < 16) {
        float m = 0.f;
        for (int q = 0; q < 64; q++) m += sv[t][q];
        m *= (1.f / 64.f);
        float var = 0.f;
        for (int q = 0; q < 64; q++) { float dd = sv[t][q] - m; var += dd * dd; }
        var *= (1.f / 64.f);
        smean[t] = m;
        srstd[t] = rsqrtf(var + 1e-5f);
    }
    __syncthreads();
    #pragma unroll
    for (int r = 0; r < 4; r++) {
        int c = t + r * 256;
        int h = c >> 6, j = c & 63;
        sv[h][j] = (sv[h][j] - smean[h]) * srstd[h] * gamma[j] + beta[j];
    }
    __syncthreads();
    if (t < 64) {
        float m = 0.f;
        for (int q = 0; q < 16; q++) m += sv[q][t];
        sq[t] = m * (1.f / 16.f);
    }
    __syncthreads();
    #pragma unroll
    for (int r = 0; r < 4; r++) {
        int c = t + r * 256;
        float acc = b1[c];
        const float* wr = w1 + (size_t)c * 64;
        #pragma unroll 8
        for (int q = 0; q < 64; q++) acc += sq[q] * wr[q];
        g_hdn[b * D_ + c] = 0.5f * acc * (1.f + erff(acc * 0.70710678118654752f));
    }
}

__global__ void __launch_bounds__(128) k_mlp2(const float* __restrict__ w2,
                                              const float* __restrict__ b2) {
    int warp = threadIdx.x >> 5, lane = threadIdx.x & 31;
    int r = blockIdx.x * 4 + warp;
    int b = blockIdx.y;
    if (r >= 2 * NF_) return;
    const float* hd = g_hdn + b * D_;
    const float* w  = w2 + (size_t)r * D_;
    float acc = 0.f;
    for (int i = lane; i < D_; i += 32) acc += hd[i] * w[i];
    #pragma unroll
    for (int o = 16; o; o >>= 1) acc += __shfl_xor_sync(0xffffffffu, acc, o);
    if (lane == 0) g_gri[b * 2 * NF_ + r] = acc + b2[r];
}

// ---------------- split-TF32 (3x) WMMA GEMM: C[m,n] = sum_k A[m,k]*W[n,k] ----------------
// Double-buffered smem + register prefetch. One __syncthreads per k-tile.
// ACOL:   A stored column-major per-batch ([b][k][s]); else row-major.
// TSTORE: store C transposed to [b][n][s]; else row-major to C.
template <bool ACOL, bool TSTORE>
__global__ void __launch_bounds__(256, 1) k_gemm(const float* __restrict__ A,
                                                 const float* __restrict__ W,
                                                 float* __restrict__ C) {
    extern __shared__ float sm[];
    constexpr int ASZ = ACOL ? 32 * 132 : 128 * 36;
    constexpr int BSZ = 128 * 36;
    constexpr int BUF = ASZ + BSZ;

    const int tid = threadIdx.x;
    const int warp = tid >> 5;
    const int wm = warp & 3;   // 4 warps along M
    const int wn = warp >> 2;  // 2 warps along N
    const int n0 = blockIdx.x * 128;
    const int m0 = blockIdx.y * 128;

    const float* Abase;
    if (ACOL) {
        int b  = m0 >> 12;
        int s0 = m0 & 4095;
        Abase = A + (size_t)b * ((size_t)D_ * S_) + s0;
    } else {
        Abase = A + (size_t)m0 * D_;
    }

    wmma::fragment<wmma::accumulator, 16, 16, 8, float> acc[2][4];
    #pragma unroll
    for (int i = 0; i < 2; i++)
        #pragma unroll
        for (int j = 0; j < 4; j++) wmma::fill_fragment(acc[i][j], 0.0f);

    float4 ra[4], rw[4];

    // ---- prologue: load tile 0 into regs, stage to buffer 0 ----
    #pragma unroll
    for (int t = 0; t < 4; t++) {
        int idx = tid + t * 256;
        if (ACOL) {
            int col = idx >> 5, mm = (idx & 31) * 4;
            ra[t] = *(const float4*)(Abase + (size_t)col * S_ + mm);
        } else {
            int row = idx >> 3, c4 = (idx & 7) * 4;
            ra[t] = *(const float4*)(Abase + (size_t)row * D_ + c4);
        }
        int row = idx >> 3, c4 = (idx & 7) * 4;
        rw[t] = *(const float4*)(W + (size_t)(n0 + row) * D_ + c4);
    }
    {
        float* As = sm;
        float* Bs = sm + ASZ;
        #pragma unroll
        for (int t = 0; t < 4; t++) {
            int idx = tid + t * 256;
            if (ACOL) {
                int col = idx >> 5, mm = (idx & 31) * 4;
                *(float4*)(As + col * 132 + mm) = ra[t];
            } else {
                int row = idx >> 3, c4 = (idx & 7) * 4;
                *(float4*)(As + row * 36 + c4) = ra[t];
            }
            int row = idx >> 3, c4 = (idx & 7) * 4;
            *(float4*)(Bs + row * 36 + c4) = rw[t];
        }
    }
    __syncthreads();

    // ---- mainloop: 32 k-tiles ----
    for (int it = 0; it < 32; it++) {
        const bool pf = (it + 1 < 32);
        const int knext = (it + 1) * 32;
        if (pf) {
            #pragma unroll
            for (int t = 0; t < 4; t++) {
                int idx = tid + t * 256;
                if (ACOL) {
                    int col = idx >> 5, mm = (idx & 31) * 4;
                    ra[t] = *(const float4*)(Abase + (size_t)(knext + col) * S_ + mm);
                } else {
                    int row = idx >> 3, c4 = (idx & 7) * 4;
                    ra[t] = *(const float4*)(Abase + (size_t)row * D_ + knext + c4);
                }
                int row = idx >> 3, c4 = (idx & 7) * 4;
                rw[t] = *(const float4*)(W + (size_t)(n0 + row) * D_ + knext + c4);
            }
        }

        float* As = sm + (it & 1) * BUF;
        float* Bs = As + ASZ;

        #pragma unroll
        for (int kk = 0; kk < 32; kk += 8) {
            wmma::fragment<wmma::matrix_b, 16, 16, 8, wmma::precision::tf32, wmma::col_major> bH[4], bL[4];
            #pragma unroll
            for (int j = 0; j < 4; j++) {
                wmma::load_matrix_sync(bH[j], Bs + (wn * 64 + j * 16) * 36 + kk, 36);
                #pragma unroll
                for (int e = 0; e < bH[j].num_elements; e++) {
                    float v = bH[j].x[e];
                    float hv = wmma::__float_to_tf32(v);
                    bL[j].x[e] = wmma::__float_to_tf32(v - hv);
                    bH[j].x[e] = hv;
                }
            }
            if (ACOL) {
                wmma::fragment<wmma::matrix_a, 16, 16, 8, wmma::precision::tf32, wmma::col_major> aH[2], aL[2];
                #pragma unroll
                for (int i = 0; i < 2; i++) {
                    wmma::load_matrix_sync(aH[i], As + kk * 132 + wm * 32 + i * 16, 132);
                    #pragma unroll
                    for (int e = 0; e < aH[i].num_elements; e++) {
                        float v = aH[i].x[e];
                        float hv = wmma::__float_to_tf32(v);
                        aL[i].x[e] = wmma::__float_to_tf32(v - hv);
                        aH[i].x[e] = hv;
                    }
                }
                #pragma unroll
                for (int i = 0; i < 2; i++)
                    #pragma unroll
                    for (int j = 0; j < 4; j++) {
                        wmma::mma_sync(acc[i][j], aL[i], bH[j], acc[i][j]);
                        wmma::mma_sync(acc[i][j], aH[i], bL[j], acc[i][j]);
                        wmma::mma_sync(acc[i][j], aH[i], bH[j], acc[i][j]);
                    }
            } else {
                wmma::fragment<wmma::matrix_a, 16, 16, 8, wmma::precision::tf32, wmma::row_major> aH[2], aL[2];
                #pragma unroll
                for (int i = 0; i < 2; i++) {
                    wmma::load_matrix_sync(aH[i], As + (wm * 32 + i * 16) * 36 + kk, 36);
                    #pragma unroll
                    for (int e = 0; e < aH[i].num_elements; e++) {
                        float v = aH[i].x[e];
                        float hv = wmma::__float_to_tf32(v);
                        aL[i].x[e] = wmma::__float_to_tf32(v - hv);
                        aH[i].x[e] = hv;
                    }
                }
                #pragma unroll
                for (int i = 0; i < 2; i++)
                    #pragma unroll
                    for (int j = 0; j < 4; j++) {
                        wmma::mma_sync(acc[i][j], aL[i], bH[j], acc[i][j]);
                        wmma::mma_sync(acc[i][j], aH[i], bL[j], acc[i][j]);
                        wmma::mma_sync(acc[i][j], aH[i], bH[j], acc[i][j]);
                    }
            }
        }

        if (pf) {
            float* Asn = sm + ((it + 1) & 1) * BUF;
            float* Bsn = Asn + ASZ;
            #pragma unroll
            for (int t = 0; t < 4; t++) {
                int idx = tid + t * 256;
                if (ACOL) {
                    int col = idx >> 5, mm = (idx & 31) * 4;
                    *(float4*)(Asn + col * 132 + mm) = ra[t];
                } else {
                    int row = idx >> 3, c4 = (idx & 7) * 4;
                    *(float4*)(Asn + row * 36 + c4) = ra[t];
                }
                int row = idx >> 3, c4 = (idx & 7) * 4;
                *(float4*)(Bsn + row * 36 + c4) = rw[t];
            }
        }
        __syncthreads();
    }

    if (TSTORE) {
        // write C^T through smem: Ct[n][m], ld=132 (aliases the buffers)
        float* Ct = sm;
        #pragma unroll
        for (int i = 0; i < 2; i++)
            #pragma unroll
            for (int j = 0; j < 4; j++)
                wmma::store_matrix_sync(Ct + (wn * 64 + j * 16) * 132 + wm * 32 + i * 16,
                                        acc[i][j], 132, wmma::mem_col_major);
        __syncthreads();
        int b  = m0 >> 12;
        int s0 = m0 & 4095;
        #pragma unroll
        for (int t = 0; t < 16; t++) {
            int idx = tid + t * 256;
            int n  = idx >> 5;
            int mm = (idx & 31) * 4;
            float4 v = *(float4*)(Ct + n * 132 + mm);
            *(float4*)(C + ((size_t)(b * D_ + n0 + n)) * S_ + s0 + mm) = v;
        }
    } else {
        #pragma unroll
        for (int i = 0; i < 2; i++)
            #pragma unroll
            for (int j = 0; j < 4; j++)
                wmma::store_matrix_sync(C + (size_t)(m0 + wm * 32 + i * 16) * D_ + n0 + wn * 64 + j * 16,
                                        acc[i][j], D_, wmma::mem_row_major);
    }
}

// ---------------- fused radix-4 FFT -> gate*modReLU -> iFFT ----------------
// skewed smem indexing to avoid bank conflicts at small strides
__device__ __forceinline__ int SK(int i) { return i + (i >> 4); }
__device__ __forceinline__ float2 cmul(float2 a, float2 b) {
    return make_float2(a.x * b.x - a.y * b.y, a.x * b.y + a.y * b.x);
}
__device__ __forceinline__ float2 cmulc(float2 a, float2 b) {  // a * conj(b)
    return make_float2(a.x * b.x + a.y * b.y, a.y * b.x - a.x * b.y);
}

__global__ void __launch_bounds__(512) k_fft(const float* __restrict__ mbias) {
    extern __shared__ float2 sd[];
    float2* dat = sd;              // skewed, 4096 + 256 slots
    float2* tw  = sd + 4352;       // 2048

    const int tid = threadIdx.x;
    const int p = blockIdx.x;      // 0..31
    const int h = blockIdx.y;      // 0..15
    const int b = blockIdx.z;      // 0..3

    const float* va = g_Vt + ((size_t)((b * H_ + h) * DH_ + 2 * p)) * S_;
    const float* vb = va + S_;
    for (int i = tid; i < NFFT; i += 512) dat[SK(i)] = make_float2(va[i], vb[i]);
    for (int i = tid; i < NFFT / 2; i += 512) tw[i] = g_tw[i];
    __syncthreads();

    // forward radix-4 DIF (natural -> digit4-reversed), twiddle e^{-}
    #pragma unroll
    for (int t = 0; t < 6; t++) {
        const int lq = 10 - 2 * t;       // log2(Q)
        const int Q = 1 << lq;
        const int step = 1 << (10 - lq); // 1024/Q
        #pragma unroll 2
        for (int q = tid; q < 1024; q += 512) {
            int j  = q & (Q - 1);
            int i0 = ((q >> lq) << (lq + 2)) | j;
            float2 x0 = dat[SK(i0)];
            float2 x1 = dat[SK(i0 + Q)];
            float2 x2 = dat[SK(i0 + 2 * Q)];
            float2 x3 = dat[SK(i0 + 3 * Q)];
            float2 t0 = make_float2(x0.x + x2.x, x0.y + x2.y);
            float2 t1 = make_float2(x0.x - x2.x, x0.y - x2.y);
            float2 t2 = make_float2(x1.x + x3.x, x1.y + x3.y);
            float2 t3 = make_float2(x1.x - x3.x, x1.y - x3.y);
            float2 w1 = tw[j * step];
            float2 w2 = tw[2 * j * step];
            float2 w3 = cmul(w1, w2);
            dat[SK(i0)]         = make_float2(t0.x + t2.x, t0.y + t2.y);
            dat[SK(i0 + Q)]     = cmul(make_float2(t1.x + t3.y, t1.y - t3.x), w1);
            dat[SK(i0 + 2 * Q)] = cmul(make_float2(t0.x - t2.x, t0.y - t2.y), w2);
            dat[SK(i0 + 3 * Q)] = cmul(make_float2(t1.x - t3.y, t1.y + t3.x), w3);
        }
        __syncthreads();
    }

    // spectral: separate Hermitian parts, ortho scale, gate, modReLU, repack
    const float bias = mbias[0];
    const float inv64 = 1.0f / 64.0f;   // 1/sqrt(N)
    const float* grb = g_gri + b * 2 * NF_;
    for (int k = tid; k <= NFFT / 2; k += 512) {
        float gr = grb[k];
        float gi = grb[NF_ + k];
        int r1 = (int)(__brev((unsigned)k) >> (32 - LOGN));
        int p1 = ((r1 & 0x555) << 1) | ((r1 & 0xAAA) >> 1);   // digit4 reversal
        if (k == 0 || k == NFFT / 2) {
            float2 Z = dat[SK(p1)];
            float Av = Z.x * inv64, Bv = Z.y * inv64;
            float ar = Av * gr, ai = Av * gi;
            float ma = sqrtf(ar * ar + ai * ai);
            float sa = fmaxf(ma + bias, 0.f) / fmaxf(ma, 1e-12f);
            float Aout = ar * sa * inv64;             // irfft drops imag of bins 0, N/2
            float br2 = Bv * gr, bi2 = Bv * gi;
            float mb = sqrtf(br2 * br2 + bi2 * bi2);
            float sb = fmaxf(mb + bias, 0.f) / fmaxf(mb, 1e-12f);
            float Bout = br2 * sb * inv64;
            dat[SK(p1)] = make_float2(Aout, Bout);
        } else {
            int r2 = (int)(__brev((unsigned)(NFFT - k)) >> (32 - LOGN));
            int p2 = ((r2 & 0x555) << 1) | ((r2 & 0xAAA) >> 1);
            float2 Z1 = dat[SK(p1)], Z2 = dat[SK(p2)];
            float Ar = 0.5f * (Z1.x + Z2.x) * inv64;
            float Ai = 0.5f * (Z1.y - Z2.y) * inv64;
            float Br = 0.5f * (Z1.y + Z2.y) * inv64;
            float Bi = 0.5f * (Z2.x - Z1.x) * inv64;
            float zar = Ar * gr - Ai * gi, zai = Ar * gi + Ai * gr;
            float ma = sqrtf(zar * zar + zai * zai);
            float sa = fmaxf(ma + bias, 0.f) / fmaxf(ma, 1e-12f) * inv64;
            zar *= sa; zai *= sa;
            float zbr = Br * gr - Bi * gi, zbi = Br * gi + Bi * gr;
            float mb = sqrtf(zbr * zbr + zbi * zbi);
            float sb = fmaxf(mb + bias, 0.f) / fmaxf(mb, 1e-12f) * inv64;
            zbr *= sb; zbi *= sb;
            dat[SK(p1)] = make_float2(zar - zbi, zai + zbr);   // Z'_k
            dat[SK(p2)] = make_float2(zar + zbi, zbr - zai);   // Z'_{N-k}
        }
    }
    __syncthreads();

    // inverse radix-4 DIT (digit4-reversed -> natural), conj twiddles
    #pragma unroll
    for (int t = 5; t >= 0; t--) {
        const int lq = 10 - 2 * t;
        const int Q = 1 << lq;
        const int step = 1 << (10 - lq);
        #pragma unroll 2
        for (int q = tid; q < 1024; q += 512) {
            int j  = q & (Q - 1);
            int i0 = ((q >> lq) << (lq + 2)) | j;
            float2 x0 = dat[SK(i0)];
            float2 x1 = dat[SK(i0 + Q)];
            float2 x2 = dat[SK(i0 + 2 * Q)];
            float2 x3 = dat[SK(i0 + 3 * Q)];
            float2 w1 = tw[j * step];
            float2 w2 = tw[2 * j * step];
            float2 w3 = cmul(w1, w2);
            float2 u1 = cmulc(x1, w1);
            float2 u2 = cmulc(x2, w2);
            float2 u3 = cmulc(x3, w3);
            float2 s0 = make_float2(x0.x + u2.x, x0.y + u2.y);
            float2 s1 = make_float2(x0.x - u2.x, x0.y - u2.y);
            float2 s2 = make_float2(u1.x + u3.x, u1.y + u3.y);
            float2 s3 = make_float2(u1.x - u3.x, u1.y - u3.y);
            dat[SK(i0)]         = make_float2(s0.x + s2.x, s0.y + s2.y);
            dat[SK(i0 + Q)]     = make_float2(s1.x - s3.y, s1.y + s3.x);
            dat[SK(i0 + 2 * Q)] = make_float2(s0.x - s2.x, s0.y - s2.y);
            dat[SK(i0 + 3 * Q)] = make_float2(s1.x + s3.y, s1.y - s3.x);
        }
        __syncthreads();
    }

    float* oa = g_At + ((size_t)((b * H_ + h) * DH_ + 2 * p)) * S_;
    float* ob = oa + S_;
    for (int i = tid; i < NFFT; i += 512) {
        float2 z = dat[SK(i)];
        oa[i] = z.x;
        ob[i] = z.y;
    }
}

// ---------------- launch ----------------
extern "C" void kernel_launch(void* const* d_in, const int* in_sizes, int n_in,
                              void* d_out, int out_size) {
    const float* x     = (const float*)d_in[0];
    const float* Wq    = (const float*)d_in[1];
    const float* Wv    = (const float*)d_in[2];
    const float* Wo    = (const float*)d_in[3];
    const float* gamma = (const float*)d_in[4];
    const float* beta  = (const float*)d_in[5];
    const float* w1    = (const float*)d_in[6];
    const float* b1    = (const float*)d_in[7];
    const float* w2    = (const float*)d_in[8];
    const float* b2    = (const float*)d_in[9];
    const float* mbias = (const float*)d_in[10];
    float* out = (float*)d_out;

    float *vt = nullptr, *at = nullptr;
    cudaGetSymbolAddress((void**)&vt, g_Vt);
    cudaGetSymbolAddress((void**)&at, g_At);

    // smem: V-GEMM 2*(128*36 + 128*36)*4 = 73728 (Ct 67584 aliases)
    //       O-GEMM 2*(32*132 + 128*36)*4 = 70656
    //       FFT    (4352 + 2048)*8       = 51200
    const int smem_gemm_v = 2 * (128 * 36 + 128 * 36) * 4;
    const int smem_gemm_o = 2 * (32 * 132 + 128 * 36) * 4;
    const int smem_fft    = (4352 + 2048) * 8;

    cudaFuncSetAttribute(k_gemm<false, true>,  cudaFuncAttributeMaxDynamicSharedMemorySize, smem_gemm_v);
    cudaFuncSetAttribute(k_gemm<true,  false>, cudaFuncAttributeMaxDynamicSharedMemorySize, smem_gemm_o);
    cudaFuncSetAttribute(k_fft,                cudaFuncAttributeMaxDynamicSharedMemorySize, smem_fft);

    // gate path (tiny) + twiddles
    k_twiddle<<<8, 256>>>();
    k_xpart<<<dim3(8, 32, 4), 128>>>(x);
    k_xsum<<<dim3(8, 4), 128>>>();
    k_meanq<<<dim3(128, 4), 256>>>(Wq);
    k_lnmlp1<<<4, 256>>>(gamma, beta, w1, b1);
    k_mlp2<<<dim3((2 * NF_ + 3) / 4, 4), 128>>>(w2, b2);

    // V projection, transposed output [b][c][s]
    k_gemm<false, true><<<dim3(8, 128), 256, smem_gemm_v>>>(x, Wv, vt);

    // fused spectral mixer
    k_fft<<<dim3(32, 16, 4), 512, smem_fft>>>(mbias);

    // output projection from transposed attn layout
    k_gemm<true, false><<<dim3(8, 128), 256, smem_gemm_o>>>(at, Wo, out);
}

// round 7
// speedup vs baseline: 1.9302x; 1.9302x over previous
#include <cuda_runtime.h>
#include <cuda_bf16.h>
#include <mma.h>
#include <math.h>
#include <stdint.h>

using namespace nvcuda;

#define B_    4
#define S_    4096
#define D_    1024
#define H_    16
#define DH_   64
#define NF_   2049
#define NFFT  4096
#define LOGN  12

// ---------------- scratch (device globals; no allocations allowed) ----------------
__device__ float  g_Vt[(size_t)B_ * D_ * S_];   // V transposed: [b][c=h*64+d][s]
__device__ float  g_At[(size_t)B_ * D_ * S_];   // attn transposed, same layout
__device__ float2 g_tw[NFFT / 2];               // e^{-2*pi*i*k/N}
__device__ float  g_xpart[B_ * 32 * D_];        // partial sums of x over s-chunks
__device__ float  g_xsum[B_ * D_];              // sum of x over s
__device__ float  g_meanq[B_ * D_];             // mean_q [b][h*64+dh]
__device__ float  g_hdn[B_ * D_];               // gelu(mlp1)
__device__ float  g_gri[B_ * 2 * NF_];          // gates real|imag

// bf16 hi/lo split of two floats, packed as bf16x2 words
__device__ __forceinline__ void split2(float v0, float v1, uint32_t& hi, uint32_t& lo) {
    __nv_bfloat16 h0 = __float2bfloat16(v0);
    __nv_bfloat16 h1 = __float2bfloat16(v1);
    __nv_bfloat16 l0 = __float2bfloat16(v0 - __bfloat162float(h0));
    __nv_bfloat16 l1 = __float2bfloat16(v1 - __bfloat162float(h1));
    hi = ((uint32_t)__bfloat16_as_ushort(h1) << 16) | __bfloat16_as_ushort(h0);
    lo = ((uint32_t)__bfloat16_as_ushort(l1) << 16) | __bfloat16_as_ushort(l0);
}
__device__ __forceinline__ void split4(float4 v, uint2& hi, uint2& lo) {
    uint32_t h01, l01, h23, l23;
    split2(v.x, v.y, h01, l01);
    split2(v.z, v.w, h23, l23);
    hi = make_uint2(h01, h23);
    lo = make_uint2(l01, l23);
}

// ---------------- twiddle table ----------------
__global__ void __launch_bounds__(256) k_twiddle() {
    int i = blockIdx.x * blockDim.x + threadIdx.x;
    if (i < NFFT / 2) {
        double ang = -6.283185307179586476925286766559 * (double)i / (double)NFFT;
        g_tw[i] = make_float2((float)cos(ang), (float)sin(ang));
    }
}

// ---------------- gate path (tiny) ----------------
__global__ void __launch_bounds__(128) k_xpart(const float* __restrict__ x) {
    int d = blockIdx.x * 128 + threadIdx.x;
    int chunk = blockIdx.y;
    int b = blockIdx.z;
    const float* p = x + ((size_t)b * S_ + (size_t)chunk * 128) * D_ + d;
    float acc = 0.f;
    #pragma unroll 4
    for (int s = 0; s < 128; s++) acc += p[(size_t)s * D_];
    g_xpart[(b * 32 + chunk) * D_ + d] = acc;
}

__global__ void __launch_bounds__(128) k_xsum() {
    int d = blockIdx.x * 128 + threadIdx.x;
    int b = blockIdx.y;
    float acc = 0.f;
    #pragma unroll
    for (int q = 0; q < 32; q++) acc += g_xpart[(b * 32 + q) * D_ + d];
    g_xsum[b * D_ + d] = acc;
}

__global__ void __launch_bounds__(256) k_meanq(const float* __restrict__ Wq) {
    int warp = threadIdx.x >> 5, lane = threadIdx.x & 31;
    int c = blockIdx.x * 8 + warp;
    int b = blockIdx.y;
    const float* w  = Wq + (size_t)c * D_;
    const float* xm = g_xsum + b * D_;
    float acc = 0.f;
    #pragma unroll 8
    for (int i = lane; i < D_; i += 32) acc += xm[i] * w[i];
    #pragma unroll
    for (int o = 16; o; o >>= 1) acc += __shfl_xor_sync(0xffffffffu, acc, o);
    if (lane == 0) g_meanq[b * D_ + c] = acc * (1.0f / S_);
}

__global__ void __launch_bounds__(256) k_lnmlp1(const float* __restrict__ gamma,
                                                const float* __restrict__ beta,
                                                const float* __restrict__ w1,
                                                const float* __restrict__ b1) {
    __shared__ float sv[16][64];
    __shared__ float sq[64];
    __shared__ float smean[16], srstd[16];
    int b = blockIdx.x;
    int t = threadIdx.x;

    #pragma unroll
    for (int r = 0; r < 4; r++) {
        int c = t + r * 256;
        sv[c >> 6][c & 63] = g_meanq[b * D_ + c];
    }
    __syncthreads();
    if (t < 16) {
        float m = 0.f;
        for (int q = 0; q < 64; q++) m += sv[t][q];
        m *= (1.f / 64.f);
        float var = 0.f;
        for (int q = 0; q < 64; q++) { float dd = sv[t][q] - m; var += dd * dd; }
        var *= (1.f / 64.f);
        smean[t] = m;
        srstd[t] = rsqrtf(var + 1e-5f);
    }
    __syncthreads();
    #pragma unroll
    for (int r = 0; r < 4; r++) {
        int c = t + r * 256;
        int h = c >> 6, j = c & 63;
        sv[h][j] = (sv[h][j] - smean[h]) * srstd[h] * gamma[j] + beta[j];
    }
    __syncthreads();
    if (t < 64) {
        float m = 0.f;
        for (int q = 0; q < 16; q++) m += sv[q][t];
        sq[t] = m * (1.f / 16.f);
    }
    __syncthreads();
    #pragma unroll
    for (int r = 0; r < 4; r++) {
        int c = t + r * 256;
        float acc = b1[c];
        const float* wr = w1 + (size_t)c * 64;
        #pragma unroll 8
        for (int q = 0; q < 64; q++) acc += sq[q] * wr[q];
        g_hdn[b * D_ + c] = 0.5f * acc * (1.f + erff(acc * 0.70710678118654752f));
    }
}

__global__ void __launch_bounds__(128) k_mlp2(const float* __restrict__ w2,
                                              const float* __restrict__ b2) {
    int warp = threadIdx.x >> 5, lane = threadIdx.x & 31;
    int r = blockIdx.x * 4 + warp;
    int b = blockIdx.y;
    if (r >= 2 * NF_) return;
    const float* hd = g_hdn + b * D_;
    const float* w  = w2 + (size_t)r * D_;
    float acc = 0.f;
    for (int i = lane; i < D_; i += 32) acc += hd[i] * w[i];
    #pragma unroll
    for (int o = 16; o; o >>= 1) acc += __shfl_xor_sync(0xffffffffu, acc, o);
    if (lane == 0) g_gri[b * 2 * NF_ + r] = acc + b2[r];
}

// =================================================================
// bf16-split WMMA GEMM: C[m,n] = sum_k A[m,k]*W[n,k]
// Split computed ONCE at staging; mainloop is pure HMMA.16816.
// 3 products: aH*bH + aL*bH + aH*bL (lo*lo dropped, ~2^-16 rel).
// Double-buffered smem, register prefetch, one sync per k-tile.
// ACOL:   A stored column-major per-batch ([b][k][s]); else row-major.
// TSTORE: store C transposed to [b][n][s]; else row-major to C.
// =================================================================
template <bool ACOL, bool TSTORE>
__global__ void __launch_bounds__(256, 1) k_gemm(const float* __restrict__ A,
                                                 const float* __restrict__ W,
                                                 float* __restrict__ C) {
    extern __shared__ __align__(16) char smraw[];
    __nv_bfloat16* sb = (__nv_bfloat16*)smraw;
    float* smf = (float*)smraw;

    // element counts (bf16)
    constexpr int ASZ = ACOL ? 32 * 136 : 128 * 40;   // one A plane (hi or lo)
    constexpr int WSZ = 128 * 40;                     // one W plane
    constexpr int BUF = 2 * ASZ + 2 * WSZ;            // AHI|ALO|WHI|WLO

    const int tid = threadIdx.x;
    const int warp = tid >> 5;
    const int wm = warp & 3;   // 4 warps along M (32 rows each)
    const int wn = warp >> 2;  // 2 warps along N (64 cols each)
    const int n0 = blockIdx.x * 128;
    const int m0 = blockIdx.y * 128;

    const float* Abase;
    if (ACOL) {
        int b  = m0 >> 12;
        int s0 = m0 & 4095;
        Abase = A + (size_t)b * ((size_t)D_ * S_) + s0;
    } else {
        Abase = A + (size_t)m0 * D_;
    }
    const float* Wbase = W + (size_t)n0 * D_;

    wmma::fragment<wmma::accumulator, 16, 16, 16, float> acc[2][4];
    #pragma unroll
    for (int i = 0; i < 2; i++)
        #pragma unroll
        for (int j = 0; j < 4; j++) wmma::fill_fragment(acc[i][j], 0.0f);

    float4 ra[4], rw[4];

    auto GLOAD = [&](int c) {
        #pragma unroll
        for (int t = 0; t < 4; t++) {
            int idx = tid + t * 256;
            if (ACOL) {
                int col = idx >> 5, mm = (idx & 31) * 4;
                ra[t] = *(const float4*)(Abase + (size_t)(c * 32 + col) * S_ + mm);
            } else {
                int row = idx >> 3, c4 = (idx & 7) * 4;
                ra[t] = *(const float4*)(Abase + (size_t)row * D_ + c * 32 + c4);
            }
            int row = idx >> 3, c4 = (idx & 7) * 4;
            rw[t] = *(const float4*)(Wbase + (size_t)row * D_ + c * 32 + c4);
        }
    };
    auto SSTORE = [&](int jb) {
        __nv_bfloat16* base = sb + jb * BUF;
        #pragma unroll
        for (int t = 0; t < 4; t++) {
            int idx = tid + t * 256;
            uint2 hi, lo;
            split4(ra[t], hi, lo);
            if (ACOL) {
                int col = idx >> 5, mm = (idx & 31) * 4;
                *(uint2*)(base + col * 136 + mm)       = hi;
                *(uint2*)(base + ASZ + col * 136 + mm) = lo;
            } else {
                int row = idx >> 3, c4 = (idx & 7) * 4;
                *(uint2*)(base + row * 40 + c4)       = hi;
                *(uint2*)(base + ASZ + row * 40 + c4) = lo;
            }
            split4(rw[t], hi, lo);
            int row = idx >> 3, c4 = (idx & 7) * 4;
            *(uint2*)(base + 2 * ASZ + row * 40 + c4)       = hi;
            *(uint2*)(base + 2 * ASZ + WSZ + row * 40 + c4) = lo;
        }
    };

    // prologue: tile 0
    GLOAD(0);
    SSTORE(0);
    __syncthreads();

    for (int it = 0; it < 32; it++) {
        const bool pf = (it + 1 < 32);
        if (pf) GLOAD(it + 1);

        const __nv_bfloat16* base = sb + (it & 1) * BUF;
        const __nv_bfloat16* Wh = base + 2 * ASZ;
        const __nv_bfloat16* Wl = Wh + WSZ;

        #pragma unroll
        for (int kk = 0; kk < 32; kk += 16) {
            if (ACOL) {
                wmma::fragment<wmma::matrix_a, 16, 16, 16, __nv_bfloat16, wmma::col_major> aH[2], aL[2];
                #pragma unroll
                for (int i = 0; i < 2; i++) {
                    wmma::load_matrix_sync(aH[i], base + kk * 136 + wm * 32 + i * 16, 136);
                    wmma::load_matrix_sync(aL[i], base + ASZ + kk * 136 + wm * 32 + i * 16, 136);
                }
                #pragma unroll
                for (int j = 0; j < 4; j++) {
                    wmma::fragment<wmma::matrix_b, 16, 16, 16, __nv_bfloat16, wmma::col_major> bH, bL;
                    wmma::load_matrix_sync(bH, Wh + (wn * 64 + j * 16) * 40 + kk, 40);
                    wmma::load_matrix_sync(bL, Wl + (wn * 64 + j * 16) * 40 + kk, 40);
                    #pragma unroll
                    for (int i = 0; i < 2; i++) {
                        wmma::mma_sync(acc[i][j], aH[i], bH, acc[i][j]);
                        wmma::mma_sync(acc[i][j], aL[i], bH, acc[i][j]);
                        wmma::mma_sync(acc[i][j], aH[i], bL, acc[i][j]);
                    }
                }
            } else {
                wmma::fragment<wmma::matrix_a, 16, 16, 16, __nv_bfloat16, wmma::row_major> aH[2], aL[2];
                #pragma unroll
                for (int i = 0; i < 2; i++) {
                    wmma::load_matrix_sync(aH[i], base + (wm * 32 + i * 16) * 40 + kk, 40);
                    wmma::load_matrix_sync(aL[i], base + ASZ + (wm * 32 + i * 16) * 40 + kk, 40);
                }
                #pragma unroll
                for (int j = 0; j < 4; j++) {
                    wmma::fragment<wmma::matrix_b, 16, 16, 16, __nv_bfloat16, wmma::col_major> bH, bL;
                    wmma::load_matrix_sync(bH, Wh + (wn * 64 + j * 16) * 40 + kk, 40);
                    wmma::load_matrix_sync(bL, Wl + (wn * 64 + j * 16) * 40 + kk, 40);
                    #pragma unroll
                    for (int i = 0; i < 2; i++) {
                        wmma::mma_sync(acc[i][j], aH[i], bH, acc[i][j]);
                        wmma::mma_sync(acc[i][j], aL[i], bH, acc[i][j]);
                        wmma::mma_sync(acc[i][j], aH[i], bL, acc[i][j]);
                    }
                }
            }
        }

        if (pf) SSTORE((it + 1) & 1);
        __syncthreads();
    }

    if (TSTORE) {
        // write C^T through smem: Ct[n][m], ld=132 (aliases the buffers)
        float* Ct = smf;
        #pragma unroll
        for (int i = 0; i < 2; i++)
            #pragma unroll
            for (int j = 0; j < 4; j++)
                wmma::store_matrix_sync(Ct + (wn * 64 + j * 16) * 132 + wm * 32 + i * 16,
                                        acc[i][j], 132, wmma::mem_col_major);
        __syncthreads();
        int b  = m0 >> 12;
        int s0 = m0 & 4095;
        #pragma unroll
        for (int t = 0; t < 16; t++) {
            int idx = tid + t * 256;
            int n  = idx >> 5;
            int mm = (idx & 31) * 4;
            float4 v = *(float4*)(Ct + n * 132 + mm);
            *(float4*)(C + ((size_t)(b * D_ + n0 + n)) * S_ + s0 + mm) = v;
        }
    } else {
        #pragma unroll
        for (int i = 0; i < 2; i++)
            #pragma unroll
            for (int j = 0; j < 4; j++)
                wmma::store_matrix_sync(C + (size_t)(m0 + wm * 32 + i * 16) * D_ + n0 + wn * 64 + j * 16,
                                        acc[i][j], D_, wmma::mem_row_major);
    }
}

// ---------------- fused radix-4 FFT -> gate*modReLU -> iFFT ----------------
__device__ __forceinline__ int SKI(int i) { return i + (i >> 4); }
__device__ __forceinline__ float2 cmul(float2 a, float2 b) {
    return make_float2(a.x * b.x - a.y * b.y, a.x * b.y + a.y * b.x);
}
__device__ __forceinline__ float2 cmulc(float2 a, float2 b) {  // a * conj(b)
    return make_float2(a.x * b.x + a.y * b.y, a.y * b.x - a.x * b.y);
}

__global__ void __launch_bounds__(512) k_fft(const float* __restrict__ mbias) {
    extern __shared__ float2 sd[];
    float2* dat = sd;              // skewed, 4096 + 256 slots
    float2* tw  = sd + 4352;       // 2048

    const int tid = threadIdx.x;
    const int p = blockIdx.x;
    const int h = blockIdx.y;
    const int b = blockIdx.z;

    const float* va = g_Vt + ((size_t)((b * H_ + h) * DH_ + 2 * p)) * S_;
    const float* vb = va + S_;
    for (int i = tid; i < NFFT; i += 512) dat[SKI(i)] = make_float2(va[i], vb[i]);
    for (int i = tid; i < NFFT / 2; i += 512) tw[i] = g_tw[i];
    __syncthreads();

    #pragma unroll
    for (int t = 0; t < 6; t++) {
        const int lq = 10 - 2 * t;
        const int Q = 1 << lq;
        const int step = 1 << (10 - lq);
        #pragma unroll 2
        for (int q = tid; q < 1024; q += 512) {
            int j  = q & (Q - 1);
            int i0 = ((q >> lq) << (lq + 2)) | j;
            float2 x0 = dat[SKI(i0)];
            float2 x1 = dat[SKI(i0 + Q)];
            float2 x2 = dat[SKI(i0 + 2 * Q)];
            float2 x3 = dat[SKI(i0 + 3 * Q)];
            float2 t0 = make_float2(x0.x + x2.x, x0.y + x2.y);
            float2 t1 = make_float2(x0.x - x2.x, x0.y - x2.y);
            float2 t2 = make_float2(x1.x + x3.x, x1.y + x3.y);
            float2 t3 = make_float2(x1.x - x3.x, x1.y - x3.y);
            float2 w1 = tw[j * step];
            float2 w2 = tw[2 * j * step];
            float2 w3 = cmul(w1, w2);
            dat[SKI(i0)]         = make_float2(t0.x + t2.x, t0.y + t2.y);
            dat[SKI(i0 + Q)]     = cmul(make_float2(t1.x + t3.y, t1.y - t3.x), w1);
            dat[SKI(i0 + 2 * Q)] = cmul(make_float2(t0.x - t2.x, t0.y - t2.y), w2);
            dat[SKI(i0 + 3 * Q)] = cmul(make_float2(t1.x - t3.y, t1.y + t3.x), w3);
        }
        __syncthreads();
    }

    const float bias = mbias[0];
    const float inv64 = 1.0f / 64.0f;
    const float* grb = g_gri + b * 2 * NF_;
    for (int k = tid; k <= NFFT / 2; k += 512) {
        float gr = grb[k];
        float gi = grb[NF_ + k];
        int r1 = (int)(__brev((unsigned)k) >> (32 - LOGN));
        int p1 = ((r1 & 0x555) << 1) | ((r1 & 0xAAA) >> 1);
        if (k == 0 || k == NFFT / 2) {
            float2 Z = dat[SKI(p1)];
            float Av = Z.x * inv64, Bv = Z.y * inv64;
            float ar = Av * gr, ai = Av * gi;
            float ma = sqrtf(ar * ar + ai * ai);
            float sa = fmaxf(ma + bias, 0.f) / fmaxf(ma, 1e-12f);
            float Aout = ar * sa * inv64;
            float br2 = Bv * gr, bi2 = Bv * gi;
            float mb = sqrtf(br2 * br2 + bi2 * bi2);
            float sb = fmaxf(mb + bias, 0.f) / fmaxf(mb, 1e-12f);
            float Bout = br2 * sb * inv64;
            dat[SKI(p1)] = make_float2(Aout, Bout);
        } else {
            int r2 = (int)(__brev((unsigned)(NFFT - k)) >> (32 - LOGN));
            int p2 = ((r2 & 0x555) << 1) | ((r2 & 0xAAA) >> 1);
            float2 Z1 = dat[SKI(p1)], Z2 = dat[SKI(p2)];
            float Ar = 0.5f * (Z1.x + Z2.x) * inv64;
            float Ai = 0.5f * (Z1.y - Z2.y) * inv64;
            float Br = 0.5f * (Z1.y + Z2.y) * inv64;
            float Bi = 0.5f * (Z2.x - Z1.x) * inv64;
            float zar = Ar * gr - Ai * gi, zai = Ar * gi + Ai * gr;
            float ma = sqrtf(zar * zar + zai * zai);
            float sa = fmaxf(ma + bias, 0.f) / fmaxf(ma, 1e-12f) * inv64;
            zar *= sa; zai *= sa;
            float zbr = Br * gr - Bi * gi, zbi = Br * gi + Bi * gr;
            float mb = sqrtf(zbr * zbr + zbi * zbi);
            float sb = fmaxf(mb + bias, 0.f) / fmaxf(mb, 1e-12f) * inv64;
            zbr *= sb; zbi *= sb;
            dat[SKI(p1)] = make_float2(zar - zbi, zai + zbr);
            dat[SKI(p2)] = make_float2(zar + zbi, zbr - zai);
        }
    }
    __syncthreads();

    #pragma unroll
    for (int t = 5; t >= 0; t--) {
        const int lq = 10 - 2 * t;
        const int Q = 1 << lq;
        const int step = 1 << (10 - lq);
        #pragma unroll 2
        for (int q = tid; q < 1024; q += 512) {
            int j  = q & (Q - 1);
            int i0 = ((q >> lq) << (lq + 2)) | j;
            float2 x0 = dat[SKI(i0)];
            float2 x1 = dat[SKI(i0 + Q)];
            float2 x2 = dat[SKI(i0 + 2 * Q)];
            float2 x3 = dat[SKI(i0 + 3 * Q)];
            float2 w1 = tw[j * step];
            float2 w2 = tw[2 * j * step];
            float2 w3 = cmul(w1, w2);
            float2 u1 = cmulc(x1, w1);
            float2 u2 = cmulc(x2, w2);
            float2 u3 = cmulc(x3, w3);
            float2 s0 = make_float2(x0.x + u2.x, x0.y + u2.y);
            float2 s1 = make_float2(x0.x - u2.x, x0.y - u2.y);
            float2 s2 = make_float2(u1.x + u3.x, u1.y + u3.y);
            float2 s3 = make_float2(u1.x - u3.x, u1.y - u3.y);
            dat[SKI(i0)]         = make_float2(s0.x + s2.x, s0.y + s2.y);
            dat[SKI(i0 + Q)]     = make_float2(s1.x - s3.y, s1.y + s3.x);
            dat[SKI(i0 + 2 * Q)] = make_float2(s0.x - s2.x, s0.y - s2.y);
            dat[SKI(i0 + 3 * Q)] = make_float2(s1.x + s3.y, s1.y - s3.x);
        }
        __syncthreads();
    }

    float* oa = g_At + ((size_t)((b * H_ + h) * DH_ + 2 * p)) * S_;
    float* ob = oa + S_;
    for (int i = tid; i < NFFT; i += 512) {
        float2 z = dat[SKI(i)];
        oa[i] = z.x;
        ob[i] = z.y;
    }
}

// ---------------- launch ----------------
extern "C" void kernel_launch(void* const* d_in, const int* in_sizes, int n_in,
                              void* d_out, int out_size) {
    const float* x     = (const float*)d_in[0];
    const float* Wq    = (const float*)d_in[1];
    const float* Wv    = (const float*)d_in[2];
    const float* Wo    = (const float*)d_in[3];
    const float* gamma = (const float*)d_in[4];
    const float* beta  = (const float*)d_in[5];
    const float* w1    = (const float*)d_in[6];
    const float* b1    = (const float*)d_in[7];
    const float* w2    = (const float*)d_in[8];
    const float* b2    = (const float*)d_in[9];
    const float* mbias = (const float*)d_in[10];
    float* out = (float*)d_out;

    float *vt = nullptr, *at = nullptr;
    cudaGetSymbolAddress((void**)&vt, g_Vt);
    cudaGetSymbolAddress((void**)&at, g_At);

    // smem (bytes):
    // V (row-major A, TSTORE): 2 buffers * (2*128*40 + 2*128*40) * 2B = 81920 ; Ct 67584 aliases
    // O (col-major A):         2 buffers * (2*32*136 + 2*128*40) * 2B = 75776
    // FFT: (4352 + 2048) * 8 = 51200
    const int smem_v   = 2 * (2 * 128 * 40 + 2 * 128 * 40) * 2;
    const int smem_o   = 2 * (2 * 32 * 136 + 2 * 128 * 40) * 2;
    const int smem_fft = (4352 + 2048) * 8;

    cudaFuncSetAttribute(k_gemm<false, true>,  cudaFuncAttributeMaxDynamicSharedMemorySize, smem_v);
    cudaFuncSetAttribute(k_gemm<true,  false>, cudaFuncAttributeMaxDynamicSharedMemorySize, smem_o);
    cudaFuncSetAttribute(k_fft,                cudaFuncAttributeMaxDynamicSharedMemorySize, smem_fft);

    // gate path (tiny) + twiddles
    k_twiddle<<<8, 256>>>();
    k_xpart<<<dim3(8, 32, 4), 128>>>(x);
    k_xsum<<<dim3(8, 4), 128>>>();
    k_meanq<<<dim3(128, 4), 256>>>(Wq);
    k_lnmlp1<<<4, 256>>>(gamma, beta, w1, b1);
    k_mlp2<<<dim3((2 * NF_ + 3) / 4, 4), 128>>>(w2, b2);

    // V projection (bf16-split WMMA), transposed output [b][c][s]
    k_gemm<false, true><<<dim3(8, 128), 256, smem_v>>>(x, Wv, vt);

    // fused spectral mixer
    k_fft<<<dim3(32, 16, 4), 512, smem_fft>>>(mbias);

    // output projection (bf16-split WMMA) from transposed attn layout
    k_gemm<true, false><<<dim3(8, 128), 256, smem_o>>>(at, Wo, out);
}

// round 8
// speedup vs baseline: 2.5468x; 1.3194x over previous
#include <cuda_runtime.h>
#include <cuda_bf16.h>
#include <mma.h>
#include <math.h>
#include <stdint.h>

using namespace nvcuda;

#define B_    4
#define S_    4096
#define D_    1024
#define H_    16
#define DH_   64
#define NF_   2049
#define NFFT  4096
#define LOGN  12

// ---------------- scratch (device globals; no allocations allowed) ----------------
__device__ float  g_Vt[(size_t)B_ * D_ * S_];        // V transposed: [b][c][s] fp32 (FFT input)
__device__ __nv_bfloat16 g_xh[(size_t)B_ * S_ * D_]; // x split hi (row-major [m][k])
__device__ __nv_bfloat16 g_xl[(size_t)B_ * S_ * D_];
__device__ __nv_bfloat16 g_Wvh[D_ * D_], g_Wvl[D_ * D_];
__device__ __nv_bfloat16 g_Woh[D_ * D_], g_Wol[D_ * D_];
__device__ __nv_bfloat16 g_Ath[(size_t)B_ * D_ * S_]; // attn split hi: [b][c][s]
__device__ __nv_bfloat16 g_Atl[(size_t)B_ * D_ * S_];
__device__ float2 g_tw[NFFT / 2];
__device__ float  g_xpart[B_ * 32 * D_];
__device__ float  g_xsum[B_ * D_];
__device__ float  g_meanq[B_ * D_];
__device__ float  g_hdn[B_ * D_];
__device__ float  g_gri[B_ * 2 * NF_];

// ---------------- small helpers ----------------
__device__ __forceinline__ uint32_t smem_u32(const void* p) {
    uint32_t a;
    asm("{ .reg .u64 t; cvta.to.shared.u64 t, %1; cvt.u32.u64 %0, t; }" : "=r"(a) : "l"(p));
    return a;
}
__device__ __forceinline__ void cpa16(uint32_t dst, const void* src) {
    asm volatile("cp.async.cg.shared.global [%0], [%1], 16;" :: "r"(dst), "l"(src));
}
#define CP_COMMIT() asm volatile("cp.async.commit_group;" ::: "memory")
#define CP_WAIT1()  asm volatile("cp.async.wait_group 1;"  ::: "memory")
#define CP_WAIT0()  asm volatile("cp.async.wait_group 0;"  ::: "memory")

// bf16 hi/lo split of two floats, packed as bf16x2 words
__device__ __forceinline__ void split2(float v0, float v1, uint32_t& hi, uint32_t& lo) {
    __nv_bfloat16 h0 = __float2bfloat16(v0);
    __nv_bfloat16 h1 = __float2bfloat16(v1);
    __nv_bfloat16 l0 = __float2bfloat16(v0 - __bfloat162float(h0));
    __nv_bfloat16 l1 = __float2bfloat16(v1 - __bfloat162float(h1));
    hi = ((uint32_t)__bfloat16_as_ushort(h1) << 16) | __bfloat16_as_ushort(h0);
    lo = ((uint32_t)__bfloat16_as_ushort(l1) << 16) | __bfloat16_as_ushort(l0);
}

// ---------------- split kernel (fp32 -> hi/lo bf16 planes) ----------------
__global__ void __launch_bounds__(256) k_split(const float4* __restrict__ src,
                                               __nv_bfloat16* __restrict__ hi,
                                               __nv_bfloat16* __restrict__ lo) {
    int i = blockIdx.x * 256 + threadIdx.x;
    float4 v = src[i];
    uint32_t h01, l01, h23, l23;
    split2(v.x, v.y, h01, l01);
    split2(v.z, v.w, h23, l23);
    ((uint2*)hi)[i] = make_uint2(h01, h23);
    ((uint2*)lo)[i] = make_uint2(l01, l23);
}

// ---------------- twiddle table ----------------
__global__ void __launch_bounds__(256) k_twiddle() {
    int i = blockIdx.x * blockDim.x + threadIdx.x;
    if (i < NFFT / 2) {
        double ang = -6.283185307179586476925286766559 * (double)i / (double)NFFT;
        g_tw[i] = make_float2((float)cos(ang), (float)sin(ang));
    }
}

// ---------------- gate path (tiny) ----------------
__global__ void __launch_bounds__(128) k_xpart(const float* __restrict__ x) {
    int d = blockIdx.x * 128 + threadIdx.x;
    int chunk = blockIdx.y;
    int b = blockIdx.z;
    const float* p = x + ((size_t)b * S_ + (size_t)chunk * 128) * D_ + d;
    float acc = 0.f;
    #pragma unroll 4
    for (int s = 0; s < 128; s++) acc += p[(size_t)s * D_];
    g_xpart[(b * 32 + chunk) * D_ + d] = acc;
}

__global__ void __launch_bounds__(128) k_xsum() {
    int d = blockIdx.x * 128 + threadIdx.x;
    int b = blockIdx.y;
    float acc = 0.f;
    #pragma unroll
    for (int q = 0; q < 32; q++) acc += g_xpart[(b * 32 + q) * D_ + d];
    g_xsum[b * D_ + d] = acc;
}

__global__ void __launch_bounds__(256) k_meanq(const float* __restrict__ Wq) {
    int warp = threadIdx.x >> 5, lane = threadIdx.x & 31;
    int c = blockIdx.x * 8 + warp;
    int b = blockIdx.y;
    const float* w  = Wq + (size_t)c * D_;
    const float* xm = g_xsum + b * D_;
    float acc = 0.f;
    #pragma unroll 8
    for (int i = lane; i < D_; i += 32) acc += xm[i] * w[i];
    #pragma unroll
    for (int o = 16; o; o >>= 1) acc += __shfl_xor_sync(0xffffffffu, acc, o);
    if (lane == 0) g_meanq[b * D_ + c] = acc * (1.0f / S_);
}

__global__ void __launch_bounds__(256) k_lnmlp1(const float* __restrict__ gamma,
                                                const float* __restrict__ beta,
                                                const float* __restrict__ w1,
                                                const float* __restrict__ b1) {
    __shared__ float sv[16][64];
    __shared__ float sq[64];
    __shared__ float smean[16], srstd[16];
    int b = blockIdx.x;
    int t = threadIdx.x;

    #pragma unroll
    for (int r = 0; r < 4; r++) {
        int c = t + r * 256;
        sv[c >> 6][c & 63] = g_meanq[b * D_ + c];
    }
    __syncthreads();
    if (t < 16) {
        float m = 0.f;
        for (int q = 0; q < 64; q++) m += sv[t][q];
        m *= (1.f / 64.f);
        float var = 0.f;
        for (int q = 0; q < 64; q++) { float dd = sv[t][q] - m; var += dd * dd; }
        var *= (1.f / 64.f);
        smean[t] = m;
        srstd[t] = rsqrtf(var + 1e-5f);
    }
    __syncthreads();
    #pragma unroll
    for (int r = 0; r < 4; r++) {
        int c = t + r * 256;
        int h = c >> 6, j = c & 63;
        sv[h][j] = (sv[h][j] - smean[h]) * srstd[h] * gamma[j] + beta[j];
    }
    __syncthreads();
    if (t < 64) {
        float m = 0.f;
        for (int q = 0; q < 16; q++) m += sv[q][t];
        sq[t] = m * (1.f / 16.f);
    }
    __syncthreads();
    #pragma unroll
    for (int r = 0; r < 4; r++) {
        int c = t + r * 256;
        float acc = b1[c];
        const float* wr = w1 + (size_t)c * 64;
        #pragma unroll 8
        for (int q = 0; q < 64; q++) acc += sq[q] * wr[q];
        g_hdn[b * D_ + c] = 0.5f * acc * (1.f + erff(acc * 0.70710678118654752f));
    }
}

__global__ void __launch_bounds__(128) k_mlp2(const float* __restrict__ w2,
                                              const float* __restrict__ b2) {
    int warp = threadIdx.x >> 5, lane = threadIdx.x & 31;
    int r = blockIdx.x * 4 + warp;
    int b = blockIdx.y;
    if (r >= 2 * NF_) return;
    const float* hd = g_hdn + b * D_;
    const float* w  = w2 + (size_t)r * D_;
    float acc = 0.f;
    for (int i = lane; i < D_; i += 32) acc += hd[i] * w[i];
    #pragma unroll
    for (int o = 16; o; o >>= 1) acc += __shfl_xor_sync(0xffffffffu, acc, o);
    if (lane == 0) g_gri[b * 2 * NF_ + r] = acc + b2[r];
}

// =================================================================
// bf16-split WMMA GEMM on pre-split hi/lo planes.
// C[m,n] = sum_k A[m,k]*W[n,k]; 3 products aH*bH + aL*bH + aH*bL.
// Block 256(M) x 128(N) x 32(K); 8 warps, 64x64 warp tiles.
// cp.async double-buffered staging; pure HMMA mainloop.
// ACOL:   A planes are [b][k][s] bf16 (FFT output); else row-major [m][k].
// TSTORE: write C^T to [b][n][s] fp32; else row-major.
// =================================================================
template <bool ACOL, bool TSTORE>
__global__ void __launch_bounds__(256, 1) k_gemm(const __nv_bfloat16* __restrict__ Ah,
                                                 const __nv_bfloat16* __restrict__ Al,
                                                 const __nv_bfloat16* __restrict__ Wh,
                                                 const __nv_bfloat16* __restrict__ Wl,
                                                 float* __restrict__ C) {
    extern __shared__ __align__(16) char smraw[];
    __nv_bfloat16* sb = (__nv_bfloat16*)smraw;
    float* smf = (float*)smraw;
    const uint32_t sb_u32 = smem_u32(sb);

    constexpr int ASZ = ACOL ? 32 * 264 : 256 * 40;   // one A plane, bf16 elems
    constexpr int WSZ = 128 * 40;                     // one W plane
    constexpr int BUF = 2 * ASZ + 2 * WSZ;            // AH|AL|WH|WL

    const int tid = threadIdx.x;
    const int warp = tid >> 5;
    const int wm = warp & 3;   // 4 warps along M, 64 rows each
    const int wn = warp >> 2;  // 2 warps along N, 64 cols each
    const int n0 = blockIdx.x * 128;
    const int m0 = blockIdx.y * 256;
    const int bb = m0 >> 12, s0 = m0 & 4095;

    auto ISSUE = [&](int kt, int jb) {
        uint32_t base = sb_u32 + (uint32_t)jb * BUF * 2;
        if constexpr (ACOL) {
            #pragma unroll
            for (int t = 0; t < 4; t++) {
                int idx = tid + t * 256;
                int col = idx >> 5, ch = (idx & 31) * 8;
                size_t g = ((size_t)(bb * D_ + kt * 32 + col)) * S_ + s0 + ch;
                cpa16(base + (uint32_t)(col * 264 + ch) * 2, Ah + g);
                cpa16(base + (uint32_t)(ASZ + col * 264 + ch) * 2, Al + g);
            }
        } else {
            #pragma unroll
            for (int t = 0; t < 4; t++) {
                int idx = tid + t * 256;
                int row = idx >> 2, ch = (idx & 3) * 8;
                size_t g = (size_t)(m0 + row) * D_ + kt * 32 + ch;
                cpa16(base + (uint32_t)(row * 40 + ch) * 2, Ah + g);
                cpa16(base + (uint32_t)(ASZ + row * 40 + ch) * 2, Al + g);
            }
        }
        #pragma unroll
        for (int t = 0; t < 2; t++) {
            int idx = tid + t * 256;
            int row = idx >> 2, ch = (idx & 3) * 8;
            size_t g = (size_t)(n0 + row) * D_ + kt * 32 + ch;
            cpa16(base + (uint32_t)(2 * ASZ + row * 40 + ch) * 2, Wh + g);
            cpa16(base + (uint32_t)(2 * ASZ + WSZ + row * 40 + ch) * 2, Wl + g);
        }
        CP_COMMIT();
    };

    wmma::fragment<wmma::accumulator, 16, 16, 16, float> acc[4][4];
    #pragma unroll
    for (int i = 0; i < 4; i++)
        #pragma unroll
        for (int j = 0; j < 4; j++) wmma::fill_fragment(acc[i][j], 0.0f);

    ISSUE(0, 0);

    for (int it = 0; it < 32; it++) {
        const bool pf = (it + 1 < 32);
        if (pf) { ISSUE(it + 1, (it + 1) & 1); CP_WAIT1(); }
        else    { CP_WAIT0(); }
        __syncthreads();

        const __nv_bfloat16* base = sb + (it & 1) * BUF;
        const __nv_bfloat16* Ahs = base;
        const __nv_bfloat16* Als = base + ASZ;
        const __nv_bfloat16* Whs = base + 2 * ASZ;
        const __nv_bfloat16* Wls = Whs + WSZ;

        #pragma unroll
        for (int kk = 0; kk < 32; kk += 16) {
            wmma::fragment<wmma::matrix_b, 16, 16, 16, __nv_bfloat16, wmma::col_major> bH[4], bL[4];
            #pragma unroll
            for (int j = 0; j < 4; j++) {
                wmma::load_matrix_sync(bH[j], Whs + (wn * 64 + j * 16) * 40 + kk, 40);
                wmma::load_matrix_sync(bL[j], Wls + (wn * 64 + j * 16) * 40 + kk, 40);
            }
            #pragma unroll
            for (int i = 0; i < 4; i++) {
                if constexpr (ACOL) {
                    wmma::fragment<wmma::matrix_a, 16, 16, 16, __nv_bfloat16, wmma::col_major> aH, aL;
                    wmma::load_matrix_sync(aH, Ahs + kk * 264 + wm * 64 + i * 16, 264);
                    wmma::load_matrix_sync(aL, Als + kk * 264 + wm * 64 + i * 16, 264);
                    #pragma unroll
                    for (int j = 0; j < 4; j++) {
                        wmma::mma_sync(acc[i][j], aH, bH[j], acc[i][j]);
                        wmma::mma_sync(acc[i][j], aL, bH[j], acc[i][j]);
                        wmma::mma_sync(acc[i][j], aH, bL[j], acc[i][j]);
                    }
                } else {
                    wmma::fragment<wmma::matrix_a, 16, 16, 16, __nv_bfloat16, wmma::row_major> aH, aL;
                    wmma::load_matrix_sync(aH, Ahs + (wm * 64 + i * 16) * 40 + kk, 40);
                    wmma::load_matrix_sync(aL, Als + (wm * 64 + i * 16) * 40 + kk, 40);
                    #pragma unroll
                    for (int j = 0; j < 4; j++) {
                        wmma::mma_sync(acc[i][j], aH, bH[j], acc[i][j]);
                        wmma::mma_sync(acc[i][j], aL, bH[j], acc[i][j]);
                        wmma::mma_sync(acc[i][j], aH, bL[j], acc[i][j]);
                    }
                }
            }
        }
        __syncthreads();
    }

    if constexpr (TSTORE) {
        // C^T via smem: Ct[n][m], ld=264 floats (aliases the buffers)
        float* Ct = smf;
        #pragma unroll
        for (int i = 0; i < 4; i++)
            #pragma unroll
            for (int j = 0; j < 4; j++)
                wmma::store_matrix_sync(Ct + (wn * 64 + j * 16) * 264 + wm * 64 + i * 16,
                                        acc[i][j], 264, wmma::mem_col_major);
        __syncthreads();
        #pragma unroll
        for (int t = 0; t < 32; t++) {
            int idx = tid + t * 256;
            int n = idx >> 6, mm = (idx & 63) * 4;
            float4 v = *(float4*)(Ct + n * 264 + mm);
            *(float4*)(C + ((size_t)(bb * D_ + n0 + n)) * S_ + s0 + mm) = v;
        }
    } else {
        #pragma unroll
        for (int i = 0; i < 4; i++)
            #pragma unroll
            for (int j = 0; j < 4; j++)
                wmma::store_matrix_sync(C + (size_t)(m0 + wm * 64 + i * 16) * D_ + n0 + wn * 64 + j * 16,
                                        acc[i][j], D_, wmma::mem_row_major);
    }
}

// ---------------- fused radix-4 FFT -> gate*modReLU -> iFFT ----------------
__device__ __forceinline__ int SKI(int i) { return i + (i >> 4); }
__device__ __forceinline__ float2 cmul(float2 a, float2 b) {
    return make_float2(a.x * b.x - a.y * b.y, a.x * b.y + a.y * b.x);
}
__device__ __forceinline__ float2 cmulc(float2 a, float2 b) {  // a * conj(b)
    return make_float2(a.x * b.x + a.y * b.y, a.y * b.x - a.x * b.y);
}

__global__ void __launch_bounds__(512) k_fft(const float* __restrict__ mbias) {
    extern __shared__ float2 sd[];
    float2* dat = sd;              // skewed, 4096 + 256 slots
    float2* tw  = sd + 4352;       // 2048

    const int tid = threadIdx.x;
    const int p = blockIdx.x;
    const int h = blockIdx.y;
    const int b = blockIdx.z;

    const float* va = g_Vt + ((size_t)((b * H_ + h) * DH_ + 2 * p)) * S_;
    const float* vb = va + S_;
    for (int i = tid; i < NFFT; i += 512) dat[SKI(i)] = make_float2(va[i], vb[i]);
    for (int i = tid; i < NFFT / 2; i += 512) tw[i] = g_tw[i];
    __syncthreads();

    #pragma unroll
    for (int t = 0; t < 6; t++) {
        const int lq = 10 - 2 * t;
        const int Q = 1 << lq;
        const int step = 1 << (10 - lq);
        #pragma unroll 2
        for (int q = tid; q < 1024; q += 512) {
            int j  = q & (Q - 1);
            int i0 = ((q >> lq) << (lq + 2)) | j;
            float2 x0 = dat[SKI(i0)];
            float2 x1 = dat[SKI(i0 + Q)];
            float2 x2 = dat[SKI(i0 + 2 * Q)];
            float2 x3 = dat[SKI(i0 + 3 * Q)];
            float2 t0 = make_float2(x0.x + x2.x, x0.y + x2.y);
            float2 t1 = make_float2(x0.x - x2.x, x0.y - x2.y);
            float2 t2 = make_float2(x1.x + x3.x, x1.y + x3.y);
            float2 t3 = make_float2(x1.x - x3.x, x1.y - x3.y);
            float2 w1 = tw[j * step];
            float2 w2 = tw[2 * j * step];
            float2 w3 = cmul(w1, w2);
            dat[SKI(i0)]         = make_float2(t0.x + t2.x, t0.y + t2.y);
            dat[SKI(i0 + Q)]     = cmul(make_float2(t1.x + t3.y, t1.y - t3.x), w1);
            dat[SKI(i0 + 2 * Q)] = cmul(make_float2(t0.x - t2.x, t0.y - t2.y), w2);
            dat[SKI(i0 + 3 * Q)] = cmul(make_float2(t1.x - t3.y, t1.y + t3.x), w3);
        }
        __syncthreads();
    }

    const float bias = mbias[0];
    const float inv64 = 1.0f / 64.0f;
    const float* grb = g_gri + b * 2 * NF_;
    for (int k = tid; k <= NFFT / 2; k += 512) {
        float gr = grb[k];
        float gi = grb[NF_ + k];
        int r1 = (int)(__brev((unsigned)k) >> (32 - LOGN));
        int p1 = ((r1 & 0x555) << 1) | ((r1 & 0xAAA) >> 1);
        if (k == 0 || k == NFFT / 2) {
            float2 Z = dat[SKI(p1)];
            float Av = Z.x * inv64, Bv = Z.y * inv64;
            float ar = Av * gr, ai = Av * gi;
            float ma = sqrtf(ar * ar + ai * ai);
            float sa = fmaxf(ma + bias, 0.f) / fmaxf(ma, 1e-12f);
            float Aout = ar * sa * inv64;
            float br2 = Bv * gr, bi2 = Bv * gi;
            float mb = sqrtf(br2 * br2 + bi2 * bi2);
            float sb = fmaxf(mb + bias, 0.f) / fmaxf(mb, 1e-12f);
            float Bout = br2 * sb * inv64;
            dat[SKI(p1)] = make_float2(Aout, Bout);
        } else {
            int r2 = (int)(__brev((unsigned)(NFFT - k)) >> (32 - LOGN));
            int p2 = ((r2 & 0x555) << 1) | ((r2 & 0xAAA) >> 1);
            float2 Z1 = dat[SKI(p1)], Z2 = dat[SKI(p2)];
            float Ar = 0.5f * (Z1.x + Z2.x) * inv64;
            float Ai = 0.5f * (Z1.y - Z2.y) * inv64;
            float Br = 0.5f * (Z1.y + Z2.y) * inv64;
            float Bi = 0.5f * (Z2.x - Z1.x) * inv64;
            float zar = Ar * gr - Ai * gi, zai = Ar * gi + Ai * gr;
            float ma = sqrtf(zar * zar + zai * zai);
            float sa = fmaxf(ma + bias, 0.f) / fmaxf(ma, 1e-12f) * inv64;
            zar *= sa; zai *= sa;
            float zbr = Br * gr - Bi * gi, zbi = Br * gi + Bi * gr;
            float mb = sqrtf(zbr * zbr + zbi * zbi);
            float sb = fmaxf(mb + bias, 0.f) / fmaxf(mb, 1e-12f) * inv64;
            zbr *= sb; zbi *= sb;
            dat[SKI(p1)] = make_float2(zar - zbi, zai + zbr);
            dat[SKI(p2)] = make_float2(zar + zbi, zbr - zai);
        }
    }
    __syncthreads();

    #pragma unroll
    for (int t = 5; t >= 0; t--) {
        const int lq = 10 - 2 * t;
        const int Q = 1 << lq;
        const int step = 1 << (10 - lq);
        #pragma unroll 2
        for (int q = tid; q < 1024; q += 512) {
            int j  = q & (Q - 1);
            int i0 = ((q >> lq) << (lq + 2)) | j;
            float2 x0 = dat[SKI(i0)];
            float2 x1 = dat[SKI(i0 + Q)];
            float2 x2 = dat[SKI(i0 + 2 * Q)];
            float2 x3 = dat[SKI(i0 + 3 * Q)];
            float2 w1 = tw[j * step];
            float2 w2 = tw[2 * j * step];
            float2 w3 = cmul(w1, w2);
            float2 u1 = cmulc(x1, w1);
            float2 u2 = cmulc(x2, w2);
            float2 u3 = cmulc(x3, w3);
            float2 s0 = make_float2(x0.x + u2.x, x0.y + u2.y);
            float2 s1 = make_float2(x0.x - u2.x, x0.y - u2.y);
            float2 s2 = make_float2(u1.x + u3.x, u1.y + u3.y);
            float2 s3 = make_float2(u1.x - u3.x, u1.y - u3.y);
            dat[SKI(i0)]         = make_float2(s0.x + s2.x, s0.y + s2.y);
            dat[SKI(i0 + Q)]     = make_float2(s1.x - s3.y, s1.y + s3.x);
            dat[SKI(i0 + 2 * Q)] = make_float2(s0.x - s2.x, s0.y - s2.y);
            dat[SKI(i0 + 3 * Q)] = make_float2(s1.x + s3.y, s1.y - s3.x);
        }
        __syncthreads();
    }

    // emit attn already split into hi/lo bf16 planes (O-GEMM A operand)
    size_t ra = ((size_t)((b * H_ + h) * DH_ + 2 * p)) * S_;
    size_t rb = ra + S_;
    for (int ii = tid; ii < 2048; ii += 512) {
        int i0 = ii * 2;
        float2 z0 = dat[SKI(i0)], z1 = dat[SKI(i0 + 1)];
        uint32_t hw, lw;
        split2(z0.x, z1.x, hw, lw);
        *(uint32_t*)(g_Ath + ra + i0) = hw;
        *(uint32_t*)(g_Atl + ra + i0) = lw;
        split2(z0.y, z1.y, hw, lw);
        *(uint32_t*)(g_Ath + rb + i0) = hw;
        *(uint32_t*)(g_Atl + rb + i0) = lw;
    }
}

// ---------------- launch ----------------
extern "C" void kernel_launch(void* const* d_in, const int* in_sizes, int n_in,
                              void* d_out, int out_size) {
    const float* x     = (const float*)d_in[0];
    const float* Wq    = (const float*)d_in[1];
    const float* Wv    = (const float*)d_in[2];
    const float* Wo    = (const float*)d_in[3];
    const float* gamma = (const float*)d_in[4];
    const float* beta  = (const float*)d_in[5];
    const float* w1    = (const float*)d_in[6];
    const float* b1    = (const float*)d_in[7];
    const float* w2    = (const float*)d_in[8];
    const float* b2    = (const float*)d_in[9];
    const float* mbias = (const float*)d_in[10];
    float* out = (float*)d_out;

    float *vt = nullptr;
    __nv_bfloat16 *xh, *xl, *wvh, *wvl, *woh, *wol, *ath, *atl;
    cudaGetSymbolAddress((void**)&vt,  g_Vt);
    cudaGetSymbolAddress((void**)&xh,  g_xh);
    cudaGetSymbolAddress((void**)&xl,  g_xl);
    cudaGetSymbolAddress((void**)&wvh, g_Wvh);
    cudaGetSymbolAddress((void**)&wvl, g_Wvl);
    cudaGetSymbolAddress((void**)&woh, g_Woh);
    cudaGetSymbolAddress((void**)&wol, g_Wol);
    cudaGetSymbolAddress((void**)&ath, g_Ath);
    cudaGetSymbolAddress((void**)&atl, g_Atl);

    // smem bytes:
    // V-GEMM: buffers 2*(2*256*40 + 2*128*40)*2 = 122880; Ct epi 128*264*4 = 135168 -> 135168
    // O-GEMM: buffers 2*(2*32*264 + 2*128*40)*2 = 108544
    // FFT: (4352 + 2048)*8 = 51200
    const int smem_v   = 135168;
    const int smem_o   = 108544;
    const int smem_fft = (4352 + 2048) * 8;

    cudaFuncSetAttribute(k_gemm<false, true>,  cudaFuncAttributeMaxDynamicSharedMemorySize, smem_v);
    cudaFuncSetAttribute(k_gemm<true,  false>, cudaFuncAttributeMaxDynamicSharedMemorySize, smem_o);
    cudaFuncSetAttribute(k_fft,                cudaFuncAttributeMaxDynamicSharedMemorySize, smem_fft);

    // pre-split inputs + twiddles
    k_split<<<16384, 256>>>((const float4*)x, xh, xl);
    k_split<<<1024, 256>>>((const float4*)Wv, wvh, wvl);
    k_split<<<1024, 256>>>((const float4*)Wo, woh, wol);
    k_twiddle<<<8, 256>>>();

    // gate path (tiny)
    k_xpart<<<dim3(8, 32, 4), 128>>>(x);
    k_xsum<<<dim3(8, 4), 128>>>();
    k_meanq<<<dim3(128, 4), 256>>>(Wq);
    k_lnmlp1<<<4, 256>>>(gamma, beta, w1, b1);
    k_mlp2<<<dim3((2 * NF_ + 3) / 4, 4), 128>>>(w2, b2);

    // V projection, transposed output [b][c][s] fp32
    k_gemm<false, true><<<dim3(8, 64), 256, smem_v>>>(xh, xl, wvh, wvl, vt);

    // fused spectral mixer (emits split attn planes)
    k_fft<<<dim3(32, 16, 4), 512, smem_fft>>>(mbias);

    // output projection from split attn planes
    k_gemm<true, false><<<dim3(8, 64), 256, smem_o>>>(ath, atl, woh, wol, out);
}

// round 9
// speedup vs baseline: 2.7529x; 1.0809x over previous
#include <cuda_runtime.h>
#include <cuda_bf16.h>
#include <mma.h>
#include <math.h>
#include <stdint.h>

using namespace nvcuda;

#define B_    4
#define S_    4096
#define D_    1024
#define H_    16
#define DH_   64
#define NF_   2049
#define NFFT  4096
#define LOGN  12

// ---------------- scratch (device globals; no allocations allowed) ----------------
__device__ float  g_Vt[(size_t)B_ * D_ * S_];        // V transposed: [b][c][s] fp32 (FFT input)
__device__ __nv_bfloat16 g_xh[(size_t)B_ * S_ * D_]; // x split hi (row-major [m][k])
__device__ __nv_bfloat16 g_xl[(size_t)B_ * S_ * D_];
__device__ __nv_bfloat16 g_Wvh[D_ * D_], g_Wvl[D_ * D_];
__device__ __nv_bfloat16 g_Woh[D_ * D_], g_Wol[D_ * D_];
__device__ __nv_bfloat16 g_Ath[(size_t)B_ * D_ * S_]; // attn split hi: [b][c][s]
__device__ __nv_bfloat16 g_Atl[(size_t)B_ * D_ * S_];
__device__ float2 g_tw[NFFT];                        // full table e^{-2*pi*i*k/N}, k<4096
__device__ float  g_xpart[B_ * 32 * D_];
__device__ float  g_xsum[B_ * D_];
__device__ float  g_meanq[B_ * D_];
__device__ float  g_hdn[B_ * D_];
__device__ float  g_gri[B_ * 2 * NF_];

// ---------------- small helpers ----------------
__device__ __forceinline__ uint32_t smem_u32(const void* p) {
    uint32_t a;
    asm("{ .reg .u64 t; cvta.to.shared.u64 t, %1; cvt.u32.u64 %0, t; }" : "=r"(a) : "l"(p));
    return a;
}
__device__ __forceinline__ void cpa16(uint32_t dst, const void* src) {
    asm volatile("cp.async.cg.shared.global [%0], [%1], 16;" :: "r"(dst), "l"(src));
}
#define CP_COMMIT() asm volatile("cp.async.commit_group;" ::: "memory")
#define CP_WAIT1()  asm volatile("cp.async.wait_group 1;"  ::: "memory")
#define CP_WAIT0()  asm volatile("cp.async.wait_group 0;"  ::: "memory")

// bf16 hi/lo split of two floats, packed as bf16x2 words
__device__ __forceinline__ void split2(float v0, float v1, uint32_t& hi, uint32_t& lo) {
    __nv_bfloat16 h0 = __float2bfloat16(v0);
    __nv_bfloat16 h1 = __float2bfloat16(v1);
    __nv_bfloat16 l0 = __float2bfloat16(v0 - __bfloat162float(h0));
    __nv_bfloat16 l1 = __float2bfloat16(v1 - __bfloat162float(h1));
    hi = ((uint32_t)__bfloat16_as_ushort(h1) << 16) | __bfloat16_as_ushort(h0);
    lo = ((uint32_t)__bfloat16_as_ushort(l1) << 16) | __bfloat16_as_ushort(l0);
}

// ---------------- split kernel (fp32 -> hi/lo bf16 planes) ----------------
__global__ void __launch_bounds__(256) k_split(const float4* __restrict__ src,
                                               __nv_bfloat16* __restrict__ hi,
                                               __nv_bfloat16* __restrict__ lo) {
    int i = blockIdx.x * 256 + threadIdx.x;
    float4 v = src[i];
    uint32_t h01, l01, h23, l23;
    split2(v.x, v.y, h01, l01);
    split2(v.z, v.w, h23, l23);
    ((uint2*)hi)[i] = make_uint2(h01, h23);
    ((uint2*)lo)[i] = make_uint2(l01, l23);
}

// ---------------- twiddle table (full 4096) ----------------
__global__ void __launch_bounds__(256) k_twiddle() {
    int i = blockIdx.x * blockDim.x + threadIdx.x;
    if (i < NFFT) {
        double ang = -6.283185307179586476925286766559 * (double)i / (double)NFFT;
        g_tw[i] = make_float2((float)cos(ang), (float)sin(ang));
    }
}

// ---------------- gate path (tiny) ----------------
__global__ void __launch_bounds__(128) k_xpart(const float* __restrict__ x) {
    int d = blockIdx.x * 128 + threadIdx.x;
    int chunk = blockIdx.y;
    int b = blockIdx.z;
    const float* p = x + ((size_t)b * S_ + (size_t)chunk * 128) * D_ + d;
    float acc = 0.f;
    #pragma unroll 4
    for (int s = 0; s < 128; s++) acc += p[(size_t)s * D_];
    g_xpart[(b * 32 + chunk) * D_ + d] = acc;
}

__global__ void __launch_bounds__(128) k_xsum() {
    int d = blockIdx.x * 128 + threadIdx.x;
    int b = blockIdx.y;
    float acc = 0.f;
    #pragma unroll
    for (int q = 0; q < 32; q++) acc += g_xpart[(b * 32 + q) * D_ + d];
    g_xsum[b * D_ + d] = acc;
}

__global__ void __launch_bounds__(256) k_meanq(const float* __restrict__ Wq) {
    int warp = threadIdx.x >> 5, lane = threadIdx.x & 31;
    int c = blockIdx.x * 8 + warp;
    int b = blockIdx.y;
    const float* w  = Wq + (size_t)c * D_;
    const float* xm = g_xsum + b * D_;
    float acc = 0.f;
    #pragma unroll 8
    for (int i = lane; i < D_; i += 32) acc += xm[i] * w[i];
    #pragma unroll
    for (int o = 16; o; o >>= 1) acc += __shfl_xor_sync(0xffffffffu, acc, o);
    if (lane == 0) g_meanq[b * D_ + c] = acc * (1.0f / S_);
}

__global__ void __launch_bounds__(256) k_lnmlp1(const float* __restrict__ gamma,
                                                const float* __restrict__ beta,
                                                const float* __restrict__ w1,
                                                const float* __restrict__ b1) {
    __shared__ float sv[16][64];
    __shared__ float sq[64];
    __shared__ float smean[16], srstd[16];
    int b = blockIdx.x;
    int t = threadIdx.x;

    #pragma unroll
    for (int r = 0; r < 4; r++) {
        int c = t + r * 256;
        sv[c >> 6][c & 63] = g_meanq[b * D_ + c];
    }
    __syncthreads();
    if (t < 16) {
        float m = 0.f;
        for (int q = 0; q < 64; q++) m += sv[t][q];
        m *= (1.f / 64.f);
        float var = 0.f;
        for (int q = 0; q < 64; q++) { float dd = sv[t][q] - m; var += dd * dd; }
        var *= (1.f / 64.f);
        smean[t] = m;
        srstd[t] = rsqrtf(var + 1e-5f);
    }
    __syncthreads();
    #pragma unroll
    for (int r = 0; r < 4; r++) {
        int c = t + r * 256;
        int h = c >> 6, j = c & 63;
        sv[h][j] = (sv[h][j] - smean[h]) * srstd[h] * gamma[j] + beta[j];
    }
    __syncthreads();
    if (t < 64) {
        float m = 0.f;
        for (int q = 0; q < 16; q++) m += sv[q][t];
        sq[t] = m * (1.f / 16.f);
    }
    __syncthreads();
    #pragma unroll
    for (int r = 0; r < 4; r++) {
        int c = t + r * 256;
        float acc = b1[c];
        const float* wr = w1 + (size_t)c * 64;
        #pragma unroll 8
        for (int q = 0; q < 64; q++) acc += sq[q] * wr[q];
        g_hdn[b * D_ + c] = 0.5f * acc * (1.f + erff(acc * 0.70710678118654752f));
    }
}

__global__ void __launch_bounds__(128) k_mlp2(const float* __restrict__ w2,
                                              const float* __restrict__ b2) {
    int warp = threadIdx.x >> 5, lane = threadIdx.x & 31;
    int r = blockIdx.x * 4 + warp;
    int b = blockIdx.y;
    if (r >= 2 * NF_) return;
    const float* hd = g_hdn + b * D_;
    const float* w  = w2 + (size_t)r * D_;
    float acc = 0.f;
    for (int i = lane; i < D_; i += 32) acc += hd[i] * w[i];
    #pragma unroll
    for (int o = 16; o; o >>= 1) acc += __shfl_xor_sync(0xffffffffu, acc, o);
    if (lane == 0) g_gri[b * 2 * NF_ + r] = acc + b2[r];
}

// =================================================================
// bf16-split WMMA GEMM on pre-split hi/lo planes, K=64 stages.
// C[m,n] = sum_k A[m,k]*W[n,k]; 3 products aH*bH + aL*bH + aH*bL.
// Block 256(M) x 128(N) x 64(K); 8 warps, 64x64 warp tiles.
// cp.async double-buffered staging; pure HMMA mainloop; 16 stages.
// ACOL:   A planes are [b][k][s] bf16 (FFT output); else row-major [m][k].
// TSTORE: write C^T to [b][n][s] fp32; else row-major.
// =================================================================
template <bool ACOL, bool TSTORE>
__global__ void __launch_bounds__(256, 1) k_gemm(const __nv_bfloat16* __restrict__ Ah,
                                                 const __nv_bfloat16* __restrict__ Al,
                                                 const __nv_bfloat16* __restrict__ Wh,
                                                 const __nv_bfloat16* __restrict__ Wl,
                                                 float* __restrict__ C) {
    extern __shared__ __align__(16) char smraw[];
    __nv_bfloat16* sb = (__nv_bfloat16*)smraw;
    float* smf = (float*)smraw;
    const uint32_t sb_u32 = smem_u32(sb);

    constexpr int ASZ = ACOL ? 64 * 264 : 256 * 72;   // one A plane, bf16 elems
    constexpr int WSZ = 128 * 72;                     // one W plane
    constexpr int BUF = 2 * ASZ + 2 * WSZ;            // AH|AL|WH|WL

    const int tid = threadIdx.x;
    const int warp = tid >> 5;
    const int wm = warp & 3;   // 4 warps along M, 64 rows each
    const int wn = warp >> 2;  // 2 warps along N, 64 cols each
    const int n0 = blockIdx.x * 128;
    const int m0 = blockIdx.y * 256;
    const int bb = m0 >> 12, s0 = m0 & 4095;

    auto ISSUE = [&](int kt, int jb) {
        uint32_t base = sb_u32 + (uint32_t)jb * BUF * 2;
        if constexpr (ACOL) {
            #pragma unroll
            for (int t = 0; t < 8; t++) {
                int idx = tid + t * 256;
                int row = idx >> 5, ch = (idx & 31) * 8;   // 64 k-rows x 256 m
                size_t g = ((size_t)(bb * D_ + kt * 64 + row)) * S_ + s0 + ch;
                cpa16(base + (uint32_t)(row * 264 + ch) * 2, Ah + g);
                cpa16(base + (uint32_t)(ASZ + row * 264 + ch) * 2, Al + g);
            }
        } else {
            #pragma unroll
            for (int t = 0; t < 8; t++) {
                int idx = tid + t * 256;
                int row = idx >> 3, ch = (idx & 7) * 8;    // 256 m-rows x 64 k
                size_t g = (size_t)(m0 + row) * D_ + kt * 64 + ch;
                cpa16(base + (uint32_t)(row * 72 + ch) * 2, Ah + g);
                cpa16(base + (uint32_t)(ASZ + row * 72 + ch) * 2, Al + g);
            }
        }
        #pragma unroll
        for (int t = 0; t < 4; t++) {
            int idx = tid + t * 256;
            int row = idx >> 3, ch = (idx & 7) * 8;        // 128 n-rows x 64 k
            size_t g = (size_t)(n0 + row) * D_ + kt * 64 + ch;
            cpa16(base + (uint32_t)(2 * ASZ + row * 72 + ch) * 2, Wh + g);
            cpa16(base + (uint32_t)(2 * ASZ + WSZ + row * 72 + ch) * 2, Wl + g);
        }
        CP_COMMIT();
    };

    wmma::fragment<wmma::accumulator, 16, 16, 16, float> acc[4][4];
    #pragma unroll
    for (int i = 0; i < 4; i++)
        #pragma unroll
        for (int j = 0; j < 4; j++) wmma::fill_fragment(acc[i][j], 0.0f);

    ISSUE(0, 0);

    for (int it = 0; it < 16; it++) {
        const bool pf = (it + 1 < 16);
        if (pf) { ISSUE(it + 1, (it + 1) & 1); CP_WAIT1(); }
        else    { CP_WAIT0(); }
        __syncthreads();

        const __nv_bfloat16* base = sb + (it & 1) * BUF;
        const __nv_bfloat16* Ahs = base;
        const __nv_bfloat16* Als = base + ASZ;
        const __nv_bfloat16* Whs = base + 2 * ASZ;
        const __nv_bfloat16* Wls = Whs + WSZ;

        #pragma unroll
        for (int kk = 0; kk < 64; kk += 16) {
            wmma::fragment<wmma::matrix_b, 16, 16, 16, __nv_bfloat16, wmma::col_major> bH[4], bL[4];
            #pragma unroll
            for (int j = 0; j < 4; j++) {
                wmma::load_matrix_sync(bH[j], Whs + (wn * 64 + j * 16) * 72 + kk, 72);
                wmma::load_matrix_sync(bL[j], Wls + (wn * 64 + j * 16) * 72 + kk, 72);
            }
            #pragma unroll
            for (int i = 0; i < 4; i++) {
                if constexpr (ACOL) {
                    wmma::fragment<wmma::matrix_a, 16, 16, 16, __nv_bfloat16, wmma::col_major> aH, aL;
                    wmma::load_matrix_sync(aH, Ahs + kk * 264 + wm * 64 + i * 16, 264);
                    wmma::load_matrix_sync(aL, Als + kk * 264 + wm * 64 + i * 16, 264);
                    #pragma unroll
                    for (int j = 0; j < 4; j++) {
                        wmma::mma_sync(acc[i][j], aH, bH[j], acc[i][j]);
                        wmma::mma_sync(acc[i][j], aL, bH[j], acc[i][j]);
                        wmma::mma_sync(acc[i][j], aH, bL[j], acc[i][j]);
                    }
                } else {
                    wmma::fragment<wmma::matrix_a, 16, 16, 16, __nv_bfloat16, wmma::row_major> aH, aL;
                    wmma::load_matrix_sync(aH, Ahs + (wm * 64 + i * 16) * 72 + kk, 72);
                    wmma::load_matrix_sync(aL, Als + (wm * 64 + i * 16) * 72 + kk, 72);
                    #pragma unroll
                    for (int j = 0; j < 4; j++) {
                        wmma::mma_sync(acc[i][j], aH, bH[j], acc[i][j]);
                        wmma::mma_sync(acc[i][j], aL, bH[j], acc[i][j]);
                        wmma::mma_sync(acc[i][j], aH, bL[j], acc[i][j]);
                    }
                }
            }
        }
        __syncthreads();
    }

    if constexpr (TSTORE) {
        // C^T via smem: Ct[n][m], ld=264 floats (aliases the buffers)
        float* Ct = smf;
        #pragma unroll
        for (int i = 0; i < 4; i++)
            #pragma unroll
            for (int j = 0; j < 4; j++)
                wmma::store_matrix_sync(Ct + (wn * 64 + j * 16) * 264 + wm * 64 + i * 16,
                                        acc[i][j], 264, wmma::mem_col_major);
        __syncthreads();
        #pragma unroll
        for (int t = 0; t < 32; t++) {
            int idx = tid + t * 256;
            int n = idx >> 6, mm = (idx & 63) * 4;
            float4 v = *(float4*)(Ct + n * 264 + mm);
            *(float4*)(C + ((size_t)(bb * D_ + n0 + n)) * S_ + s0 + mm) = v;
        }
    } else {
        #pragma unroll
        for (int i = 0; i < 4; i++)
            #pragma unroll
            for (int j = 0; j < 4; j++)
                wmma::store_matrix_sync(C + (size_t)(m0 + wm * 64 + i * 16) * D_ + n0 + wn * 64 + j * 16,
                                        acc[i][j], D_, wmma::mem_row_major);
    }
}

// ---------------- fused radix-8 FFT -> gate*modReLU -> iFFT ----------------
__device__ __forceinline__ int SKI(int i) { return i + (i >> 4); }
__device__ __forceinline__ float2 cmul(float2 a, float2 b) {
    return make_float2(a.x * b.x - a.y * b.y, a.x * b.y + a.y * b.x);
}
__device__ __forceinline__ float2 cmulc(float2 a, float2 b) {  // a * conj(b)
    return make_float2(a.x * b.x + a.y * b.y, a.y * b.x - a.x * b.y);
}
__device__ __forceinline__ float2 cadd(float2 a, float2 b) { return make_float2(a.x + b.x, a.y + b.y); }
__device__ __forceinline__ float2 csub(float2 a, float2 b) { return make_float2(a.x - b.x, a.y - b.y); }
#define RC8 0.70710678118654752440f

// digit-8 reversal of 4 octal digits (12 bits)
__device__ __forceinline__ int rev8(int k) {
    return ((k & 7) << 9) | (((k >> 3) & 7) << 6) | (((k >> 6) & 7) << 3) | ((k >> 9) & 7);
}

__global__ void __launch_bounds__(512) k_fft(const float* __restrict__ mbias) {
    extern __shared__ float2 sd[];
    float2* dat = sd;              // skewed, 4096 + 256 slots
    float2* tw  = sd + 4352;       // 4096 full table

    const int tid = threadIdx.x;
    const int p = blockIdx.x;
    const int h = blockIdx.y;
    const int b = blockIdx.z;

    const float* va = g_Vt + ((size_t)((b * H_ + h) * DH_ + 2 * p)) * S_;
    const float* vb = va + S_;
    for (int i = tid; i < NFFT; i += 512) dat[SKI(i)] = make_float2(va[i], vb[i]);
    for (int i = tid; i < NFFT; i += 512) tw[i] = g_tw[i];
    __syncthreads();

    // ---- forward radix-8 DIF (natural -> digit8-reversed), 4 stages ----
    #pragma unroll
    for (int t = 0; t < 4; t++) {
        const int lq = 9 - 3 * t;
        const int Q = 1 << lq;
        const int step = 1 << (3 * t);
        const int q = tid;                      // one butterfly per thread
        const int j = q & (Q - 1);
        const int i0 = ((q >> lq) << (lq + 3)) | j;
        float2 x0 = dat[SKI(i0)];
        float2 x1 = dat[SKI(i0 + Q)];
        float2 x2 = dat[SKI(i0 + 2 * Q)];
        float2 x3 = dat[SKI(i0 + 3 * Q)];
        float2 x4 = dat[SKI(i0 + 4 * Q)];
        float2 x5 = dat[SKI(i0 + 5 * Q)];
        float2 x6 = dat[SKI(i0 + 6 * Q)];
        float2 x7 = dat[SKI(i0 + 7 * Q)];
        // even part (x0,x2,x4,x6), omega4 = -i
        float2 s02 = cadd(x0, x4), d02 = csub(x0, x4);
        float2 s26 = cadd(x2, x6), d26 = csub(x2, x6);
        float2 E0 = cadd(s02, s26), E2 = csub(s02, s26);
        float2 E1 = make_float2(d02.x + d26.y, d02.y - d26.x);
        float2 E3 = make_float2(d02.x - d26.y, d02.y + d26.x);
        // odd part (x1,x3,x5,x7)
        float2 s15 = cadd(x1, x5), d15 = csub(x1, x5);
        float2 s37 = cadd(x3, x7), d37 = csub(x3, x7);
        float2 O0 = cadd(s15, s37), O2 = csub(s15, s37);
        float2 O1 = make_float2(d15.x + d37.y, d15.y - d37.x);
        float2 O3 = make_float2(d15.x - d37.y, d15.y + d37.x);
        // rotate odds by omega8^r
        float2 T0 = O0;
        float2 T1 = make_float2(RC8 * (O1.x + O1.y), RC8 * (O1.y - O1.x));   // *c(1-i)
        float2 T2 = make_float2(O2.y, -O2.x);                                 // *(-i)
        float2 T3 = make_float2(RC8 * (O3.y - O3.x), -RC8 * (O3.x + O3.y));  // *(-c(1+i))
        float2 X0 = cadd(E0, T0), X4 = csub(E0, T0);
        float2 X1 = cadd(E1, T1), X5 = csub(E1, T1);
        float2 X2 = cadd(E2, T2), X6 = csub(E2, T2);
        float2 X3 = cadd(E3, T3), X7 = csub(E3, T3);
        const int js = j * step;
        dat[SKI(i0)]         = X0;
        dat[SKI(i0 + Q)]     = cmul(X1, tw[js]);
        dat[SKI(i0 + 2 * Q)] = cmul(X2, tw[2 * js]);
        dat[SKI(i0 + 3 * Q)] = cmul(X3, tw[3 * js]);
        dat[SKI(i0 + 4 * Q)] = cmul(X4, tw[4 * js]);
        dat[SKI(i0 + 5 * Q)] = cmul(X5, tw[5 * js]);
        dat[SKI(i0 + 6 * Q)] = cmul(X6, tw[6 * js]);
        dat[SKI(i0 + 7 * Q)] = cmul(X7, tw[7 * js]);
        __syncthreads();
    }

    // ---- spectral: Hermitian separation, ortho scale, gate, modReLU ----
    const float bias = mbias[0];
    const float inv64 = 1.0f / 64.0f;
    const float* grb = g_gri + b * 2 * NF_;
    for (int k = tid; k <= NFFT / 2; k += 512) {
        float gr = grb[k];
        float gi = grb[NF_ + k];
        int p1 = rev8(k);
        if (k == 0 || k == NFFT / 2) {
            float2 Z = dat[SKI(p1)];
            float Av = Z.x * inv64, Bv = Z.y * inv64;
            float ar = Av * gr, ai = Av * gi;
            float ma = sqrtf(ar * ar + ai * ai);
            float sa = fmaxf(ma + bias, 0.f) / fmaxf(ma, 1e-12f);
            float Aout = ar * sa * inv64;
            float br2 = Bv * gr, bi2 = Bv * gi;
            float mb = sqrtf(br2 * br2 + bi2 * bi2);
            float sb = fmaxf(mb + bias, 0.f) / fmaxf(mb, 1e-12f);
            float Bout = br2 * sb * inv64;
            dat[SKI(p1)] = make_float2(Aout, Bout);
        } else {
            int p2 = rev8(NFFT - k);
            float2 Z1 = dat[SKI(p1)], Z2 = dat[SKI(p2)];
            float Ar = 0.5f * (Z1.x + Z2.x) * inv64;
            float Ai = 0.5f * (Z1.y - Z2.y) * inv64;
            float Br = 0.5f * (Z1.y + Z2.y) * inv64;
            float Bi = 0.5f * (Z2.x - Z1.x) * inv64;
            float zar = Ar * gr - Ai * gi, zai = Ar * gi + Ai * gr;
            float ma = sqrtf(zar * zar + zai * zai);
            float sa = fmaxf(ma + bias, 0.f) / fmaxf(ma, 1e-12f) * inv64;
            zar *= sa; zai *= sa;
            float zbr = Br * gr - Bi * gi, zbi = Br * gi + Bi * gr;
            float mb = sqrtf(zbr * zbr + zbi * zbi);
            float sb = fmaxf(mb + bias, 0.f) / fmaxf(mb, 1e-12f) * inv64;
            zbr *= sb; zbi *= sb;
            dat[SKI(p1)] = make_float2(zar - zbi, zai + zbr);
            dat[SKI(p2)] = make_float2(zar + zbi, zbr - zai);
        }
    }
    __syncthreads();

    // ---- inverse radix-8 DIT (digit8-reversed -> natural), 4 stages ----
    #pragma unroll
    for (int t = 3; t >= 0; t--) {
        const int lq = 9 - 3 * t;
        const int Q = 1 << lq;
        const int step = 1 << (3 * t);
        const int q = tid;
        const int j = q & (Q - 1);
        const int i0 = ((q >> lq) << (lq + 3)) | j;
        const int js = j * step;
        float2 u0 = dat[SKI(i0)];
        float2 u1 = cmulc(dat[SKI(i0 + Q)],     tw[js]);
        float2 u2 = cmulc(dat[SKI(i0 + 2 * Q)], tw[2 * js]);
        float2 u3 = cmulc(dat[SKI(i0 + 3 * Q)], tw[3 * js]);
        float2 u4 = cmulc(dat[SKI(i0 + 4 * Q)], tw[4 * js]);
        float2 u5 = cmulc(dat[SKI(i0 + 5 * Q)], tw[5 * js]);
        float2 u6 = cmulc(dat[SKI(i0 + 6 * Q)], tw[6 * js]);
        float2 u7 = cmulc(dat[SKI(i0 + 7 * Q)], tw[7 * js]);
        // even (u0,u2,u4,u6), omega4 = +i
        float2 s02 = cadd(u0, u4), d02 = csub(u0, u4);
        float2 s26 = cadd(u2, u6), d26 = csub(u2, u6);
        float2 E0 = cadd(s02, s26), E2 = csub(s02, s26);
        float2 E1 = make_float2(d02.x - d26.y, d02.y + d26.x);
        float2 E3 = make_float2(d02.x + d26.y, d02.y - d26.x);
        // odd (u1,u3,u5,u7)
        float2 s15 = cadd(u1, u5), d15 = csub(u1, u5);
        float2 s37 = cadd(u3, u7), d37 = csub(u3, u7);
        float2 O0 = cadd(s15, s37), O2 = csub(s15, s37);
        float2 O1 = make_float2(d15.x - d37.y, d15.y + d37.x);
        float2 O3 = make_float2(d15.x + d37.y, d15.y - d37.x);
        // rotate odds by omega8^{-r}
        float2 T0 = O0;
        float2 T1 = make_float2(RC8 * (O1.x - O1.y), RC8 * (O1.x + O1.y));    // *c(1+i)
        float2 T2 = make_float2(-O2.y, O2.x);                                  // *(+i)
        float2 T3 = make_float2(-RC8 * (O3.x + O3.y), RC8 * (O3.x - O3.y));   // *(-c(1-i))
        dat[SKI(i0)]         = cadd(E0, T0);
        dat[SKI(i0 + 4 * Q)] = csub(E0, T0);
        dat[SKI(i0 + Q)]     = cadd(E1, T1);
        dat[SKI(i0 + 5 * Q)] = csub(E1, T1);
        dat[SKI(i0 + 2 * Q)] = cadd(E2, T2);
        dat[SKI(i0 + 6 * Q)] = csub(E2, T2);
        dat[SKI(i0 + 3 * Q)] = cadd(E3, T3);
        dat[SKI(i0 + 7 * Q)] = csub(E3, T3);
        __syncthreads();
    }

    // emit attn already split into hi/lo bf16 planes (O-GEMM A operand)
    size_t ra = ((size_t)((b * H_ + h) * DH_ + 2 * p)) * S_;
    size_t rb = ra + S_;
    for (int ii = tid; ii < 2048; ii += 512) {
        int i0 = ii * 2;
        float2 z0 = dat[SKI(i0)], z1 = dat[SKI(i0 + 1)];
        uint32_t hw, lw;
        split2(z0.x, z1.x, hw, lw);
        *(uint32_t*)(g_Ath + ra + i0) = hw;
        *(uint32_t*)(g_Atl + ra + i0) = lw;
        split2(z0.y, z1.y, hw, lw);
        *(uint32_t*)(g_Ath + rb + i0) = hw;
        *(uint32_t*)(g_Atl + rb + i0) = lw;
    }
}

// ---------------- launch ----------------
extern "C" void kernel_launch(void* const* d_in, const int* in_sizes, int n_in,
                              void* d_out, int out_size) {
    const float* x     = (const float*)d_in[0];
    const float* Wq    = (const float*)d_in[1];
    const float* Wv    = (const float*)d_in[2];
    const float* Wo    = (const float*)d_in[3];
    const float* gamma = (const float*)d_in[4];
    const float* beta  = (const float*)d_in[5];
    const float* w1    = (const float*)d_in[6];
    const float* b1    = (const float*)d_in[7];
    const float* w2    = (const float*)d_in[8];
    const float* b2    = (const float*)d_in[9];
    const float* mbias = (const float*)d_in[10];
    float* out = (float*)d_out;

    float *vt = nullptr;
    __nv_bfloat16 *xh, *xl, *wvh, *wvl, *woh, *wol, *ath, *atl;
    cudaGetSymbolAddress((void**)&vt,  g_Vt);
    cudaGetSymbolAddress((void**)&xh,  g_xh);
    cudaGetSymbolAddress((void**)&xl,  g_xl);
    cudaGetSymbolAddress((void**)&wvh, g_Wvh);
    cudaGetSymbolAddress((void**)&wvl, g_Wvl);
    cudaGetSymbolAddress((void**)&woh, g_Woh);
    cudaGetSymbolAddress((void**)&wol, g_Wol);
    cudaGetSymbolAddress((void**)&ath, g_Ath);
    cudaGetSymbolAddress((void**)&atl, g_Atl);

    // smem bytes:
    // V-GEMM: 2 stages * (2*256*72 + 2*128*72)*2 = 221184 ; Ct epi 135168 aliases
    // O-GEMM: 2 stages * (2*64*264 + 2*128*72)*2 = 208896
    // FFT: (4352 + 4096)*8 = 67584
    const int smem_v   = 221184;
    const int smem_o   = 208896;
    const int smem_fft = (4352 + 4096) * 8;

    cudaFuncSetAttribute(k_gemm<false, true>,  cudaFuncAttributeMaxDynamicSharedMemorySize, smem_v);
    cudaFuncSetAttribute(k_gemm<true,  false>, cudaFuncAttributeMaxDynamicSharedMemorySize, smem_o);
    cudaFuncSetAttribute(k_fft,                cudaFuncAttributeMaxDynamicSharedMemorySize, smem_fft);

    // pre-split inputs + twiddles
    k_split<<<16384, 256>>>((const float4*)x, xh, xl);
    k_split<<<1024, 256>>>((const float4*)Wv, wvh, wvl);
    k_split<<<1024, 256>>>((const float4*)Wo, woh, wol);
    k_twiddle<<<16, 256>>>();

    // gate path (tiny)
    k_xpart<<<dim3(8, 32, 4), 128>>>(x);
    k_xsum<<<dim3(8, 4), 128>>>();
    k_meanq<<<dim3(128, 4), 256>>>(Wq);
    k_lnmlp1<<<4, 256>>>(gamma, beta, w1, b1);
    k_mlp2<<<dim3((2 * NF_ + 3) / 4, 4), 128>>>(w2, b2);

    // V projection, transposed output [b][c][s] fp32
    k_gemm<false, true><<<dim3(8, 64), 256, smem_v>>>(xh, xl, wvh, wvl, vt);

    // fused spectral mixer (emits split attn planes)
    k_fft<<<dim3(32, 16, 4), 512, smem_fft>>>(mbias);

    // output projection from split attn planes
    k_gemm<true, false><<<dim3(8, 64), 256, smem_o>>>(ath, atl, woh, wol, out);
}

// round 10
// speedup vs baseline: 2.8651x; 1.0408x over previous
#include <cuda_runtime.h>
#include <cuda_bf16.h>
#include <mma.h>
#include <math.h>
#include <stdint.h>

using namespace nvcuda;

#define B_    4
#define S_    4096
#define D_    1024
#define H_    16
#define DH_   64
#define NF_   2049
#define NFFT  4096
#define LOGN  12

// ---------------- scratch (device globals; no allocations allowed) ----------------
__device__ float  g_Vt[(size_t)B_ * D_ * S_];        // V transposed: [b][c][s] fp32 (FFT input)
__device__ __nv_bfloat16 g_xh[(size_t)B_ * S_ * D_]; // x split hi (row-major [m][k])
__device__ __nv_bfloat16 g_xl[(size_t)B_ * S_ * D_];
__device__ __nv_bfloat16 g_Wvh[D_ * D_], g_Wvl[D_ * D_];
__device__ __nv_bfloat16 g_Woh[D_ * D_], g_Wol[D_ * D_];
__device__ __nv_bfloat16 g_Ath[(size_t)B_ * D_ * S_]; // attn split hi: [b][c][s]
__device__ __nv_bfloat16 g_Atl[(size_t)B_ * D_ * S_];
__device__ float2 g_tw[NFFT];                        // full table e^{-2*pi*i*k/N}
__device__ float  g_xpart[B_ * 32 * D_];
__device__ float  g_xsum[B_ * D_];
__device__ float  g_meanq[B_ * D_];
__device__ float  g_hdn[B_ * D_];
__device__ float  g_gri[B_ * 2 * NF_];

// ---------------- small helpers ----------------
__device__ __forceinline__ uint32_t smem_u32(const void* p) {
    uint32_t a;
    asm("{ .reg .u64 t; cvta.to.shared.u64 t, %1; cvt.u32.u64 %0, t; }" : "=r"(a) : "l"(p));
    return a;
}
__device__ __forceinline__ void cpa16(uint32_t dst, const void* src) {
    asm volatile("cp.async.cg.shared.global [%0], [%1], 16;" :: "r"(dst), "l"(src));
}
#define CP_COMMIT() asm volatile("cp.async.commit_group;" ::: "memory")
#define CP_WAIT1()  asm volatile("cp.async.wait_group 1;"  ::: "memory")
#define CP_WAIT0()  asm volatile("cp.async.wait_group 0;"  ::: "memory")

// bf16 hi/lo split helpers
__device__ __forceinline__ void split1(float v, __nv_bfloat16& h, __nv_bfloat16& l) {
    h = __float2bfloat16(v);
    l = __float2bfloat16(v - __bfloat162float(h));
}
__device__ __forceinline__ void split2(float v0, float v1, uint32_t& hi, uint32_t& lo) {
    __nv_bfloat16 h0, l0, h1, l1;
    split1(v0, h0, l0);
    split1(v1, h1, l1);
    hi = ((uint32_t)__bfloat16_as_ushort(h1) << 16) | __bfloat16_as_ushort(h0);
    lo = ((uint32_t)__bfloat16_as_ushort(l1) << 16) | __bfloat16_as_ushort(l0);
}

// ---------------- prep: weight splits + twiddle in one launch ----------------
__global__ void __launch_bounds__(256) k_prep(const float4* __restrict__ Wv,
                                              const float4* __restrict__ Wo) {
    int blk = blockIdx.x;
    if (blk < 1024) {
        int i = blk * 256 + threadIdx.x;
        float4 v = Wv[i];
        uint32_t h01, l01, h23, l23;
        split2(v.x, v.y, h01, l01);
        split2(v.z, v.w, h23, l23);
        ((uint2*)g_Wvh)[i] = make_uint2(h01, h23);
        ((uint2*)g_Wvl)[i] = make_uint2(l01, l23);
    } else if (blk < 2048) {
        int i = (blk - 1024) * 256 + threadIdx.x;
        float4 v = Wo[i];
        uint32_t h01, l01, h23, l23;
        split2(v.x, v.y, h01, l01);
        split2(v.z, v.w, h23, l23);
        ((uint2*)g_Woh)[i] = make_uint2(h01, h23);
        ((uint2*)g_Wol)[i] = make_uint2(l01, l23);
    } else {
        int i = (blk - 2048) * 256 + threadIdx.x;
        if (i < NFFT) {
            double ang = -6.283185307179586476925286766559 * (double)i / (double)NFFT;
            g_tw[i] = make_float2((float)cos(ang), (float)sin(ang));
        }
    }
}

// ---------------- fused x split + partial sums ----------------
// grid (8 dblk, 32 chunk, 4 b), 128 threads: splits x into bf16 planes and
// accumulates per-chunk column sums in one pass over x.
__global__ void __launch_bounds__(128) k_xpart(const float* __restrict__ x) {
    int d = blockIdx.x * 128 + threadIdx.x;
    int chunk = blockIdx.y;
    int b = blockIdx.z;
    size_t base = ((size_t)b * S_ + (size_t)chunk * 128) * D_ + d;
    const float* p = x + base;
    __nv_bfloat16* ph = g_xh + base;
    __nv_bfloat16* pl = g_xl + base;
    float acc = 0.f;
    #pragma unroll 4
    for (int s = 0; s < 128; s++) {
        float v = p[(size_t)s * D_];
        acc += v;
        __nv_bfloat16 h, l;
        split1(v, h, l);
        ph[(size_t)s * D_] = h;
        pl[(size_t)s * D_] = l;
    }
    g_xpart[(b * 32 + chunk) * D_ + d] = acc;
}

__global__ void __launch_bounds__(128) k_xsum() {
    int d = blockIdx.x * 128 + threadIdx.x;
    int b = blockIdx.y;
    float acc = 0.f;
    #pragma unroll
    for (int q = 0; q < 32; q++) acc += g_xpart[(b * 32 + q) * D_ + d];
    g_xsum[b * D_ + d] = acc;
}

__global__ void __launch_bounds__(256) k_meanq(const float* __restrict__ Wq) {
    int warp = threadIdx.x >> 5, lane = threadIdx.x & 31;
    int c = blockIdx.x * 8 + warp;
    int b = blockIdx.y;
    const float* w  = Wq + (size_t)c * D_;
    const float* xm = g_xsum + b * D_;
    float acc = 0.f;
    #pragma unroll 8
    for (int i = lane; i < D_; i += 32) acc += xm[i] * w[i];
    #pragma unroll
    for (int o = 16; o; o >>= 1) acc += __shfl_xor_sync(0xffffffffu, acc, o);
    if (lane == 0) g_meanq[b * D_ + c] = acc * (1.0f / S_);
}

__global__ void __launch_bounds__(256) k_lnmlp1(const float* __restrict__ gamma,
                                                const float* __restrict__ beta,
                                                const float* __restrict__ w1,
                                                const float* __restrict__ b1) {
    __shared__ float sv[16][64];
    __shared__ float sq[64];
    __shared__ float smean[16], srstd[16];
    int b = blockIdx.x;
    int t = threadIdx.x;

    #pragma unroll
    for (int r = 0; r < 4; r++) {
        int c = t + r * 256;
        sv[c >> 6][c & 63] = g_meanq[b * D_ + c];
    }
    __syncthreads();
    if (t < 16) {
        float m = 0.f;
        for (int q = 0; q < 64; q++) m += sv[t][q];
        m *= (1.f / 64.f);
        float var = 0.f;
        for (int q = 0; q < 64; q++) { float dd = sv[t][q] - m; var += dd * dd; }
        var *= (1.f / 64.f);
        smean[t] = m;
        srstd[t] = rsqrtf(var + 1e-5f);
    }
    __syncthreads();
    #pragma unroll
    for (int r = 0; r < 4; r++) {
        int c = t + r * 256;
        int h = c >> 6, j = c & 63;
        sv[h][j] = (sv[h][j] - smean[h]) * srstd[h] * gamma[j] + beta[j];
    }
    __syncthreads();
    if (t < 64) {
        float m = 0.f;
        for (int q = 0; q < 16; q++) m += sv[q][t];
        sq[t] = m * (1.f / 16.f);
    }
    __syncthreads();
    #pragma unroll
    for (int r = 0; r < 4; r++) {
        int c = t + r * 256;
        float acc = b1[c];
        const float* wr = w1 + (size_t)c * 64;
        #pragma unroll 8
        for (int q = 0; q < 64; q++) acc += sq[q] * wr[q];
        g_hdn[b * D_ + c] = 0.5f * acc * (1.f + erff(acc * 0.70710678118654752f));
    }
}

__global__ void __launch_bounds__(128) k_mlp2(const float* __restrict__ w2,
                                              const float* __restrict__ b2) {
    int warp = threadIdx.x >> 5, lane = threadIdx.x & 31;
    int r = blockIdx.x * 4 + warp;
    int b = blockIdx.y;
    if (r >= 2 * NF_) return;
    const float* hd = g_hdn + b * D_;
    const float* w  = w2 + (size_t)r * D_;
    float acc = 0.f;
    for (int i = lane; i < D_; i += 32) acc += hd[i] * w[i];
    #pragma unroll
    for (int o = 16; o; o >>= 1) acc += __shfl_xor_sync(0xffffffffu, acc, o);
    if (lane == 0) g_gri[b * 2 * NF_ + r] = acc + b2[r];
}

// =================================================================
// bf16-split WMMA GEMM (unchanged from R9): K=64 stages, cp.async 2-buffer.
// =================================================================
template <bool ACOL, bool TSTORE>
__global__ void __launch_bounds__(256, 1) k_gemm(const __nv_bfloat16* __restrict__ Ah,
                                                 const __nv_bfloat16* __restrict__ Al,
                                                 const __nv_bfloat16* __restrict__ Wh,
                                                 const __nv_bfloat16* __restrict__ Wl,
                                                 float* __restrict__ C) {
    extern __shared__ __align__(16) char smraw[];
    __nv_bfloat16* sb = (__nv_bfloat16*)smraw;
    float* smf = (float*)smraw;
    const uint32_t sb_u32 = smem_u32(sb);

    constexpr int ASZ = ACOL ? 64 * 264 : 256 * 72;
    constexpr int WSZ = 128 * 72;
    constexpr int BUF = 2 * ASZ + 2 * WSZ;

    const int tid = threadIdx.x;
    const int warp = tid >> 5;
    const int wm = warp & 3;
    const int wn = warp >> 2;
    const int n0 = blockIdx.x * 128;
    const int m0 = blockIdx.y * 256;
    const int bb = m0 >> 12, s0 = m0 & 4095;

    auto ISSUE = [&](int kt, int jb) {
        uint32_t base = sb_u32 + (uint32_t)jb * BUF * 2;
        if constexpr (ACOL) {
            #pragma unroll
            for (int t = 0; t < 8; t++) {
                int idx = tid + t * 256;
                int row = idx >> 5, ch = (idx & 31) * 8;
                size_t g = ((size_t)(bb * D_ + kt * 64 + row)) * S_ + s0 + ch;
                cpa16(base + (uint32_t)(row * 264 + ch) * 2, Ah + g);
                cpa16(base + (uint32_t)(ASZ + row * 264 + ch) * 2, Al + g);
            }
        } else {
            #pragma unroll
            for (int t = 0; t < 8; t++) {
                int idx = tid + t * 256;
                int row = idx >> 3, ch = (idx & 7) * 8;
                size_t g = (size_t)(m0 + row) * D_ + kt * 64 + ch;
                cpa16(base + (uint32_t)(row * 72 + ch) * 2, Ah + g);
                cpa16(base + (uint32_t)(ASZ + row * 72 + ch) * 2, Al + g);
            }
        }
        #pragma unroll
        for (int t = 0; t < 4; t++) {
            int idx = tid + t * 256;
            int row = idx >> 3, ch = (idx & 7) * 8;
            size_t g = (size_t)(n0 + row) * D_ + kt * 64 + ch;
            cpa16(base + (uint32_t)(2 * ASZ + row * 72 + ch) * 2, Wh + g);
            cpa16(base + (uint32_t)(2 * ASZ + WSZ + row * 72 + ch) * 2, Wl + g);
        }
        CP_COMMIT();
    };

    wmma::fragment<wmma::accumulator, 16, 16, 16, float> acc[4][4];
    #pragma unroll
    for (int i = 0; i < 4; i++)
        #pragma unroll
        for (int j = 0; j < 4; j++) wmma::fill_fragment(acc[i][j], 0.0f);

    ISSUE(0, 0);

    for (int it = 0; it < 16; it++) {
        const bool pf = (it + 1 < 16);
        if (pf) { ISSUE(it + 1, (it + 1) & 1); CP_WAIT1(); }
        else    { CP_WAIT0(); }
        __syncthreads();

        const __nv_bfloat16* base = sb + (it & 1) * BUF;
        const __nv_bfloat16* Ahs = base;
        const __nv_bfloat16* Als = base + ASZ;
        const __nv_bfloat16* Whs = base + 2 * ASZ;
        const __nv_bfloat16* Wls = Whs + WSZ;

        #pragma unroll
        for (int kk = 0; kk < 64; kk += 16) {
            wmma::fragment<wmma::matrix_b, 16, 16, 16, __nv_bfloat16, wmma::col_major> bH[4], bL[4];
            #pragma unroll
            for (int j = 0; j < 4; j++) {
                wmma::load_matrix_sync(bH[j], Whs + (wn * 64 + j * 16) * 72 + kk, 72);
                wmma::load_matrix_sync(bL[j], Wls + (wn * 64 + j * 16) * 72 + kk, 72);
            }
            #pragma unroll
            for (int i = 0; i < 4; i++) {
                if constexpr (ACOL) {
                    wmma::fragment<wmma::matrix_a, 16, 16, 16, __nv_bfloat16, wmma::col_major> aH, aL;
                    wmma::load_matrix_sync(aH, Ahs + kk * 264 + wm * 64 + i * 16, 264);
                    wmma::load_matrix_sync(aL, Als + kk * 264 + wm * 64 + i * 16, 264);
                    #pragma unroll
                    for (int j = 0; j < 4; j++) {
                        wmma::mma_sync(acc[i][j], aH, bH[j], acc[i][j]);
                        wmma::mma_sync(acc[i][j], aL, bH[j], acc[i][j]);
                        wmma::mma_sync(acc[i][j], aH, bL[j], acc[i][j]);
                    }
                } else {
                    wmma::fragment<wmma::matrix_a, 16, 16, 16, __nv_bfloat16, wmma::row_major> aH, aL;
                    wmma::load_matrix_sync(aH, Ahs + (wm * 64 + i * 16) * 72 + kk, 72);
                    wmma::load_matrix_sync(aL, Als + (wm * 64 + i * 16) * 72 + kk, 72);
                    #pragma unroll
                    for (int j = 0; j < 4; j++) {
                        wmma::mma_sync(acc[i][j], aH, bH[j], acc[i][j]);
                        wmma::mma_sync(acc[i][j], aL, bH[j], acc[i][j]);
                        wmma::mma_sync(acc[i][j], aH, bL[j], acc[i][j]);
                    }
                }
            }
        }
        __syncthreads();
    }

    if constexpr (TSTORE) {
        float* Ct = smf;
        #pragma unroll
        for (int i = 0; i < 4; i++)
            #pragma unroll
            for (int j = 0; j < 4; j++)
                wmma::store_matrix_sync(Ct + (wn * 64 + j * 16) * 264 + wm * 64 + i * 16,
                                        acc[i][j], 264, wmma::mem_col_major);
        __syncthreads();
        #pragma unroll
        for (int t = 0; t < 32; t++) {
            int idx = tid + t * 256;
            int n = idx >> 6, mm = (idx & 63) * 4;
            float4 v = *(float4*)(Ct + n * 264 + mm);
            *(float4*)(C + ((size_t)(bb * D_ + n0 + n)) * S_ + s0 + mm) = v;
        }
    } else {
        #pragma unroll
        for (int i = 0; i < 4; i++)
            #pragma unroll
            for (int j = 0; j < 4; j++)
                wmma::store_matrix_sync(C + (size_t)(m0 + wm * 64 + i * 16) * D_ + n0 + wn * 64 + j * 16,
                                        acc[i][j], D_, wmma::mem_row_major);
    }
}

// ---------------- fused radix-8 FFT -> gate*modReLU -> iFFT ----------------
// First forward stage fused with global load; last inverse stage fused with
// global store + bf16 split. 6 smem butterfly round-trips instead of 8.
__device__ __forceinline__ int SKI(int i) { return i + (i >> 4); }
__device__ __forceinline__ float2 cmul(float2 a, float2 b) {
    return make_float2(a.x * b.x - a.y * b.y, a.x * b.y + a.y * b.x);
}
__device__ __forceinline__ float2 cmulc(float2 a, float2 b) {
    return make_float2(a.x * b.x + a.y * b.y, a.y * b.x - a.x * b.y);
}
__device__ __forceinline__ float2 cadd(float2 a, float2 b) { return make_float2(a.x + b.x, a.y + b.y); }
__device__ __forceinline__ float2 csub(float2 a, float2 b) { return make_float2(a.x - b.x, a.y - b.y); }
#define RC8 0.70710678118654752440f

__device__ __forceinline__ int rev8(int k) {
    return ((k & 7) << 9) | (((k >> 3) & 7) << 6) | (((k >> 6) & 7) << 3) | ((k >> 9) & 7);
}

// forward radix-8 butterfly core: inputs x0..x7, outputs X0..X7 (DIF, e^-)
#define FWD8(x0,x1,x2,x3,x4,x5,x6,x7, X0,X1,X2,X3,X4,X5,X6,X7) do { \
    float2 s02 = cadd(x0, x4), d02 = csub(x0, x4); \
    float2 s26 = cadd(x2, x6), d26 = csub(x2, x6); \
    float2 E0 = cadd(s02, s26), E2 = csub(s02, s26); \
    float2 E1 = make_float2(d02.x + d26.y, d02.y - d26.x); \
    float2 E3 = make_float2(d02.x - d26.y, d02.y + d26.x); \
    float2 s15 = cadd(x1, x5), d15 = csub(x1, x5); \
    float2 s37 = cadd(x3, x7), d37 = csub(x3, x7); \
    float2 O0 = cadd(s15, s37), O2 = csub(s15, s37); \
    float2 O1 = make_float2(d15.x + d37.y, d15.y - d37.x); \
    float2 O3 = make_float2(d15.x - d37.y, d15.y + d37.x); \
    float2 T0 = O0; \
    float2 T1 = make_float2(RC8 * (O1.x + O1.y), RC8 * (O1.y - O1.x)); \
    float2 T2 = make_float2(O2.y, -O2.x); \
    float2 T3 = make_float2(RC8 * (O3.y - O3.x), -RC8 * (O3.x + O3.y)); \
    X0 = cadd(E0, T0); X4 = csub(E0, T0); \
    X1 = cadd(E1, T1); X5 = csub(E1, T1); \
    X2 = cadd(E2, T2); X6 = csub(E2, T2); \
    X3 = cadd(E3, T3); X7 = csub(E3, T3); \
} while (0)

// inverse radix-8 butterfly core (DIT, e^+), inputs u0..u7 (already de-twiddled)
#define INV8(u0,u1,u2,u3,u4,u5,u6,u7, Y0,Y1,Y2,Y3,Y4,Y5,Y6,Y7) do { \
    float2 s02 = cadd(u0, u4), d02 = csub(u0, u4); \
    float2 s26 = cadd(u2, u6), d26 = csub(u2, u6); \
    float2 E0 = cadd(s02, s26), E2 = csub(s02, s26); \
    float2 E1 = make_float2(d02.x - d26.y, d02.y + d26.x); \
    float2 E3 = make_float2(d02.x + d26.y, d02.y - d26.x); \
    float2 s15 = cadd(u1, u5), d15 = csub(u1, u5); \
    float2 s37 = cadd(u3, u7), d37 = csub(u3, u7); \
    float2 O0 = cadd(s15, s37), O2 = csub(s15, s37); \
    float2 O1 = make_float2(d15.x - d37.y, d15.y + d37.x); \
    float2 O3 = make_float2(d15.x + d37.y, d15.y - d37.x); \
    float2 T0 = O0; \
    float2 T1 = make_float2(RC8 * (O1.x - O1.y), RC8 * (O1.x + O1.y)); \
    float2 T2 = make_float2(-O2.y, O2.x); \
    float2 T3 = make_float2(-RC8 * (O3.x + O3.y), RC8 * (O3.x - O3.y)); \
    Y0 = cadd(E0, T0); Y4 = csub(E0, T0); \
    Y1 = cadd(E1, T1); Y5 = csub(E1, T1); \
    Y2 = cadd(E2, T2); Y6 = csub(E2, T2); \
    Y3 = cadd(E3, T3); Y7 = csub(E3, T3); \
} while (0)

__global__ void __launch_bounds__(512) k_fft(const float* __restrict__ mbias) {
    extern __shared__ float2 sd[];
    float2* dat = sd;              // skewed, 4096 + 256 slots
    float2* tw  = sd + 4352;       // 4096 full table

    const int tid = threadIdx.x;
    const int p = blockIdx.x;
    const int h = blockIdx.y;
    const int b = blockIdx.z;

    const float* va = g_Vt + ((size_t)((b * H_ + h) * DH_ + 2 * p)) * S_;
    const float* vb = va + S_;

    // stage tw into smem (used by stages t>=1 and inverse)
    for (int i = tid; i < NFFT; i += 512) tw[i] = g_tw[i];

    // ---- forward stage 0 (Q=512) fused with global load; twiddles from global ----
    {
        float2 x0 = make_float2(va[tid],          vb[tid]);
        float2 x1 = make_float2(va[tid + 512],    vb[tid + 512]);
        float2 x2 = make_float2(va[tid + 1024],   vb[tid + 1024]);
        float2 x3 = make_float2(va[tid + 1536],   vb[tid + 1536]);
        float2 x4 = make_float2(va[tid + 2048],   vb[tid + 2048]);
        float2 x5 = make_float2(va[tid + 2560],   vb[tid + 2560]);
        float2 x6 = make_float2(va[tid + 3072],   vb[tid + 3072]);
        float2 x7 = make_float2(va[tid + 3584],   vb[tid + 3584]);
        float2 X0, X1, X2, X3, X4, X5, X6, X7;
        FWD8(x0,x1,x2,x3,x4,x5,x6,x7, X0,X1,X2,X3,X4,X5,X6,X7);
        dat[SKI(tid)]        = X0;
        dat[SKI(tid + 512)]  = cmul(X1, g_tw[tid]);
        dat[SKI(tid + 1024)] = cmul(X2, g_tw[2 * tid]);
        dat[SKI(tid + 1536)] = cmul(X3, g_tw[3 * tid]);
        dat[SKI(tid + 2048)] = cmul(X4, g_tw[4 * tid]);
        dat[SKI(tid + 2560)] = cmul(X5, g_tw[5 * tid]);
        dat[SKI(tid + 3072)] = cmul(X6, g_tw[6 * tid]);
        dat[SKI(tid + 3584)] = cmul(X7, g_tw[7 * tid]);
    }
    __syncthreads();

    // ---- forward stages t=1..3 ----
    #pragma unroll
    for (int t = 1; t < 4; t++) {
        const int lq = 9 - 3 * t;
        const int Q = 1 << lq;
        const int step = 1 << (3 * t);
        const int j = tid & (Q - 1);
        const int i0 = ((tid >> lq) << (lq + 3)) | j;
        float2 x0 = dat[SKI(i0)];
        float2 x1 = dat[SKI(i0 + Q)];
        float2 x2 = dat[SKI(i0 + 2 * Q)];
        float2 x3 = dat[SKI(i0 + 3 * Q)];
        float2 x4 = dat[SKI(i0 + 4 * Q)];
        float2 x5 = dat[SKI(i0 + 5 * Q)];
        float2 x6 = dat[SKI(i0 + 6 * Q)];
        float2 x7 = dat[SKI(i0 + 7 * Q)];
        float2 X0, X1, X2, X3, X4, X5, X6, X7;
        FWD8(x0,x1,x2,x3,x4,x5,x6,x7, X0,X1,X2,X3,X4,X5,X6,X7);
        const int js = j * step;
        dat[SKI(i0)]         = X0;
        dat[SKI(i0 + Q)]     = cmul(X1, tw[js]);
        dat[SKI(i0 + 2 * Q)] = cmul(X2, tw[2 * js]);
        dat[SKI(i0 + 3 * Q)] = cmul(X3, tw[3 * js]);
        dat[SKI(i0 + 4 * Q)] = cmul(X4, tw[4 * js]);
        dat[SKI(i0 + 5 * Q)] = cmul(X5, tw[5 * js]);
        dat[SKI(i0 + 6 * Q)] = cmul(X6, tw[6 * js]);
        dat[SKI(i0 + 7 * Q)] = cmul(X7, tw[7 * js]);
        __syncthreads();
    }

    // ---- spectral: Hermitian separation, ortho scale, gate, modReLU ----
    const float bias = mbias[0];
    const float inv64 = 1.0f / 64.0f;
    const float* grb = g_gri + b * 2 * NF_;
    for (int k = tid; k <= NFFT / 2; k += 512) {
        float gr = grb[k];
        float gi = grb[NF_ + k];
        int p1 = rev8(k);
        if (k == 0 || k == NFFT / 2) {
            float2 Z = dat[SKI(p1)];
            float Av = Z.x * inv64, Bv = Z.y * inv64;
            float ar = Av * gr, ai = Av * gi;
            float ma = sqrtf(ar * ar + ai * ai);
            float sa = fmaxf(ma + bias, 0.f) / fmaxf(ma, 1e-12f);
            float Aout = ar * sa * inv64;
            float br2 = Bv * gr, bi2 = Bv * gi;
            float mb = sqrtf(br2 * br2 + bi2 * bi2);
            float sb = fmaxf(mb + bias, 0.f) / fmaxf(mb, 1e-12f);
            float Bout = br2 * sb * inv64;
            dat[SKI(p1)] = make_float2(Aout, Bout);
        } else {
            int p2 = rev8(NFFT - k);
            float2 Z1 = dat[SKI(p1)], Z2 = dat[SKI(p2)];
            float Ar = 0.5f * (Z1.x + Z2.x) * inv64;
            float Ai = 0.5f * (Z1.y - Z2.y) * inv64;
            float Br = 0.5f * (Z1.y + Z2.y) * inv64;
            float Bi = 0.5f * (Z2.x - Z1.x) * inv64;
            float zar = Ar * gr - Ai * gi, zai = Ar * gi + Ai * gr;
            float ma = sqrtf(zar * zar + zai * zai);
            float sa = fmaxf(ma + bias, 0.f) / fmaxf(ma, 1e-12f) * inv64;
            zar *= sa; zai *= sa;
            float zbr = Br * gr - Bi * gi, zbi = Br * gi + Bi * gr;
            float mb = sqrtf(zbr * zbr + zbi * zbi);
            float sb = fmaxf(mb + bias, 0.f) / fmaxf(mb, 1e-12f) * inv64;
            zbr *= sb; zbi *= sb;
            dat[SKI(p1)] = make_float2(zar - zbi, zai + zbr);
            dat[SKI(p2)] = make_float2(zar + zbi, zbr - zai);
        }
    }
    __syncthreads();

    // ---- inverse stages t=3..1 ----
    #pragma unroll
    for (int t = 3; t >= 1; t--) {
        const int lq = 9 - 3 * t;
        const int Q = 1 << lq;
        const int step = 1 << (3 * t);
        const int j = tid & (Q - 1);
        const int i0 = ((tid >> lq) << (lq + 3)) | j;
        const int js = j * step;
        float2 u0 = dat[SKI(i0)];
        float2 u1 = cmulc(dat[SKI(i0 + Q)],     tw[js]);
        float2 u2 = cmulc(dat[SKI(i0 + 2 * Q)], tw[2 * js]);
        float2 u3 = cmulc(dat[SKI(i0 + 3 * Q)], tw[3 * js]);
        float2 u4 = cmulc(dat[SKI(i0 + 4 * Q)], tw[4 * js]);
        float2 u5 = cmulc(dat[SKI(i0 + 5 * Q)], tw[5 * js]);
        float2 u6 = cmulc(dat[SKI(i0 + 6 * Q)], tw[6 * js]);
        float2 u7 = cmulc(dat[SKI(i0 + 7 * Q)], tw[7 * js]);
        float2 Y0, Y1, Y2, Y3, Y4, Y5, Y6, Y7;
        INV8(u0,u1,u2,u3,u4,u5,u6,u7, Y0,Y1,Y2,Y3,Y4,Y5,Y6,Y7);
        dat[SKI(i0)]         = Y0;
        dat[SKI(i0 + Q)]     = Y1;
        dat[SKI(i0 + 2 * Q)] = Y2;
        dat[SKI(i0 + 3 * Q)] = Y3;
        dat[SKI(i0 + 4 * Q)] = Y4;
        dat[SKI(i0 + 5 * Q)] = Y5;
        dat[SKI(i0 + 6 * Q)] = Y6;
        dat[SKI(i0 + 7 * Q)] = Y7;
        __syncthreads();
    }

    // ---- inverse stage 0 (Q=512) fused with split + global store ----
    {
        float2 u0 = dat[SKI(tid)];
        float2 u1 = cmulc(dat[SKI(tid + 512)],  tw[tid]);
        float2 u2 = cmulc(dat[SKI(tid + 1024)], tw[2 * tid]);
        float2 u3 = cmulc(dat[SKI(tid + 1536)], tw[3 * tid]);
        float2 u4 = cmulc(dat[SKI(tid + 2048)], tw[4 * tid]);
        float2 u5 = cmulc(dat[SKI(tid + 2560)], tw[5 * tid]);
        float2 u6 = cmulc(dat[SKI(tid + 3072)], tw[6 * tid]);
        float2 u7 = cmulc(dat[SKI(tid + 3584)], tw[7 * tid]);
        float2 Y[8];
        INV8(u0,u1,u2,u3,u4,u5,u6,u7, Y[0],Y[1],Y[2],Y[3],Y[4],Y[5],Y[6],Y[7]);
        size_t ra = ((size_t)((b * H_ + h) * DH_ + 2 * p)) * S_;
        size_t rb = ra + S_;
        #pragma unroll
        for (int r = 0; r < 8; r++) {
            size_t s = (size_t)tid + r * 512;
            __nv_bfloat16 hv, lv;
            split1(Y[r].x, hv, lv);
            g_Ath[ra + s] = hv;
            g_Atl[ra + s] = lv;
            split1(Y[r].y, hv, lv);
            g_Ath[rb + s] = hv;
            g_Atl[rb + s] = lv;
        }
    }
}

// ---------------- launch ----------------
extern "C" void kernel_launch(void* const* d_in, const int* in_sizes, int n_in,
                              void* d_out, int out_size) {
    const float* x     = (const float*)d_in[0];
    const float* Wq    = (const float*)d_in[1];
    const float* Wv    = (const float*)d_in[2];
    const float* Wo    = (const float*)d_in[3];
    const float* gamma = (const float*)d_in[4];
    const float* beta  = (const float*)d_in[5];
    const float* w1    = (const float*)d_in[6];
    const float* b1    = (const float*)d_in[7];
    const float* w2    = (const float*)d_in[8];
    const float* b2    = (const float*)d_in[9];
    const float* mbias = (const float*)d_in[10];
    float* out = (float*)d_out;

    float *vt = nullptr;
    __nv_bfloat16 *xh, *xl, *wvh, *wvl, *woh, *wol, *ath, *atl;
    cudaGetSymbolAddress((void**)&vt,  g_Vt);
    cudaGetSymbolAddress((void**)&xh,  g_xh);
    cudaGetSymbolAddress((void**)&xl,  g_xl);
    cudaGetSymbolAddress((void**)&wvh, g_Wvh);
    cudaGetSymbolAddress((void**)&wvl, g_Wvl);
    cudaGetSymbolAddress((void**)&woh, g_Woh);
    cudaGetSymbolAddress((void**)&wol, g_Wol);
    cudaGetSymbolAddress((void**)&ath, g_Ath);
    cudaGetSymbolAddress((void**)&atl, g_Atl);

    const int smem_v   = 221184;
    const int smem_o   = 208896;
    const int smem_fft = (4352 + 4096) * 8;

    cudaFuncSetAttribute(k_gemm<false, true>,  cudaFuncAttributeMaxDynamicSharedMemorySize, smem_v);
    cudaFuncSetAttribute(k_gemm<true,  false>, cudaFuncAttributeMaxDynamicSharedMemorySize, smem_o);
    cudaFuncSetAttribute(k_fft,                cudaFuncAttributeMaxDynamicSharedMemorySize, smem_fft);

    // prep (weight splits + twiddle), fused x split + partial sums
    k_prep<<<2064, 256>>>((const float4*)Wv, (const float4*)Wo);
    k_xpart<<<dim3(8, 32, 4), 128>>>(x);

    // gate path (tiny)
    k_xsum<<<dim3(8, 4), 128>>>();
    k_meanq<<<dim3(128, 4), 256>>>(Wq);
    k_lnmlp1<<<4, 256>>>(gamma, beta, w1, b1);
    k_mlp2<<<dim3((2 * NF_ + 3) / 4, 4), 128>>>(w2, b2);

    // V projection, transposed output [b][c][s] fp32
    k_gemm<false, true><<<dim3(8, 64), 256, smem_v>>>(xh, xl, wvh, wvl, vt);

    // fused spectral mixer (emits split attn planes)
    k_fft<<<dim3(32, 16, 4), 512, smem_fft>>>(mbias);

    // output projection from split attn planes
    k_gemm<true, false><<<dim3(8, 64), 256, smem_o>>>(ath, atl, woh, wol, out);
}

// round 11
// speedup vs baseline: 3.7983x; 1.3257x over previous
#include <cuda_runtime.h>
#include <cuda_fp16.h>
#include <mma.h>
#include <math.h>
#include <stdint.h>

using namespace nvcuda;

#define B_    4
#define S_    4096
#define D_    1024
#define H_    16
#define DH_   64
#define NF_   2049
#define NFFT  4096
#define LOGN  12

// ---------------- scratch (device globals; no allocations allowed) ----------------
__device__ float  g_Vt[(size_t)B_ * D_ * S_];      // V transposed: [b][c][s] fp32 (FFT input)
__device__ __half g_xh[(size_t)B_ * S_ * D_];      // x split hi (row-major [m][k]) fp16
__device__ __half g_xl[(size_t)B_ * S_ * D_];      // x split lo
__device__ __half g_Wvh[D_ * D_];                  // Wv rounded to fp16 (single plane)
__device__ __half g_Woh[D_ * D_];                  // Wo rounded to fp16
__device__ __half g_Ath[(size_t)B_ * D_ * S_];     // attn split hi: [b][c][s]
__device__ __half g_Atl[(size_t)B_ * D_ * S_];
__device__ float2 g_tw[NFFT];                      // full table e^{-2*pi*i*k/N}
__device__ float  g_xpart[B_ * 32 * D_];
__device__ float  g_xsum[B_ * D_];
__device__ float  g_meanq[B_ * D_];
__device__ float  g_hdn[B_ * D_];
__device__ float  g_gri[B_ * 2 * NF_];

// ---------------- small helpers ----------------
__device__ __forceinline__ uint32_t smem_u32(const void* p) {
    uint32_t a;
    asm("{ .reg .u64 t; cvta.to.shared.u64 t, %1; cvt.u32.u64 %0, t; }" : "=r"(a) : "l"(p));
    return a;
}
__device__ __forceinline__ void cpa16(uint32_t dst, const void* src) {
    asm volatile("cp.async.cg.shared.global [%0], [%1], 16;" :: "r"(dst), "l"(src));
}
#define CP_COMMIT() asm volatile("cp.async.commit_group;" ::: "memory")
#define CP_WAIT1()  asm volatile("cp.async.wait_group 1;"  ::: "memory")
#define CP_WAIT0()  asm volatile("cp.async.wait_group 0;"  ::: "memory")

// fp16 hi/lo split
__device__ __forceinline__ void split1h(float v, __half& h, __half& l) {
    h = __float2half_rn(v);
    l = __float2half_rn(v - __half2float(h));
}

// ---------------- prep: weight fp16 rounding + twiddle in one launch ----------------
__global__ void __launch_bounds__(256) k_prep(const float4* __restrict__ Wv,
                                              const float4* __restrict__ Wo) {
    int blk = blockIdx.x;
    if (blk < 1024) {
        int i = blk * 256 + threadIdx.x;
        float4 v = Wv[i];
        ((__half2*)g_Wvh)[2 * i]     = __floats2half2_rn(v.x, v.y);
        ((__half2*)g_Wvh)[2 * i + 1] = __floats2half2_rn(v.z, v.w);
    } else if (blk < 2048) {
        int i = (blk - 1024) * 256 + threadIdx.x;
        float4 v = Wo[i];
        ((__half2*)g_Woh)[2 * i]     = __floats2half2_rn(v.x, v.y);
        ((__half2*)g_Woh)[2 * i + 1] = __floats2half2_rn(v.z, v.w);
    } else {
        int i = (blk - 2048) * 256 + threadIdx.x;
        if (i < NFFT) {
            double ang = -6.283185307179586476925286766559 * (double)i / (double)NFFT;
            g_tw[i] = make_float2((float)cos(ang), (float)sin(ang));
        }
    }
}

// ---------------- fused x split + partial sums ----------------
__global__ void __launch_bounds__(128) k_xpart(const float* __restrict__ x) {
    int d = blockIdx.x * 128 + threadIdx.x;
    int chunk = blockIdx.y;
    int b = blockIdx.z;
    size_t base = ((size_t)b * S_ + (size_t)chunk * 128) * D_ + d;
    const float* p = x + base;
    __half* ph = g_xh + base;
    __half* pl = g_xl + base;
    float acc = 0.f;
    #pragma unroll 4
    for (int s = 0; s < 128; s++) {
        float v = p[(size_t)s * D_];
        acc += v;
        __half h, l;
        split1h(v, h, l);
        ph[(size_t)s * D_] = h;
        pl[(size_t)s * D_] = l;
    }
    g_xpart[(b * 32 + chunk) * D_ + d] = acc;
}

__global__ void __launch_bounds__(128) k_xsum() {
    int d = blockIdx.x * 128 + threadIdx.x;
    int b = blockIdx.y;
    float acc = 0.f;
    #pragma unroll
    for (int q = 0; q < 32; q++) acc += g_xpart[(b * 32 + q) * D_ + d];
    g_xsum[b * D_ + d] = acc;
}

__global__ void __launch_bounds__(256) k_meanq(const float* __restrict__ Wq) {
    int warp = threadIdx.x >> 5, lane = threadIdx.x & 31;
    int c = blockIdx.x * 8 + warp;
    int b = blockIdx.y;
    const float* w  = Wq + (size_t)c * D_;
    const float* xm = g_xsum + b * D_;
    float acc = 0.f;
    #pragma unroll 8
    for (int i = lane; i < D_; i += 32) acc += xm[i] * w[i];
    #pragma unroll
    for (int o = 16; o; o >>= 1) acc += __shfl_xor_sync(0xffffffffu, acc, o);
    if (lane == 0) g_meanq[b * D_ + c] = acc * (1.0f / S_);
}

__global__ void __launch_bounds__(256) k_lnmlp1(const float* __restrict__ gamma,
                                                const float* __restrict__ beta,
                                                const float* __restrict__ w1,
                                                const float* __restrict__ b1) {
    __shared__ float sv[16][64];
    __shared__ float sq[64];
    __shared__ float smean[16], srstd[16];
    int b = blockIdx.x;
    int t = threadIdx.x;

    #pragma unroll
    for (int r = 0; r < 4; r++) {
        int c = t + r * 256;
        sv[c >> 6][c & 63] = g_meanq[b * D_ + c];
    }
    __syncthreads();
    if (t < 16) {
        float m = 0.f;
        for (int q = 0; q < 64; q++) m += sv[t][q];
        m *= (1.f / 64.f);
        float var = 0.f;
        for (int q = 0; q < 64; q++) { float dd = sv[t][q] - m; var += dd * dd; }
        var *= (1.f / 64.f);
        smean[t] = m;
        srstd[t] = rsqrtf(var + 1e-5f);
    }
    __syncthreads();
    #pragma unroll
    for (int r = 0; r < 4; r++) {
        int c = t + r * 256;
        int h = c >> 6, j = c & 63;
        sv[h][j] = (sv[h][j] - smean[h]) * srstd[h] * gamma[j] + beta[j];
    }
    __syncthreads();
    if (t < 64) {
        float m = 0.f;
        for (int q = 0; q < 16; q++) m += sv[q][t];
        sq[t] = m * (1.f / 16.f);
    }
    __syncthreads();
    #pragma unroll
    for (int r = 0; r < 4; r++) {
        int c = t + r * 256;
        float acc = b1[c];
        const float* wr = w1 + (size_t)c * 64;
        #pragma unroll 8
        for (int q = 0; q < 64; q++) acc += sq[q] * wr[q];
        g_hdn[b * D_ + c] = 0.5f * acc * (1.f + erff(acc * 0.70710678118654752f));
    }
}

__global__ void __launch_bounds__(128) k_mlp2(const float* __restrict__ w2,
                                              const float* __restrict__ b2) {
    int warp = threadIdx.x >> 5, lane = threadIdx.x & 31;
    int r = blockIdx.x * 4 + warp;
    int b = blockIdx.y;
    if (r >= 2 * NF_) return;
    const float* hd = g_hdn + b * D_;
    const float* w  = w2 + (size_t)r * D_;
    float acc = 0.f;
    for (int i = lane; i < D_; i += 32) acc += hd[i] * w[i];
    #pragma unroll
    for (int o = 16; o; o >>= 1) acc += __shfl_xor_sync(0xffffffffu, acc, o);
    if (lane == 0) g_gri[b * 2 * NF_ + r] = acc + b2[r];
}

// =================================================================
// fp16 2-product WMMA GEMM: C = A@W^T with A = Ah + Al (fp16 split),
// W rounded to fp16. acc += Ah*W + Al*W. K=64 stages, cp.async 2-buffer.
// ACOL:   A planes are [b][k][s] (FFT output); else row-major [m][k].
// TSTORE: write C^T to [b][n][s] fp32; else row-major.
// =================================================================
template <bool ACOL, bool TSTORE>
__global__ void __launch_bounds__(256, 1) k_gemm(const __half* __restrict__ Ah,
                                                 const __half* __restrict__ Al,
                                                 const __half* __restrict__ Wh,
                                                 float* __restrict__ C) {
    extern __shared__ __align__(16) char smraw[];
    __half* sb = (__half*)smraw;
    float* smf = (float*)smraw;
    const uint32_t sb_u32 = smem_u32(sb);

    constexpr int ASZ = ACOL ? 64 * 264 : 256 * 72;   // one A plane, fp16 elems
    constexpr int WSZ = 128 * 72;                     // single W plane
    constexpr int BUF = 2 * ASZ + WSZ;                // AH|AL|W

    const int tid = threadIdx.x;
    const int warp = tid >> 5;
    const int wm = warp & 3;   // 4 warps along M, 64 rows each
    const int wn = warp >> 2;  // 2 warps along N, 64 cols each
    const int n0 = blockIdx.x * 128;
    const int m0 = blockIdx.y * 256;
    const int bb = m0 >> 12, s0 = m0 & 4095;

    auto ISSUE = [&](int kt, int jb) {
        uint32_t base = sb_u32 + (uint32_t)jb * BUF * 2;
        if constexpr (ACOL) {
            #pragma unroll
            for (int t = 0; t < 8; t++) {
                int idx = tid + t * 256;
                int row = idx >> 5, ch = (idx & 31) * 8;   // 64 k-rows x 256 m
                size_t g = ((size_t)(bb * D_ + kt * 64 + row)) * S_ + s0 + ch;
                cpa16(base + (uint32_t)(row * 264 + ch) * 2, Ah + g);
                cpa16(base + (uint32_t)(ASZ + row * 264 + ch) * 2, Al + g);
            }
        } else {
            #pragma unroll
            for (int t = 0; t < 8; t++) {
                int idx = tid + t * 256;
                int row = idx >> 3, ch = (idx & 7) * 8;    // 256 m-rows x 64 k
                size_t g = (size_t)(m0 + row) * D_ + kt * 64 + ch;
                cpa16(base + (uint32_t)(row * 72 + ch) * 2, Ah + g);
                cpa16(base + (uint32_t)(ASZ + row * 72 + ch) * 2, Al + g);
            }
        }
        #pragma unroll
        for (int t = 0; t < 4; t++) {
            int idx = tid + t * 256;
            int row = idx >> 3, ch = (idx & 7) * 8;        // 128 n-rows x 64 k
            size_t g = (size_t)(n0 + row) * D_ + kt * 64 + ch;
            cpa16(base + (uint32_t)(2 * ASZ + row * 72 + ch) * 2, Wh + g);
        }
        CP_COMMIT();
    };

    wmma::fragment<wmma::accumulator, 16, 16, 16, float> acc[4][4];
    #pragma unroll
    for (int i = 0; i < 4; i++)
        #pragma unroll
        for (int j = 0; j < 4; j++) wmma::fill_fragment(acc[i][j], 0.0f);

    ISSUE(0, 0);

    for (int it = 0; it < 16; it++) {
        const bool pf = (it + 1 < 16);
        if (pf) { ISSUE(it + 1, (it + 1) & 1); CP_WAIT1(); }
        else    { CP_WAIT0(); }
        __syncthreads();

        const __half* base = sb + (it & 1) * BUF;
        const __half* Ahs = base;
        const __half* Als = base + ASZ;
        const __half* Whs = base + 2 * ASZ;

        #pragma unroll
        for (int kk = 0; kk < 64; kk += 16) {
            wmma::fragment<wmma::matrix_b, 16, 16, 16, __half, wmma::col_major> bF[4];
            #pragma unroll
            for (int j = 0; j < 4; j++)
                wmma::load_matrix_sync(bF[j], Whs + (wn * 64 + j * 16) * 72 + kk, 72);
            #pragma unroll
            for (int i = 0; i < 4; i++) {
                if constexpr (ACOL) {
                    wmma::fragment<wmma::matrix_a, 16, 16, 16, __half, wmma::col_major> aH, aL;
                    wmma::load_matrix_sync(aH, Ahs + kk * 264 + wm * 64 + i * 16, 264);
                    wmma::load_matrix_sync(aL, Als + kk * 264 + wm * 64 + i * 16, 264);
                    #pragma unroll
                    for (int j = 0; j < 4; j++) {
                        wmma::mma_sync(acc[i][j], aH, bF[j], acc[i][j]);
                        wmma::mma_sync(acc[i][j], aL, bF[j], acc[i][j]);
                    }
                } else {
                    wmma::fragment<wmma::matrix_a, 16, 16, 16, __half, wmma::row_major> aH, aL;
                    wmma::load_matrix_sync(aH, Ahs + (wm * 64 + i * 16) * 72 + kk, 72);
                    wmma::load_matrix_sync(aL, Als + (wm * 64 + i * 16) * 72 + kk, 72);
                    #pragma unroll
                    for (int j = 0; j < 4; j++) {
                        wmma::mma_sync(acc[i][j], aH, bF[j], acc[i][j]);
                        wmma::mma_sync(acc[i][j], aL, bF[j], acc[i][j]);
                    }
                }
            }
        }
        __syncthreads();
    }

    if constexpr (TSTORE) {
        float* Ct = smf;
        #pragma unroll
        for (int i = 0; i < 4; i++)
            #pragma unroll
            for (int j = 0; j < 4; j++)
                wmma::store_matrix_sync(Ct + (wn * 64 + j * 16) * 264 + wm * 64 + i * 16,
                                        acc[i][j], 264, wmma::mem_col_major);
        __syncthreads();
        #pragma unroll
        for (int t = 0; t < 32; t++) {
            int idx = tid + t * 256;
            int n = idx >> 6, mm = (idx & 63) * 4;
            float4 v = *(float4*)(Ct + n * 264 + mm);
            *(float4*)(C + ((size_t)(bb * D_ + n0 + n)) * S_ + s0 + mm) = v;
        }
    } else {
        #pragma unroll
        for (int i = 0; i < 4; i++)
            #pragma unroll
            for (int j = 0; j < 4; j++)
                wmma::store_matrix_sync(C + (size_t)(m0 + wm * 64 + i * 16) * D_ + n0 + wn * 64 + j * 16,
                                        acc[i][j], D_, wmma::mem_row_major);
    }
}

// ---------------- fused radix-8 FFT -> gate*modReLU -> iFFT ----------------
__device__ __forceinline__ int SKI(int i) { return i + (i >> 4); }
__device__ __forceinline__ float2 cmul(float2 a, float2 b) {
    return make_float2(a.x * b.x - a.y * b.y, a.x * b.y + a.y * b.x);
}
__device__ __forceinline__ float2 cmulc(float2 a, float2 b) {
    return make_float2(a.x * b.x + a.y * b.y, a.y * b.x - a.x * b.y);
}
__device__ __forceinline__ float2 cadd(float2 a, float2 b) { return make_float2(a.x + b.x, a.y + b.y); }
__device__ __forceinline__ float2 csub(float2 a, float2 b) { return make_float2(a.x - b.x, a.y - b.y); }
#define RC8 0.70710678118654752440f

__device__ __forceinline__ int rev8(int k) {
    return ((k & 7) << 9) | (((k >> 3) & 7) << 6) | (((k >> 6) & 7) << 3) | ((k >> 9) & 7);
}

#define FWD8(x0,x1,x2,x3,x4,x5,x6,x7, X0,X1,X2,X3,X4,X5,X6,X7) do { \
    float2 s02 = cadd(x0, x4), d02 = csub(x0, x4); \
    float2 s26 = cadd(x2, x6), d26 = csub(x2, x6); \
    float2 E0 = cadd(s02, s26), E2 = csub(s02, s26); \
    float2 E1 = make_float2(d02.x + d26.y, d02.y - d26.x); \
    float2 E3 = make_float2(d02.x - d26.y, d02.y + d26.x); \
    float2 s15 = cadd(x1, x5), d15 = csub(x1, x5); \
    float2 s37 = cadd(x3, x7), d37 = csub(x3, x7); \
    float2 O0 = cadd(s15, s37), O2 = csub(s15, s37); \
    float2 O1 = make_float2(d15.x + d37.y, d15.y - d37.x); \
    float2 O3 = make_float2(d15.x - d37.y, d15.y + d37.x); \
    float2 T0 = O0; \
    float2 T1 = make_float2(RC8 * (O1.x + O1.y), RC8 * (O1.y - O1.x)); \
    float2 T2 = make_float2(O2.y, -O2.x); \
    float2 T3 = make_float2(RC8 * (O3.y - O3.x), -RC8 * (O3.x + O3.y)); \
    X0 = cadd(E0, T0); X4 = csub(E0, T0); \
    X1 = cadd(E1, T1); X5 = csub(E1, T1); \
    X2 = cadd(E2, T2); X6 = csub(E2, T2); \
    X3 = cadd(E3, T3); X7 = csub(E3, T3); \
} while (0)

#define INV8(u0,u1,u2,u3,u4,u5,u6,u7, Y0,Y1,Y2,Y3,Y4,Y5,Y6,Y7) do { \
    float2 s02 = cadd(u0, u4), d02 = csub(u0, u4); \
    float2 s26 = cadd(u2, u6), d26 = csub(u2, u6); \
    float2 E0 = cadd(s02, s26), E2 = csub(s02, s26); \
    float2 E1 = make_float2(d02.x - d26.y, d02.y + d26.x); \
    float2 E3 = make_float2(d02.x + d26.y, d02.y - d26.x); \
    float2 s15 = cadd(u1, u5), d15 = csub(u1, u5); \
    float2 s37 = cadd(u3, u7), d37 = csub(u3, u7); \
    float2 O0 = cadd(s15, s37), O2 = csub(s15, s37); \
    float2 O1 = make_float2(d15.x - d37.y, d15.y + d37.x); \
    float2 O3 = make_float2(d15.x + d37.y, d15.y - d37.x); \
    float2 T0 = O0; \
    float2 T1 = make_float2(RC8 * (O1.x - O1.y), RC8 * (O1.x + O1.y)); \
    float2 T2 = make_float2(-O2.y, O2.x); \
    float2 T3 = make_float2(-RC8 * (O3.x + O3.y), RC8 * (O3.x - O3.y)); \
    Y0 = cadd(E0, T0); Y4 = csub(E0, T0); \
    Y1 = cadd(E1, T1); Y5 = csub(E1, T1); \
    Y2 = cadd(E2, T2); Y6 = csub(E2, T2); \
    Y3 = cadd(E3, T3); Y7 = csub(E3, T3); \
} while (0)

__global__ void __launch_bounds__(512) k_fft(const float* __restrict__ mbias) {
    extern __shared__ float2 sd[];
    float2* dat = sd;              // skewed, 4096 + 256 slots
    float2* tw  = sd + 4352;       // 4096 full table

    const int tid = threadIdx.x;
    const int p = blockIdx.x;
    const int h = blockIdx.y;
    const int b = blockIdx.z;

    const float* va = g_Vt + ((size_t)((b * H_ + h) * DH_ + 2 * p)) * S_;
    const float* vb = va + S_;

    for (int i = tid; i < NFFT; i += 512) tw[i] = g_tw[i];

    // ---- forward stage 0 (Q=512) fused with global load ----
    {
        float2 x0 = make_float2(va[tid],          vb[tid]);
        float2 x1 = make_float2(va[tid + 512],    vb[tid + 512]);
        float2 x2 = make_float2(va[tid + 1024],   vb[tid + 1024]);
        float2 x3 = make_float2(va[tid + 1536],   vb[tid + 1536]);
        float2 x4 = make_float2(va[tid + 2048],   vb[tid + 2048]);
        float2 x5 = make_float2(va[tid + 2560],   vb[tid + 2560]);
        float2 x6 = make_float2(va[tid + 3072],   vb[tid + 3072]);
        float2 x7 = make_float2(va[tid + 3584],   vb[tid + 3584]);
        float2 X0, X1, X2, X3, X4, X5, X6, X7;
        FWD8(x0,x1,x2,x3,x4,x5,x6,x7, X0,X1,X2,X3,X4,X5,X6,X7);
        dat[SKI(tid)]        = X0;
        dat[SKI(tid + 512)]  = cmul(X1, g_tw[tid]);
        dat[SKI(tid + 1024)] = cmul(X2, g_tw[2 * tid]);
        dat[SKI(tid + 1536)] = cmul(X3, g_tw[3 * tid]);
        dat[SKI(tid + 2048)] = cmul(X4, g_tw[4 * tid]);
        dat[SKI(tid + 2560)] = cmul(X5, g_tw[5 * tid]);
        dat[SKI(tid + 3072)] = cmul(X6, g_tw[6 * tid]);
        dat[SKI(tid + 3584)] = cmul(X7, g_tw[7 * tid]);
    }
    __syncthreads();

    // ---- forward stages t=1..3 ----
    #pragma unroll
    for (int t = 1; t < 4; t++) {
        const int lq = 9 - 3 * t;
        const int Q = 1 << lq;
        const int step = 1 << (3 * t);
        const int j = tid & (Q - 1);
        const int i0 = ((tid >> lq) << (lq + 3)) | j;
        float2 x0 = dat[SKI(i0)];
        float2 x1 = dat[SKI(i0 + Q)];
        float2 x2 = dat[SKI(i0 + 2 * Q)];
        float2 x3 = dat[SKI(i0 + 3 * Q)];
        float2 x4 = dat[SKI(i0 + 4 * Q)];
        float2 x5 = dat[SKI(i0 + 5 * Q)];
        float2 x6 = dat[SKI(i0 + 6 * Q)];
        float2 x7 = dat[SKI(i0 + 7 * Q)];
        float2 X0, X1, X2, X3, X4, X5, X6, X7;
        FWD8(x0,x1,x2,x3,x4,x5,x6,x7, X0,X1,X2,X3,X4,X5,X6,X7);
        const int js = j * step;
        dat[SKI(i0)]         = X0;
        dat[SKI(i0 + Q)]     = cmul(X1, tw[js]);
        dat[SKI(i0 + 2 * Q)] = cmul(X2, tw[2 * js]);
        dat[SKI(i0 + 3 * Q)] = cmul(X3, tw[3 * js]);
        dat[SKI(i0 + 4 * Q)] = cmul(X4, tw[4 * js]);
        dat[SKI(i0 + 5 * Q)] = cmul(X5, tw[5 * js]);
        dat[SKI(i0 + 6 * Q)] = cmul(X6, tw[6 * js]);
        dat[SKI(i0 + 7 * Q)] = cmul(X7, tw[7 * js]);
        __syncthreads();
    }

    // ---- spectral: Hermitian separation, ortho scale, gate, modReLU ----
    const float bias = mbias[0];
    const float inv64 = 1.0f / 64.0f;
    const float* grb = g_gri + b * 2 * NF_;
    for (int k = tid; k <= NFFT / 2; k += 512) {
        float gr = grb[k];
        float gi = grb[NF_ + k];
        int p1 = rev8(k);
        if (k == 0 || k == NFFT / 2) {
            float2 Z = dat[SKI(p1)];
            float Av = Z.x * inv64, Bv = Z.y * inv64;
            float ar = Av * gr, ai = Av * gi;
            float ma = sqrtf(ar * ar + ai * ai);
            float sa = fmaxf(ma + bias, 0.f) / fmaxf(ma, 1e-12f);
            float Aout = ar * sa * inv64;
            float br2 = Bv * gr, bi2 = Bv * gi;
            float mb = sqrtf(br2 * br2 + bi2 * bi2);
            float sb = fmaxf(mb + bias, 0.f) / fmaxf(mb, 1e-12f);
            float Bout = br2 * sb * inv64;
            dat[SKI(p1)] = make_float2(Aout, Bout);
        } else {
            int p2 = rev8(NFFT - k);
            float2 Z1 = dat[SKI(p1)], Z2 = dat[SKI(p2)];
            float Ar = 0.5f * (Z1.x + Z2.x) * inv64;
            float Ai = 0.5f * (Z1.y - Z2.y) * inv64;
            float Br = 0.5f * (Z1.y + Z2.y) * inv64;
            float Bi = 0.5f * (Z2.x - Z1.x) * inv64;
            float zar = Ar * gr - Ai * gi, zai = Ar * gi + Ai * gr;
            float ma = sqrtf(zar * zar + zai * zai);
            float sa = fmaxf(ma + bias, 0.f) / fmaxf(ma, 1e-12f) * inv64;
            zar *= sa; zai *= sa;
            float zbr = Br * gr - Bi * gi, zbi = Br * gi + Bi * gr;
            float mb = sqrtf(zbr * zbr + zbi * zbi);
            float sb = fmaxf(mb + bias, 0.f) / fmaxf(mb, 1e-12f) * inv64;
            zbr *= sb; zbi *= sb;
            dat[SKI(p1)] = make_float2(zar - zbi, zai + zbr);
            dat[SKI(p2)] = make_float2(zar + zbi, zbr - zai);
        }
    }
    __syncthreads();

    // ---- inverse stages t=3..1 ----
    #pragma unroll
    for (int t = 3; t >= 1; t--) {
        const int lq = 9 - 3 * t;
        const int Q = 1 << lq;
        const int step = 1 << (3 * t);
        const int j = tid & (Q - 1);
        const int i0 = ((tid >> lq) << (lq + 3)) | j;
        const int js = j * step;
        float2 u0 = dat[SKI(i0)];
        float2 u1 = cmulc(dat[SKI(i0 + Q)],     tw[js]);
        float2 u2 = cmulc(dat[SKI(i0 + 2 * Q)], tw[2 * js]);
        float2 u3 = cmulc(dat[SKI(i0 + 3 * Q)], tw[3 * js]);
        float2 u4 = cmulc(dat[SKI(i0 + 4 * Q)], tw[4 * js]);
        float2 u5 = cmulc(dat[SKI(i0 + 5 * Q)], tw[5 * js]);
        float2 u6 = cmulc(dat[SKI(i0 + 6 * Q)], tw[6 * js]);
        float2 u7 = cmulc(dat[SKI(i0 + 7 * Q)], tw[7 * js]);
        float2 Y0, Y1, Y2, Y3, Y4, Y5, Y6, Y7;
        INV8(u0,u1,u2,u3,u4,u5,u6,u7, Y0,Y1,Y2,Y3,Y4,Y5,Y6,Y7);
        dat[SKI(i0)]         = Y0;
        dat[SKI(i0 + Q)]     = Y1;
        dat[SKI(i0 + 2 * Q)] = Y2;
        dat[SKI(i0 + 3 * Q)] = Y3;
        dat[SKI(i0 + 4 * Q)] = Y4;
        dat[SKI(i0 + 5 * Q)] = Y5;
        dat[SKI(i0 + 6 * Q)] = Y6;
        dat[SKI(i0 + 7 * Q)] = Y7;
        __syncthreads();
    }

    // ---- inverse stage 0 (Q=512) fused with fp16 split + global store ----
    {
        float2 u0 = dat[SKI(tid)];
        float2 u1 = cmulc(dat[SKI(tid + 512)],  tw[tid]);
        float2 u2 = cmulc(dat[SKI(tid + 1024)], tw[2 * tid]);
        float2 u3 = cmulc(dat[SKI(tid + 1536)], tw[3 * tid]);
        float2 u4 = cmulc(dat[SKI(tid + 2048)], tw[4 * tid]);
        float2 u5 = cmulc(dat[SKI(tid + 2560)], tw[5 * tid]);
        float2 u6 = cmulc(dat[SKI(tid + 3072)], tw[6 * tid]);
        float2 u7 = cmulc(dat[SKI(tid + 3584)], tw[7 * tid]);
        float2 Y[8];
        INV8(u0,u1,u2,u3,u4,u5,u6,u7, Y[0],Y[1],Y[2],Y[3],Y[4],Y[5],Y[6],Y[7]);
        size_t ra = ((size_t)((b * H_ + h) * DH_ + 2 * p)) * S_;
        size_t rb = ra + S_;
        #pragma unroll
        for (int r = 0; r < 8; r++) {
            size_t s = (size_t)tid + r * 512;
            __half hv, lv;
            split1h(Y[r].x, hv, lv);
            g_Ath[ra + s] = hv;
            g_Atl[ra + s] = lv;
            split1h(Y[r].y, hv, lv);
            g_Ath[rb + s] = hv;
            g_Atl[rb + s] = lv;
        }
    }
}

// ---------------- launch ----------------
extern "C" void kernel_launch(void* const* d_in, const int* in_sizes, int n_in,
                              void* d_out, int out_size) {
    const float* x     = (const float*)d_in[0];
    const float* Wq    = (const float*)d_in[1];
    const float* Wv    = (const float*)d_in[2];
    const float* Wo    = (const float*)d_in[3];
    const float* gamma = (const float*)d_in[4];
    const float* beta  = (const float*)d_in[5];
    const float* w1    = (const float*)d_in[6];
    const float* b1    = (const float*)d_in[7];
    const float* w2    = (const float*)d_in[8];
    const float* b2    = (const float*)d_in[9];
    const float* mbias = (const float*)d_in[10];
    float* out = (float*)d_out;

    float *vt = nullptr;
    __half *xh, *xl, *wvh, *woh, *ath, *atl;
    cudaGetSymbolAddress((void**)&vt,  g_Vt);
    cudaGetSymbolAddress((void**)&xh,  g_xh);
    cudaGetSymbolAddress((void**)&xl,  g_xl);
    cudaGetSymbolAddress((void**)&wvh, g_Wvh);
    cudaGetSymbolAddress((void**)&woh, g_Woh);
    cudaGetSymbolAddress((void**)&ath, g_Ath);
    cudaGetSymbolAddress((void**)&atl, g_Atl);

    // smem bytes:
    // V-GEMM: 2 stages * (2*256*72 + 128*72)*2 = 184320 ; Ct epi 135168 aliases
    // O-GEMM: 2 stages * (2*64*264 + 128*72)*2 = 172032
    // FFT: (4352 + 4096)*8 = 67584
    const int smem_v   = 184320;
    const int smem_o   = 172032;
    const int smem_fft = (4352 + 4096) * 8;

    cudaFuncSetAttribute(k_gemm<false, true>,  cudaFuncAttributeMaxDynamicSharedMemorySize, smem_v);
    cudaFuncSetAttribute(k_gemm<true,  false>, cudaFuncAttributeMaxDynamicSharedMemorySize, smem_o);
    cudaFuncSetAttribute(k_fft,                cudaFuncAttributeMaxDynamicSharedMemorySize, smem_fft);

    // prep (weight fp16 rounding + twiddle), fused x split + partial sums
    k_prep<<<2064, 256>>>((const float4*)Wv, (const float4*)Wo);
    k_xpart<<<dim3(8, 32, 4), 128>>>(x);

    // gate path (tiny)
    k_xsum<<<dim3(8, 4), 128>>>();
    k_meanq<<<dim3(128, 4), 256>>>(Wq);
    k_lnmlp1<<<4, 256>>>(gamma, beta, w1, b1);
    k_mlp2<<<dim3((2 * NF_ + 3) / 4, 4), 128>>>(w2, b2);

    // V projection, transposed output [b][c][s] fp32
    k_gemm<false, true><<<dim3(8, 64), 256, smem_v>>>(xh, xl, wvh, vt);

    // fused spectral mixer (emits fp16-split attn planes)
    k_fft<<<dim3(32, 16, 4), 512, smem_fft>>>(mbias);

    // output projection from fp16-split attn planes
    k_gemm<true, false><<<dim3(8, 64), 256, smem_o>>>(ath, atl, woh, out);
}

// round 12
// speedup vs baseline: 3.9293x; 1.0345x over previous
#include <cuda_runtime.h>
#include <cuda_fp16.h>
#include <mma.h>
#include <math.h>
#include <stdint.h>

using namespace nvcuda;

#define B_    4
#define S_    4096
#define D_    1024
#define H_    16
#define DH_   64
#define NF_   2049
#define NFFT  4096
#define LOGN  12

// ---------------- scratch (device globals; no allocations allowed) ----------------
__device__ float  g_Vt[(size_t)B_ * D_ * S_];      // V transposed: [b][c][s] fp32 (FFT input)
__device__ __half g_xh[(size_t)B_ * S_ * D_];      // x split hi (row-major [m][k]) fp16
__device__ __half g_xl[(size_t)B_ * S_ * D_];      // x split lo
__device__ __half g_Wvh[D_ * D_];                  // Wv rounded to fp16
__device__ __half g_Woh[D_ * D_];                  // Wo rounded to fp16
__device__ __half g_Ath[(size_t)B_ * D_ * S_];     // attn split hi: [b][c][s]
__device__ __half g_Atl[(size_t)B_ * D_ * S_];
__device__ float2 g_tw[512];                       // e^{-2*pi*i*k/N}, k<512 (chained beyond)
__device__ float  g_xpart[B_ * 32 * D_];
__device__ float  g_xsum[B_ * D_];
__device__ float  g_meanq[B_ * D_];
__device__ float  g_hdn[B_ * D_];
__device__ float  g_gri[B_ * 2 * NF_];

// ---------------- small helpers ----------------
__device__ __forceinline__ uint32_t smem_u32(const void* p) {
    uint32_t a;
    asm("{ .reg .u64 t; cvta.to.shared.u64 t, %1; cvt.u32.u64 %0, t; }" : "=r"(a) : "l"(p));
    return a;
}
__device__ __forceinline__ void cpa16(uint32_t dst, const void* src) {
    asm volatile("cp.async.cg.shared.global [%0], [%1], 16;" :: "r"(dst), "l"(src));
}
#define CP_COMMIT() asm volatile("cp.async.commit_group;" ::: "memory")
#define CP_WAIT2()  asm volatile("cp.async.wait_group 2;"  ::: "memory")
#define CP_WAIT1()  asm volatile("cp.async.wait_group 1;"  ::: "memory")
#define CP_WAIT0()  asm volatile("cp.async.wait_group 0;"  ::: "memory")

// fp16 hi/lo split
__device__ __forceinline__ void split1h(float v, __half& h, __half& l) {
    h = __float2half_rn(v);
    l = __float2half_rn(v - __half2float(h));
}

// ---------------- prep: weight fp16 rounding + twiddle in one launch ----------------
__global__ void __launch_bounds__(256) k_prep(const float4* __restrict__ Wv,
                                              const float4* __restrict__ Wo) {
    int blk = blockIdx.x;
    if (blk < 1024) {
        int i = blk * 256 + threadIdx.x;
        float4 v = Wv[i];
        ((__half2*)g_Wvh)[2 * i]     = __floats2half2_rn(v.x, v.y);
        ((__half2*)g_Wvh)[2 * i + 1] = __floats2half2_rn(v.z, v.w);
    } else if (blk < 2048) {
        int i = (blk - 1024) * 256 + threadIdx.x;
        float4 v = Wo[i];
        ((__half2*)g_Woh)[2 * i]     = __floats2half2_rn(v.x, v.y);
        ((__half2*)g_Woh)[2 * i + 1] = __floats2half2_rn(v.z, v.w);
    } else {
        int i = (blk - 2048) * 256 + threadIdx.x;
        if (i < 512) {
            double ang = -6.283185307179586476925286766559 * (double)i / (double)NFFT;
            g_tw[i] = make_float2((float)cos(ang), (float)sin(ang));
        }
    }
}

// ---------------- fused x split + partial sums ----------------
__global__ void __launch_bounds__(128) k_xpart(const float* __restrict__ x) {
    int d = blockIdx.x * 128 + threadIdx.x;
    int chunk = blockIdx.y;
    int b = blockIdx.z;
    size_t base = ((size_t)b * S_ + (size_t)chunk * 128) * D_ + d;
    const float* p = x + base;
    __half* ph = g_xh + base;
    __half* pl = g_xl + base;
    float acc = 0.f;
    #pragma unroll 4
    for (int s = 0; s < 128; s++) {
        float v = p[(size_t)s * D_];
        acc += v;
        __half h, l;
        split1h(v, h, l);
        ph[(size_t)s * D_] = h;
        pl[(size_t)s * D_] = l;
    }
    g_xpart[(b * 32 + chunk) * D_ + d] = acc;
}

__global__ void __launch_bounds__(128) k_xsum() {
    int d = blockIdx.x * 128 + threadIdx.x;
    int b = blockIdx.y;
    float acc = 0.f;
    #pragma unroll
    for (int q = 0; q < 32; q++) acc += g_xpart[(b * 32 + q) * D_ + d];
    g_xsum[b * D_ + d] = acc;
}

__global__ void __launch_bounds__(256) k_meanq(const float* __restrict__ Wq) {
    int warp = threadIdx.x >> 5, lane = threadIdx.x & 31;
    int c = blockIdx.x * 8 + warp;
    int b = blockIdx.y;
    const float* w  = Wq + (size_t)c * D_;
    const float* xm = g_xsum + b * D_;
    float acc = 0.f;
    #pragma unroll 8
    for (int i = lane; i < D_; i += 32) acc += xm[i] * w[i];
    #pragma unroll
    for (int o = 16; o; o >>= 1) acc += __shfl_xor_sync(0xffffffffu, acc, o);
    if (lane == 0) g_meanq[b * D_ + c] = acc * (1.0f / S_);
}

__global__ void __launch_bounds__(256) k_lnmlp1(const float* __restrict__ gamma,
                                                const float* __restrict__ beta,
                                                const float* __restrict__ w1,
                                                const float* __restrict__ b1) {
    __shared__ float sv[16][64];
    __shared__ float sq[64];
    __shared__ float smean[16], srstd[16];
    int b = blockIdx.x;
    int t = threadIdx.x;

    #pragma unroll
    for (int r = 0; r < 4; r++) {
        int c = t + r * 256;
        sv[c >> 6][c & 63] = g_meanq[b * D_ + c];
    }
    __syncthreads();
    if (t < 16) {
        float m = 0.f;
        for (int q = 0; q < 64; q++) m += sv[t][q];
        m *= (1.f / 64.f);
        float var = 0.f;
        for (int q = 0; q < 64; q++) { float dd = sv[t][q] - m; var += dd * dd; }
        var *= (1.f / 64.f);
        smean[t] = m;
        srstd[t] = rsqrtf(var + 1e-5f);
    }
    __syncthreads();
    #pragma unroll
    for (int r = 0; r < 4; r++) {
        int c = t + r * 256;
        int h = c >> 6, j = c & 63;
        sv[h][j] = (sv[h][j] - smean[h]) * srstd[h] * gamma[j] + beta[j];
    }
    __syncthreads();
    if (t < 64) {
        float m = 0.f;
        for (int q = 0; q < 16; q++) m += sv[q][t];
        sq[t] = m * (1.f / 16.f);
    }
    __syncthreads();
    #pragma unroll
    for (int r = 0; r < 4; r++) {
        int c = t + r * 256;
        float acc = b1[c];
        const float* wr = w1 + (size_t)c * 64;
        #pragma unroll 8
        for (int q = 0; q < 64; q++) acc += sq[q] * wr[q];
        g_hdn[b * D_ + c] = 0.5f * acc * (1.f + erff(acc * 0.70710678118654752f));
    }
}

__global__ void __launch_bounds__(128) k_mlp2(const float* __restrict__ w2,
                                              const float* __restrict__ b2) {
    int warp = threadIdx.x >> 5, lane = threadIdx.x & 31;
    int r = blockIdx.x * 4 + warp;
    int b = blockIdx.y;
    if (r >= 2 * NF_) return;
    const float* hd = g_hdn + b * D_;
    const float* w  = w2 + (size_t)r * D_;
    float acc = 0.f;
    for (int i = lane; i < D_; i += 32) acc += hd[i] * w[i];
    #pragma unroll
    for (int o = 16; o; o >>= 1) acc += __shfl_xor_sync(0xffffffffu, acc, o);
    if (lane == 0) g_gri[b * 2 * NF_ + r] = acc + b2[r];
}

// =================================================================
// fp16 2-product WMMA GEMM: C = A@W^T with A = Ah + Al (fp16 split),
// W rounded to fp16. K=32 stages, 4-buffer cp.async ring,
// ONE __syncthreads per stage (wait -> sync -> issue(it+3) -> compute).
// ACOL:   A planes are [b][k][s] (FFT output); else row-major [m][k].
// TSTORE: write C^T to [b][n][s] fp32; else row-major.
// =================================================================
template <bool ACOL, bool TSTORE>
__global__ void __launch_bounds__(256, 1) k_gemm(const __half* __restrict__ Ah,
                                                 const __half* __restrict__ Al,
                                                 const __half* __restrict__ Wh,
                                                 float* __restrict__ C) {
    extern __shared__ __align__(16) char smraw[];
    __half* sb = (__half*)smraw;
    float* smf = (float*)smraw;
    const uint32_t sb_u32 = smem_u32(sb);

    constexpr int ASZ = ACOL ? 32 * 264 : 256 * 40;   // one A plane, fp16 elems
    constexpr int WSZ = 128 * 40;                     // single W plane
    constexpr int BUF = 2 * ASZ + WSZ;                // AH|AL|W

    const int tid = threadIdx.x;
    const int warp = tid >> 5;
    const int wm = warp & 3;   // 4 warps along M, 64 rows each
    const int wn = warp >> 2;  // 2 warps along N, 64 cols each
    const int n0 = blockIdx.x * 128;
    const int m0 = blockIdx.y * 256;
    const int bb = m0 >> 12, s0 = m0 & 4095;

    auto ISSUE = [&](int kt) {
        uint32_t base = sb_u32 + (uint32_t)(kt & 3) * BUF * 2;
        if constexpr (ACOL) {
            #pragma unroll
            for (int t = 0; t < 4; t++) {
                int idx = tid + t * 256;
                int row = idx >> 5, ch = (idx & 31) * 8;   // 32 k-rows x 256 m
                size_t g = ((size_t)(bb * D_ + kt * 32 + row)) * S_ + s0 + ch;
                cpa16(base + (uint32_t)(row * 264 + ch) * 2, Ah + g);
                cpa16(base + (uint32_t)(ASZ + row * 264 + ch) * 2, Al + g);
            }
        } else {
            #pragma unroll
            for (int t = 0; t < 4; t++) {
                int idx = tid + t * 256;
                int row = idx >> 2, ch = (idx & 3) * 8;    // 256 m-rows x 32 k
                size_t g = (size_t)(m0 + row) * D_ + kt * 32 + ch;
                cpa16(base + (uint32_t)(row * 40 + ch) * 2, Ah + g);
                cpa16(base + (uint32_t)(ASZ + row * 40 + ch) * 2, Al + g);
            }
        }
        #pragma unroll
        for (int t = 0; t < 2; t++) {
            int idx = tid + t * 256;
            int row = idx >> 2, ch = (idx & 3) * 8;        // 128 n-rows x 32 k
            size_t g = (size_t)(n0 + row) * D_ + kt * 32 + ch;
            cpa16(base + (uint32_t)(2 * ASZ + row * 40 + ch) * 2, Wh + g);
        }
        CP_COMMIT();
    };

    wmma::fragment<wmma::accumulator, 16, 16, 16, float> acc[4][4];
    #pragma unroll
    for (int i = 0; i < 4; i++)
        #pragma unroll
        for (int j = 0; j < 4; j++) wmma::fill_fragment(acc[i][j], 0.0f);

    ISSUE(0);
    ISSUE(1);
    ISSUE(2);

    for (int it = 0; it < 32; it++) {
        if (it <= 29)      CP_WAIT2();
        else if (it == 30) CP_WAIT1();
        else               CP_WAIT0();
        __syncthreads();                 // all warps done with stage it-1
        if (it + 3 < 32) ISSUE(it + 3);  // safe: overwrites buffer consumed at it-1

        const __half* base = sb + (it & 3) * BUF;
        const __half* Ahs = base;
        const __half* Als = base + ASZ;
        const __half* Whs = base + 2 * ASZ;

        #pragma unroll
        for (int kk = 0; kk < 32; kk += 16) {
            wmma::fragment<wmma::matrix_b, 16, 16, 16, __half, wmma::col_major> bF[4];
            #pragma unroll
            for (int j = 0; j < 4; j++)
                wmma::load_matrix_sync(bF[j], Whs + (wn * 64 + j * 16) * 40 + kk, 40);
            #pragma unroll
            for (int i = 0; i < 4; i++) {
                if constexpr (ACOL) {
                    wmma::fragment<wmma::matrix_a, 16, 16, 16, __half, wmma::col_major> aH, aL;
                    wmma::load_matrix_sync(aH, Ahs + kk * 264 + wm * 64 + i * 16, 264);
                    wmma::load_matrix_sync(aL, Als + kk * 264 + wm * 64 + i * 16, 264);
                    #pragma unroll
                    for (int j = 0; j < 4; j++) {
                        wmma::mma_sync(acc[i][j], aH, bF[j], acc[i][j]);
                        wmma::mma_sync(acc[i][j], aL, bF[j], acc[i][j]);
                    }
                } else {
                    wmma::fragment<wmma::matrix_a, 16, 16, 16, __half, wmma::row_major> aH, aL;
                    wmma::load_matrix_sync(aH, Ahs + (wm * 64 + i * 16) * 40 + kk, 40);
                    wmma::load_matrix_sync(aL, Als + (wm * 64 + i * 16) * 40 + kk, 40);
                    #pragma unroll
                    for (int j = 0; j < 4; j++) {
                        wmma::mma_sync(acc[i][j], aH, bF[j], acc[i][j]);
                        wmma::mma_sync(acc[i][j], aL, bF[j], acc[i][j]);
                    }
                }
            }
        }
    }
    __syncthreads();   // all compute done before smem reuse / exit

    if constexpr (TSTORE) {
        float* Ct = smf;
        #pragma unroll
        for (int i = 0; i < 4; i++)
            #pragma unroll
            for (int j = 0; j < 4; j++)
                wmma::store_matrix_sync(Ct + (wn * 64 + j * 16) * 264 + wm * 64 + i * 16,
                                        acc[i][j], 264, wmma::mem_col_major);
        __syncthreads();
        #pragma unroll
        for (int t = 0; t < 32; t++) {
            int idx = tid + t * 256;
            int n = idx >> 6, mm = (idx & 63) * 4;
            float4 v = *(float4*)(Ct + n * 264 + mm);
            *(float4*)(C + ((size_t)(bb * D_ + n0 + n)) * S_ + s0 + mm) = v;
        }
    } else {
        #pragma unroll
        for (int i = 0; i < 4; i++)
            #pragma unroll
            for (int j = 0; j < 4; j++)
                wmma::store_matrix_sync(C + (size_t)(m0 + wm * 64 + i * 16) * D_ + n0 + wn * 64 + j * 16,
                                        acc[i][j], D_, wmma::mem_row_major);
    }
}

// ---------------- fused radix-8 FFT -> gate*modReLU -> iFFT ----------------
// 512-entry twiddle table; higher powers chained via cmul.
__device__ __forceinline__ int SKI(int i) { return i + (i >> 4); }
__device__ __forceinline__ float2 cmul(float2 a, float2 b) {
    return make_float2(a.x * b.x - a.y * b.y, a.x * b.y + a.y * b.x);
}
__device__ __forceinline__ float2 cmulc(float2 a, float2 b) {
    return make_float2(a.x * b.x + a.y * b.y, a.y * b.x - a.x * b.y);
}
__device__ __forceinline__ float2 cadd(float2 a, float2 b) { return make_float2(a.x + b.x, a.y + b.y); }
__device__ __forceinline__ float2 csub(float2 a, float2 b) { return make_float2(a.x - b.x, a.y - b.y); }
#define RC8 0.70710678118654752440f

__device__ __forceinline__ int rev8(int k) {
    return ((k & 7) << 9) | (((k >> 3) & 7) << 6) | (((k >> 6) & 7) << 3) | ((k >> 9) & 7);
}

#define TWCHAIN(w1, w2, w3, w4, w5, w6, w7) \
    float2 w2 = cmul(w1, w1); \
    float2 w3 = cmul(w2, w1); \
    float2 w4 = cmul(w2, w2); \
    float2 w5 = cmul(w3, w2); \
    float2 w6 = cmul(w3, w3); \
    float2 w7 = cmul(w4, w3)

#define FWD8(x0,x1,x2,x3,x4,x5,x6,x7, X0,X1,X2,X3,X4,X5,X6,X7) do { \
    float2 s02 = cadd(x0, x4), d02 = csub(x0, x4); \
    float2 s26 = cadd(x2, x6), d26 = csub(x2, x6); \
    float2 E0 = cadd(s02, s26), E2 = csub(s02, s26); \
    float2 E1 = make_float2(d02.x + d26.y, d02.y - d26.x); \
    float2 E3 = make_float2(d02.x - d26.y, d02.y + d26.x); \
    float2 s15 = cadd(x1, x5), d15 = csub(x1, x5); \
    float2 s37 = cadd(x3, x7), d37 = csub(x3, x7); \
    float2 O0 = cadd(s15, s37), O2 = csub(s15, s37); \
    float2 O1 = make_float2(d15.x + d37.y, d15.y - d37.x); \
    float2 O3 = make_float2(d15.x - d37.y, d15.y + d37.x); \
    float2 T0 = O0; \
    float2 T1 = make_float2(RC8 * (O1.x + O1.y), RC8 * (O1.y - O1.x)); \
    float2 T2 = make_float2(O2.y, -O2.x); \
    float2 T3 = make_float2(RC8 * (O3.y - O3.x), -RC8 * (O3.x + O3.y)); \
    X0 = cadd(E0, T0); X4 = csub(E0, T0); \
    X1 = cadd(E1, T1); X5 = csub(E1, T1); \
    X2 = cadd(E2, T2); X6 = csub(E2, T2); \
    X3 = cadd(E3, T3); X7 = csub(E3, T3); \
} while (0)

#define INV8(u0,u1,u2,u3,u4,u5,u6,u7, Y0,Y1,Y2,Y3,Y4,Y5,Y6,Y7) do { \
    float2 s02 = cadd(u0, u4), d02 = csub(u0, u4); \
    float2 s26 = cadd(u2, u6), d26 = csub(u2, u6); \
    float2 E0 = cadd(s02, s26), E2 = csub(s02, s26); \
    float2 E1 = make_float2(d02.x - d26.y, d02.y + d26.x); \
    float2 E3 = make_float2(d02.x + d26.y, d02.y - d26.x); \
    float2 s15 = cadd(u1, u5), d15 = csub(u1, u5); \
    float2 s37 = cadd(u3, u7), d37 = csub(u3, u7); \
    float2 O0 = cadd(s15, s37), O2 = csub(s15, s37); \
    float2 O1 = make_float2(d15.x - d37.y, d15.y + d37.x); \
    float2 O3 = make_float2(d15.x + d37.y, d15.y - d37.x); \
    float2 T0 = O0; \
    float2 T1 = make_float2(RC8 * (O1.x - O1.y), RC8 * (O1.x + O1.y)); \
    float2 T2 = make_float2(-O2.y, O2.x); \
    float2 T3 = make_float2(-RC8 * (O3.x + O3.y), RC8 * (O3.x - O3.y)); \
    Y0 = cadd(E0, T0); Y4 = csub(E0, T0); \
    Y1 = cadd(E1, T1); Y5 = csub(E1, T1); \
    Y2 = cadd(E2, T2); Y6 = csub(E2, T2); \
    Y3 = cadd(E3, T3); Y7 = csub(E3, T3); \
} while (0)

__global__ void __launch_bounds__(512) k_fft(const float* __restrict__ mbias) {
    extern __shared__ float2 sd[];
    float2* dat = sd;              // skewed, 4096 + 256 slots
    float2* tws = sd + 4352;       // 512-entry table

    const int tid = threadIdx.x;
    const int p = blockIdx.x;
    const int h = blockIdx.y;
    const int b = blockIdx.z;

    const float* va = g_Vt + ((size_t)((b * H_ + h) * DH_ + 2 * p)) * S_;
    const float* vb = va + S_;

    tws[tid] = g_tw[tid];          // 512 threads, 512 entries

    // ---- forward stage 0 (Q=512) fused with global load ----
    {
        float2 x0 = make_float2(va[tid],          vb[tid]);
        float2 x1 = make_float2(va[tid + 512],    vb[tid + 512]);
        float2 x2 = make_float2(va[tid + 1024],   vb[tid + 1024]);
        float2 x3 = make_float2(va[tid + 1536],   vb[tid + 1536]);
        float2 x4 = make_float2(va[tid + 2048],   vb[tid + 2048]);
        float2 x5 = make_float2(va[tid + 2560],   vb[tid + 2560]);
        float2 x6 = make_float2(va[tid + 3072],   vb[tid + 3072]);
        float2 x7 = make_float2(va[tid + 3584],   vb[tid + 3584]);
        float2 X0, X1, X2, X3, X4, X5, X6, X7;
        FWD8(x0,x1,x2,x3,x4,x5,x6,x7, X0,X1,X2,X3,X4,X5,X6,X7);
        float2 w1 = g_tw[tid];
        TWCHAIN(w1, w2, w3, w4, w5, w6, w7);
        dat[SKI(tid)]        = X0;
        dat[SKI(tid + 512)]  = cmul(X1, w1);
        dat[SKI(tid + 1024)] = cmul(X2, w2);
        dat[SKI(tid + 1536)] = cmul(X3, w3);
        dat[SKI(tid + 2048)] = cmul(X4, w4);
        dat[SKI(tid + 2560)] = cmul(X5, w5);
        dat[SKI(tid + 3072)] = cmul(X6, w6);
        dat[SKI(tid + 3584)] = cmul(X7, w7);
    }
    __syncthreads();

    // ---- forward stages t=1..3 ----
    #pragma unroll
    for (int t = 1; t < 4; t++) {
        const int lq = 9 - 3 * t;
        const int Q = 1 << lq;
        const int step = 1 << (3 * t);
        const int j = tid & (Q - 1);
        const int i0 = ((tid >> lq) << (lq + 3)) | j;
        float2 x0 = dat[SKI(i0)];
        float2 x1 = dat[SKI(i0 + Q)];
        float2 x2 = dat[SKI(i0 + 2 * Q)];
        float2 x3 = dat[SKI(i0 + 3 * Q)];
        float2 x4 = dat[SKI(i0 + 4 * Q)];
        float2 x5 = dat[SKI(i0 + 5 * Q)];
        float2 x6 = dat[SKI(i0 + 6 * Q)];
        float2 x7 = dat[SKI(i0 + 7 * Q)];
        float2 X0, X1, X2, X3, X4, X5, X6, X7;
        FWD8(x0,x1,x2,x3,x4,x5,x6,x7, X0,X1,X2,X3,X4,X5,X6,X7);
        float2 w1 = tws[j * step];
        TWCHAIN(w1, w2, w3, w4, w5, w6, w7);
        dat[SKI(i0)]         = X0;
        dat[SKI(i0 + Q)]     = cmul(X1, w1);
        dat[SKI(i0 + 2 * Q)] = cmul(X2, w2);
        dat[SKI(i0 + 3 * Q)] = cmul(X3, w3);
        dat[SKI(i0 + 4 * Q)] = cmul(X4, w4);
        dat[SKI(i0 + 5 * Q)] = cmul(X5, w5);
        dat[SKI(i0 + 6 * Q)] = cmul(X6, w6);
        dat[SKI(i0 + 7 * Q)] = cmul(X7, w7);
        __syncthreads();
    }

    // ---- spectral: Hermitian separation, ortho scale, gate, modReLU ----
    const float bias = mbias[0];
    const float inv64 = 1.0f / 64.0f;
    const float* grb = g_gri + b * 2 * NF_;
    for (int k = tid; k <= NFFT / 2; k += 512) {
        float gr = grb[k];
        float gi = grb[NF_ + k];
        int p1 = rev8(k);
        if (k == 0 || k == NFFT / 2) {
            float2 Z = dat[SKI(p1)];
            float Av = Z.x * inv64, Bv = Z.y * inv64;
            float ar = Av * gr, ai = Av * gi;
            float ma = sqrtf(ar * ar + ai * ai);
            float sa = fmaxf(ma + bias, 0.f) / fmaxf(ma, 1e-12f);
            float Aout = ar * sa * inv64;
            float br2 = Bv * gr, bi2 = Bv * gi;
            float mb = sqrtf(br2 * br2 + bi2 * bi2);
            float sb = fmaxf(mb + bias, 0.f) / fmaxf(mb, 1e-12f);
            float Bout = br2 * sb * inv64;
            dat[SKI(p1)] = make_float2(Aout, Bout);
        } else {
            int p2 = rev8(NFFT - k);
            float2 Z1 = dat[SKI(p1)], Z2 = dat[SKI(p2)];
            float Ar = 0.5f * (Z1.x + Z2.x) * inv64;
            float Ai = 0.5f * (Z1.y - Z2.y) * inv64;
            float Br = 0.5f * (Z1.y + Z2.y) * inv64;
            float Bi = 0.5f * (Z2.x - Z1.x) * inv64;
            float zar = Ar * gr - Ai * gi, zai = Ar * gi + Ai * gr;
            float ma = sqrtf(zar * zar + zai * zai);
            float sa = fmaxf(ma + bias, 0.f) / fmaxf(ma, 1e-12f) * inv64;
            zar *= sa; zai *= sa;
            float zbr = Br * gr - Bi * gi, zbi = Br * gi + Bi * gr;
            float mb = sqrtf(zbr * zbr + zbi * zbi);
            float sb = fmaxf(mb + bias, 0.f) / fmaxf(mb, 1e-12f) * inv64;
            zbr *= sb; zbi *= sb;
            dat[SKI(p1)] = make_float2(zar - zbi, zai + zbr);
            dat[SKI(p2)] = make_float2(zar + zbi, zbr - zai);
        }
    }
    __syncthreads();

    // ---- inverse stages t=3..1 ----
    #pragma unroll
    for (int t = 3; t >= 1; t--) {
        const int lq = 9 - 3 * t;
        const int Q = 1 << lq;
        const int step = 1 << (3 * t);
        const int j = tid & (Q - 1);
        const int i0 = ((tid >> lq) << (lq + 3)) | j;
        float2 w1 = tws[j * step];
        TWCHAIN(w1, w2, w3, w4, w5, w6, w7);
        float2 u0 = dat[SKI(i0)];
        float2 u1 = cmulc(dat[SKI(i0 + Q)],     w1);
        float2 u2 = cmulc(dat[SKI(i0 + 2 * Q)], w2);
        float2 u3 = cmulc(dat[SKI(i0 + 3 * Q)], w3);
        float2 u4 = cmulc(dat[SKI(i0 + 4 * Q)], w4);
        float2 u5 = cmulc(dat[SKI(i0 + 5 * Q)], w5);
        float2 u6 = cmulc(dat[SKI(i0 + 6 * Q)], w6);
        float2 u7 = cmulc(dat[SKI(i0 + 7 * Q)], w7);
        float2 Y0, Y1, Y2, Y3, Y4, Y5, Y6, Y7;
        INV8(u0,u1,u2,u3,u4,u5,u6,u7, Y0,Y1,Y2,Y3,Y4,Y5,Y6,Y7);
        dat[SKI(i0)]         = Y0;
        dat[SKI(i0 + Q)]     = Y1;
        dat[SKI(i0 + 2 * Q)] = Y2;
        dat[SKI(i0 + 3 * Q)] = Y3;
        dat[SKI(i0 + 4 * Q)] = Y4;
        dat[SKI(i0 + 5 * Q)] = Y5;
        dat[SKI(i0 + 6 * Q)] = Y6;
        dat[SKI(i0 + 7 * Q)] = Y7;
        __syncthreads();
    }

    // ---- inverse stage 0 (Q=512) fused with fp16 split + global store ----
    {
        float2 w1 = tws[tid];
        TWCHAIN(w1, w2, w3, w4, w5, w6, w7);
        float2 u0 = dat[SKI(tid)];
        float2 u1 = cmulc(dat[SKI(tid + 512)],  w1);
        float2 u2 = cmulc(dat[SKI(tid + 1024)], w2);
        float2 u3 = cmulc(dat[SKI(tid + 1536)], w3);
        float2 u4 = cmulc(dat[SKI(tid + 2048)], w4);
        float2 u5 = cmulc(dat[SKI(tid + 2560)], w5);
        float2 u6 = cmulc(dat[SKI(tid + 3072)], w6);
        float2 u7 = cmulc(dat[SKI(tid + 3584)], w7);
        float2 Y[8];
        INV8(u0,u1,u2,u3,u4,u5,u6,u7, Y[0],Y[1],Y[2],Y[3],Y[4],Y[5],Y[6],Y[7]);
        size_t ra = ((size_t)((b * H_ + h) * DH_ + 2 * p)) * S_;
        size_t rb = ra + S_;
        #pragma unroll
        for (int r = 0; r < 8; r++) {
            size_t s = (size_t)tid + r * 512;
            __half hv, lv;
            split1h(Y[r].x, hv, lv);
            g_Ath[ra + s] = hv;
            g_Atl[ra + s] = lv;
            split1h(Y[r].y, hv, lv);
            g_Ath[rb + s] = hv;
            g_Atl[rb + s] = lv;
        }
    }
}

// ---------------- launch ----------------
extern "C" void kernel_launch(void* const* d_in, const int* in_sizes, int n_in,
                              void* d_out, int out_size) {
    const float* x     = (const float*)d_in[0];
    const float* Wq    = (const float*)d_in[1];
    const float* Wv    = (const float*)d_in[2];
    const float* Wo    = (const float*)d_in[3];
    const float* gamma = (const float*)d_in[4];
    const float* beta  = (const float*)d_in[5];
    const float* w1    = (const float*)d_in[6];
    const float* b1    = (const float*)d_in[7];
    const float* w2    = (const float*)d_in[8];
    const float* b2    = (const float*)d_in[9];
    const float* mbias = (const float*)d_in[10];
    float* out = (float*)d_out;

    float *vt = nullptr;
    __half *xh, *xl, *wvh, *woh, *ath, *atl;
    cudaGetSymbolAddress((void**)&vt,  g_Vt);
    cudaGetSymbolAddress((void**)&xh,  g_xh);
    cudaGetSymbolAddress((void**)&xl,  g_xl);
    cudaGetSymbolAddress((void**)&wvh, g_Wvh);
    cudaGetSymbolAddress((void**)&woh, g_Woh);
    cudaGetSymbolAddress((void**)&ath, g_Ath);
    cudaGetSymbolAddress((void**)&atl, g_Atl);

    // smem bytes:
    // V-GEMM: 4 stages * (2*256*40 + 128*40)*2 = 204800 ; Ct epi 135168 aliases
    // O-GEMM: 4 stages * (2*32*264 + 128*40)*2 = 176128
    // FFT: (4352 + 512)*8 = 38912
    const int smem_v   = 204800;
    const int smem_o   = 176128;
    const int smem_fft = (4352 + 512) * 8;

    cudaFuncSetAttribute(k_gemm<false, true>,  cudaFuncAttributeMaxDynamicSharedMemorySize, smem_v);
    cudaFuncSetAttribute(k_gemm<true,  false>, cudaFuncAttributeMaxDynamicSharedMemorySize, smem_o);
    cudaFuncSetAttribute(k_fft,                cudaFuncAttributeMaxDynamicSharedMemorySize, smem_fft);

    // prep (weight fp16 rounding + twiddle), fused x split + partial sums
    k_prep<<<2050, 256>>>((const float4*)Wv, (const float4*)Wo);
    k_xpart<<<dim3(8, 32, 4), 128>>>(x);

    // gate path (tiny)
    k_xsum<<<dim3(8, 4), 128>>>();
    k_meanq<<<dim3(128, 4), 256>>>(Wq);
    k_lnmlp1<<<4, 256>>>(gamma, beta, w1, b1);
    k_mlp2<<<dim3((2 * NF_ + 3) / 4, 4), 128>>>(w2, b2);

    // V projection, transposed output [b][c][s] fp32
    k_gemm<false, true><<<dim3(8, 64), 256, smem_v>>>(xh, xl, wvh, vt);

    // fused spectral mixer (emits fp16-split attn planes)
    k_fft<<<dim3(32, 16, 4), 512, smem_fft>>>(mbias);

    // output projection from fp16-split attn planes
    k_gemm<true, false><<<dim3(8, 64), 256, smem_o>>>(ath, atl, woh, out);
}